// round 1
// baseline (speedup 1.0000x reference)
#include <cuda_runtime.h>

// ---------------------------------------------------------------------------
// Problem constants
// ---------------------------------------------------------------------------
#define NB   4
#define CIN  256
#define CKEY 448
#define NTOK 4096
#define NEGV (-1e15f)
#define EPSV 1e-5f

// ---------------------------------------------------------------------------
// Scratch (static device globals; no runtime allocation)
// ---------------------------------------------------------------------------
__device__ float g_FqT [(size_t)NB * CKEY * NTOK];   // [b][Ck][N]  f(content_key)
__device__ float g_G   [(size_t)NB * CKEY * NTOK];   // [b][Ck][N]  g(style_key)
__device__ float g_HvT [(size_t)NB * CIN  * NTOK];   // [b][C][N]   h(style)
__device__ float g_Hv2T[(size_t)NB * CIN  * NTOK];   // [b][C][N]   h(style)^2
__device__ float g_S   [(size_t)NB * NTOK * NTOK];   // [b][N][N]   scores -> attn (in place)
__device__ float g_meanT[(size_t)NB * CIN * NTOK];   // [b][C][N]
__device__ float g_m2T [(size_t)NB * CIN  * NTOK];   // [b][C][N]
__device__ float g_cmean[NB * CIN];
__device__ float g_crstd[NB * CIN];

// ---------------------------------------------------------------------------
// Generic 128x128x16 SGEMM, 256 threads, 8x8 per-thread tile.
//   C[m][n] = sum_k Aelem(m,k) * Belem(k,n)   (+ bias[m])   [+ C2 = C*C]
//   A_KM  true:  A stored [K][M]  (contiguous m)   -- "T" operand
//         false: A stored [M][K]  (contiguous k)
//   B_NK  true:  B stored [N][K]  (contiguous k)   -- "T" operand
//         false: B stored [K][N]  (contiguous n)
// N and K are always multiples of 128/16 here; only M may be ragged (448/256).
// ---------------------------------------------------------------------------
template <bool A_KM, bool B_NK, bool BIAS, bool SQ>
__global__ __launch_bounds__(256) void gemm128(
    const float* __restrict__ A, const float* __restrict__ B,
    const float* __restrict__ bias,
    float* __restrict__ C, float* __restrict__ C2,
    int M, int N, int K,
    size_t sA, size_t sB, size_t sC)
{
    constexpr int BM = 128, BN = 128, BK = 16;
    __shared__ float As[BK][BM + 4];
    __shared__ float Bs[BK][BN + 4];

    const int tid = threadIdx.x;
    const int tx  = tid & 15;   // -> N
    const int ty  = tid >> 4;   // -> M
    const int bz  = blockIdx.z;

    A += (size_t)bz * sA;
    B += (size_t)bz * sB;
    C += (size_t)bz * sC;
    if (SQ) C2 += (size_t)bz * sC;

    const int m0 = blockIdx.y * BM;
    const int n0 = blockIdx.x * BN;

    float acc[8][8];
#pragma unroll
    for (int i = 0; i < 8; i++)
#pragma unroll
        for (int j = 0; j < 8; j++) acc[i][j] = 0.f;

    for (int k0 = 0; k0 < K; k0 += BK) {
        // ---- stage A tile -> As[k][m] ----
        if (A_KM) {
#pragma unroll
            for (int r = 0; r < 2; r++) {
                int t  = tid + r * 256;           // 0..511
                int k  = t >> 5;                  // 0..15
                int m4 = (t & 31) << 2;           // 0..124
                float4 v = make_float4(0.f, 0.f, 0.f, 0.f);
                if (m0 + m4 < M)
                    v = *reinterpret_cast<const float4*>(&A[(size_t)(k0 + k) * M + m0 + m4]);
                *reinterpret_cast<float4*>(&As[k][m4]) = v;
            }
        } else {
#pragma unroll
            for (int r = 0; r < 2; r++) {
                int t  = tid + r * 256;
                int m  = t >> 2;                  // 0..127
                int k4 = (t & 3) << 2;            // 0..12
                float4 v = make_float4(0.f, 0.f, 0.f, 0.f);
                if (m0 + m < M)
                    v = *reinterpret_cast<const float4*>(&A[(size_t)(m0 + m) * K + k0 + k4]);
                As[k4 + 0][m] = v.x; As[k4 + 1][m] = v.y;
                As[k4 + 2][m] = v.z; As[k4 + 3][m] = v.w;
            }
        }
        // ---- stage B tile -> Bs[k][n] ----
        if (!B_NK) {
#pragma unroll
            for (int r = 0; r < 2; r++) {
                int t  = tid + r * 256;
                int k  = t >> 5;
                int n4 = (t & 31) << 2;
                float4 v = *reinterpret_cast<const float4*>(&B[(size_t)(k0 + k) * N + n0 + n4]);
                *reinterpret_cast<float4*>(&Bs[k][n4]) = v;
            }
        } else {
#pragma unroll
            for (int r = 0; r < 2; r++) {
                int t  = tid + r * 256;
                int n  = t >> 2;
                int k4 = (t & 3) << 2;
                float4 v = *reinterpret_cast<const float4*>(&B[(size_t)(n0 + n) * K + k0 + k4]);
                Bs[k4 + 0][n] = v.x; Bs[k4 + 1][n] = v.y;
                Bs[k4 + 2][n] = v.z; Bs[k4 + 3][n] = v.w;
            }
        }
        __syncthreads();

#pragma unroll
        for (int kk = 0; kk < BK; kk++) {
            float4 a0 = *reinterpret_cast<const float4*>(&As[kk][ty * 8]);
            float4 a1 = *reinterpret_cast<const float4*>(&As[kk][ty * 8 + 4]);
            float4 b0 = *reinterpret_cast<const float4*>(&Bs[kk][tx * 8]);
            float4 b1 = *reinterpret_cast<const float4*>(&Bs[kk][tx * 8 + 4]);
            float ra[8] = {a0.x, a0.y, a0.z, a0.w, a1.x, a1.y, a1.z, a1.w};
            float rb[8] = {b0.x, b0.y, b0.z, b0.w, b1.x, b1.y, b1.z, b1.w};
#pragma unroll
            for (int i = 0; i < 8; i++)
#pragma unroll
                for (int j = 0; j < 8; j++)
                    acc[i][j] += ra[i] * rb[j];
        }
        __syncthreads();
    }

    // ---- epilogue ----
#pragma unroll
    for (int i = 0; i < 8; i++) {
        int m = m0 + ty * 8 + i;
        if (m >= M) continue;
        float bv = BIAS ? bias[m] : 0.f;
#pragma unroll
        for (int j = 0; j < 8; j += 4) {
            int n = n0 + tx * 8 + j;
            float4 o;
            o.x = acc[i][j + 0] + bv;
            o.y = acc[i][j + 1] + bv;
            o.z = acc[i][j + 2] + bv;
            o.w = acc[i][j + 3] + bv;
            *reinterpret_cast<float4*>(&C[(size_t)m * N + n]) = o;
            if (SQ) {
                float4 q;
                q.x = o.x * o.x; q.y = o.y * o.y; q.z = o.z * o.z; q.w = o.w * o.w;
                *reinterpret_cast<float4*>(&C2[(size_t)m * N + n]) = q;
            }
        }
    }
}

// ---------------------------------------------------------------------------
// Reductions
// ---------------------------------------------------------------------------
__device__ __forceinline__ float warpMax(float v) {
#pragma unroll
    for (int o = 16; o; o >>= 1) v = fmaxf(v, __shfl_xor_sync(0xffffffffu, v, o));
    return v;
}
__device__ __forceinline__ float warpSum(float v) {
#pragma unroll
    for (int o = 16; o; o >>= 1) v += __shfl_xor_sync(0xffffffffu, v, o);
    return v;
}

// ---------------------------------------------------------------------------
// Masked softmax over rows of S, in place. One block per (b, n) row.
// ---------------------------------------------------------------------------
__global__ __launch_bounds__(256) void softmax_mask_kernel(
    float* __restrict__ S,
    const int* __restrict__ cmask,
    const int* __restrict__ smask)
{
    const int n = blockIdx.x;
    const int b = blockIdx.y;
    float* row = S + ((size_t)b * NTOK + n) * NTOK;
    const int* sm = smask + (size_t)b * NTOK;
    const bool cmn = (cmask[(size_t)b * NTOK + n] != 0);
    const int tid = threadIdx.x;

    __shared__ float red[8];

    float v[16];
    float mx = -INFINITY;
#pragma unroll
    for (int i = 0; i < 16; i++) {
        int m = tid + i * 256;
        float s = row[m];
        if (cmn && sm[m] == 0) s = NEGV;
        v[i] = s;
        mx = fmaxf(mx, s);
    }
    mx = warpMax(mx);
    if ((tid & 31) == 0) red[tid >> 5] = mx;
    __syncthreads();
    if (tid < 32) {
        float x = (tid < 8) ? red[tid] : -INFINITY;
        x = warpMax(x);
        if (tid == 0) red[0] = x;
    }
    __syncthreads();
    mx = red[0];
    __syncthreads();

    float sum = 0.f;
#pragma unroll
    for (int i = 0; i < 16; i++) {
        v[i] = __expf(v[i] - mx);
        sum += v[i];
    }
    sum = warpSum(sum);
    if ((tid & 31) == 0) red[tid >> 5] = sum;
    __syncthreads();
    if (tid < 32) {
        float x = (tid < 8) ? red[tid] : 0.f;
        x = warpSum(x);
        if (tid == 0) red[0] = x;
    }
    __syncthreads();
    const float inv = 1.f / red[0];

#pragma unroll
    for (int i = 0; i < 16; i++)
        row[tid + i * 256] = v[i] * inv;
}

// ---------------------------------------------------------------------------
// Per-(b,c) mean / rstd of content over spatial (unbiased var, torch default)
// ---------------------------------------------------------------------------
__global__ __launch_bounds__(256) void mvn_stats_kernel(
    const float* __restrict__ content,
    float* __restrict__ cmean, float* __restrict__ crstd)
{
    const int c = blockIdx.x;
    const int b = blockIdx.y;
    const float* p = content + ((size_t)b * CIN + c) * NTOK;
    const int tid = threadIdx.x;

    float s = 0.f, ss = 0.f;
#pragma unroll
    for (int i = 0; i < 16; i++) {
        float x = p[tid + i * 256];
        s += x;
        ss += x * x;
    }
    __shared__ float shs[8], shss[8];
    s  = warpSum(s);
    ss = warpSum(ss);
    if ((tid & 31) == 0) { shs[tid >> 5] = s; shss[tid >> 5] = ss; }
    __syncthreads();
    if (tid == 0) {
        float S = 0.f, SS = 0.f;
#pragma unroll
        for (int i = 0; i < 8; i++) { S += shs[i]; SS += shss[i]; }
        float mean = S / (float)NTOK;
        float var  = (SS - S * S / (float)NTOK) / (float)(NTOK - 1);
        cmean[b * CIN + c] = mean;
        crstd[b * CIN + c] = rsqrtf(var + EPSV);
    }
}

// ---------------------------------------------------------------------------
// out = sqrt(relu(m2 - mean^2)) * mvn(content) + mean   (all [b][C][N] layout)
// ---------------------------------------------------------------------------
__global__ __launch_bounds__(256) void combine_kernel(
    const float4* __restrict__ content,
    const float4* __restrict__ meanT,
    const float4* __restrict__ m2T,
    const float*  __restrict__ cmean,
    const float*  __restrict__ crstd,
    float4* __restrict__ out)
{
    const int gid = blockIdx.x * 256 + threadIdx.x;   // over NB*CIN*NTOK/4
    const int bc  = gid >> 10;                        // NTOK/4 = 1024 vec4 per (b,c)
    const float mu = cmean[bc];
    const float rs = crstd[bc];
    float4 mn = meanT[gid];
    float4 m2 = m2T[gid];
    float4 ct = content[gid];
    float4 o;
    o.x = sqrtf(fmaxf(m2.x - mn.x * mn.x, 0.f)) * ((ct.x - mu) * rs) + mn.x;
    o.y = sqrtf(fmaxf(m2.y - mn.y * mn.y, 0.f)) * ((ct.y - mu) * rs) + mn.y;
    o.z = sqrtf(fmaxf(m2.z - mn.z * mn.z, 0.f)) * ((ct.z - mu) * rs) + mn.z;
    o.w = sqrtf(fmaxf(m2.w - mn.w * mn.w, 0.f)) * ((ct.w - mu) * rs) + mn.w;
    out[gid] = o;
}

// ---------------------------------------------------------------------------
// Launch
// ---------------------------------------------------------------------------
extern "C" void kernel_launch(void* const* d_in, const int* in_sizes, int n_in,
                              void* d_out, int out_size)
{
    const float* content = (const float*)d_in[0];
    const float* style   = (const float*)d_in[1];
    const float* ckey    = (const float*)d_in[2];
    const float* skey    = (const float*)d_in[3];
    const int*   cmask   = (const int*)  d_in[4];
    const int*   smask   = (const int*)  d_in[5];
    const float* Wf = (const float*)d_in[6];
    const float* bf = (const float*)d_in[7];
    const float* Wg = (const float*)d_in[8];
    const float* bg = (const float*)d_in[9];
    const float* Wh = (const float*)d_in[10];
    const float* bh = (const float*)d_in[11];
    float* out = (float*)d_out;

    float *pFq, *pG, *pHv, *pHv2, *pS, *pMean, *pM2, *pCm, *pCr;
    cudaGetSymbolAddress((void**)&pFq,  g_FqT);
    cudaGetSymbolAddress((void**)&pG,   g_G);
    cudaGetSymbolAddress((void**)&pHv,  g_HvT);
    cudaGetSymbolAddress((void**)&pHv2, g_Hv2T);
    cudaGetSymbolAddress((void**)&pS,   g_S);
    cudaGetSymbolAddress((void**)&pMean, g_meanT);
    cudaGetSymbolAddress((void**)&pM2,  g_m2T);
    cudaGetSymbolAddress((void**)&pCm,  g_cmean);
    cudaGetSymbolAddress((void**)&pCr,  g_crstd);

    const dim3 blk(256);

    // Projections: out[Cout][N] = W[Cout][Cin] @ X[Cin][N] + b
    gemm128<false, false, true, false><<<dim3(32, 4, NB), blk>>>(
        Wf, ckey, bf, pFq, nullptr, CKEY, NTOK, CKEY,
        0, (size_t)CKEY * NTOK, (size_t)CKEY * NTOK);
    gemm128<false, false, true, false><<<dim3(32, 4, NB), blk>>>(
        Wg, skey, bg, pG, nullptr, CKEY, NTOK, CKEY,
        0, (size_t)CKEY * NTOK, (size_t)CKEY * NTOK);
    gemm128<false, false, true, true><<<dim3(32, 2, NB), blk>>>(
        Wh, style, bh, pHv, pHv2, CIN, NTOK, CIN,
        0, (size_t)CIN * NTOK, (size_t)CIN * NTOK);

    // S[n][m] = sum_k FqT[k][n] * G[k][m]   (TN gemm)
    gemm128<true, false, false, false><<<dim3(32, 32, NB), blk>>>(
        pFq, pG, nullptr, pS, nullptr, NTOK, NTOK, CKEY,
        (size_t)CKEY * NTOK, (size_t)CKEY * NTOK, (size_t)NTOK * NTOK);

    // masked softmax (in place)
    softmax_mask_kernel<<<dim3(NTOK, NB), blk>>>(pS, cmask, smask);

    // meanT[c][n] = sum_m HvT[c][m] * A[n][m]   (NT gemm); same for m2
    gemm128<false, true, false, false><<<dim3(32, 2, NB), blk>>>(
        pHv, pS, nullptr, pMean, nullptr, CIN, NTOK, NTOK,
        (size_t)CIN * NTOK, (size_t)NTOK * NTOK, (size_t)CIN * NTOK);
    gemm128<false, true, false, false><<<dim3(32, 2, NB), blk>>>(
        pHv2, pS, nullptr, pM2, nullptr, CIN, NTOK, NTOK,
        (size_t)CIN * NTOK, (size_t)NTOK * NTOK, (size_t)CIN * NTOK);

    // mvn stats + final combine
    mvn_stats_kernel<<<dim3(CIN, NB), blk>>>(content, pCm, pCr);
    combine_kernel<<<dim3((NB * CIN * NTOK / 4) / 256), blk>>>(
        (const float4*)content, (const float4*)pMean, (const float4*)pM2,
        pCm, pCr, (float4*)out);
}

// round 3
// speedup vs baseline: 2.4540x; 2.4540x over previous
#include <cuda_runtime.h>
#include <cstdint>

// ---------------------------------------------------------------------------
// Problem constants
// ---------------------------------------------------------------------------
#define NB   4
#define CIN  256
#define CKEY 448
#define NTOK 4096
#define NEGV (-1e15f)
#define EPSV 1e-5f

// ---------------------------------------------------------------------------
// Scratch (static device globals; no runtime allocation)
// ---------------------------------------------------------------------------
__device__ float g_FqT [(size_t)NB * CKEY * NTOK];   // [b][Ck][N] f(ckey)
__device__ float g_G   [(size_t)NB * CKEY * NTOK];   // [b][Ck][N] g(skey)
__device__ float g_FqN [(size_t)NB * NTOK * CKEY];   // [b][N][Ck] token-major (tf32)
__device__ float g_GN  [(size_t)NB * NTOK * CKEY];   // [b][N][Ck] token-major (tf32)
__device__ float g_HvT [(size_t)NB * CIN  * NTOK];   // [b][C][N]  h(style)   (tf32)
__device__ float g_Hv2T[(size_t)NB * CIN  * NTOK];   // [b][C][N]  h(style)^2 (tf32)
__device__ float g_S   [(size_t)NB * NTOK * NTOK];   // [b][N][N]  scores -> attn
__device__ float g_meanT[(size_t)NB * CIN * NTOK];   // [b][C][N]
__device__ float g_m2T [(size_t)NB * CIN  * NTOK];   // [b][C][N]
__device__ float g_cmean[NB * CIN];
__device__ float g_crstd[NB * CIN];

// ---------------------------------------------------------------------------
// Helpers (sm_103 baseline features only — NO 'a'-suffix instructions)
// ---------------------------------------------------------------------------
__device__ __forceinline__ uint32_t smem_u32(const void* p) {
    uint32_t a;
    asm("{ .reg .u64 t; cvta.to.shared.u64 t, %1; cvt.u32.u64 %0, t; }"
        : "=r"(a) : "l"(p));
    return a;
}
__device__ __forceinline__ float tf32r(float x) {
    float y;
    asm("cvt.rna.tf32.f32 %0, %1;" : "=f"(y) : "f"(x));
    return y;
}
__device__ __forceinline__ void cp16(uint32_t s, const void* g) {
    asm volatile("cp.async.cg.shared.global [%0], [%1], 16;" :: "r"(s), "l"(g));
}
__device__ __forceinline__ void cp_commit() {
    asm volatile("cp.async.commit_group;" ::: "memory");
}
template <int N> __device__ __forceinline__ void cp_wait() {
    asm volatile("cp.async.wait_group %0;" :: "n"(N) : "memory");
}
__device__ __forceinline__ void mma_tf32(float* d, const uint32_t* a, const uint32_t* b) {
    asm volatile(
        "mma.sync.aligned.m16n8k8.row.col.f32.tf32.tf32.f32 "
        "{%0,%1,%2,%3}, {%4,%5,%6,%7}, {%8,%9}, {%0,%1,%2,%3};"
        : "+f"(d[0]), "+f"(d[1]), "+f"(d[2]), "+f"(d[3])
        : "r"(a[0]), "r"(a[1]), "r"(a[2]), "r"(a[3]), "r"(b[0]), "r"(b[1]));
}

// ---------------------------------------------------------------------------
// TF32 mma.sync GEMM:  C[M][N] = A[M][K] * B[N][K]^T   (both row-major-by-K)
//   - 256 threads, warp grid WMW x WNW, warp tile 32x64 (2x8 m16n8k8 tiles)
//   - BK = 32, cp.async double buffer, padded smem stride 36 (conflict-free)
//   - TRANS: store C transposed: out[col*ldc + row]  (for [C][N] outputs)
// M % BM == 0, N % BN == 0, K % 32 == 0 (all true for this problem).
// ---------------------------------------------------------------------------
template <int BM, int BN, int WMW, int WNW, bool TRANS>
__global__ __launch_bounds__(256) void mma_gemm(
    const float* __restrict__ A, const float* __restrict__ B,
    float* __restrict__ C,
    int K, int lda, int ldb, int ldc,
    size_t sA, size_t sB, size_t sC)
{
    constexpr int ASZ = BM * 36;
    constexpr int BSZ = BN * 36;
    constexpr int STG = ASZ + BSZ;          // floats per stage
    constexpr int AV4 = BM * 8 / 256;       // float4 loads per thread for A
    constexpr int BV4 = BN * 8 / 256;

    extern __shared__ float sm[];
    const uint32_t sbase = smem_u32(sm);

    const int tid = threadIdx.x, lane = tid & 31, wid = tid >> 5;
    const int wM = wid % WMW, wN = wid / WMW;
    const int m0 = blockIdx.y * BM, n0 = blockIdx.x * BN, b = blockIdx.z;

    A += (size_t)b * sA + (size_t)m0 * lda;
    B += (size_t)b * sB + (size_t)n0 * ldb;
    C += (size_t)b * sC;

    float acc[2][8][4];
#pragma unroll
    for (int mi = 0; mi < 2; mi++)
#pragma unroll
        for (int ni = 0; ni < 8; ni++)
#pragma unroll
            for (int q = 0; q < 4; q++) acc[mi][ni][q] = 0.f;

    const int NK = K >> 5;

    // ---- prefetch stage 0 ----
    {
#pragma unroll
        for (int v = 0; v < AV4; v++) {
            int t = tid + v * 256, r = t >> 3, cf = (t & 7) << 2;
            cp16(sbase + (uint32_t)(r * 36 + cf) * 4, A + (size_t)r * lda + cf);
        }
#pragma unroll
        for (int v = 0; v < BV4; v++) {
            int t = tid + v * 256, r = t >> 3, cf = (t & 7) << 2;
            cp16(sbase + (uint32_t)(ASZ + r * 36 + cf) * 4, B + (size_t)r * ldb + cf);
        }
        cp_commit();
    }

    for (int i = 0; i < NK; i++) {
        if (i + 1 < NK) {
            const int st = (i + 1) & 1;
            const int k0 = (i + 1) << 5;
#pragma unroll
            for (int v = 0; v < AV4; v++) {
                int t = tid + v * 256, r = t >> 3, cf = (t & 7) << 2;
                cp16(sbase + (uint32_t)(st * STG + r * 36 + cf) * 4,
                     A + (size_t)r * lda + k0 + cf);
            }
#pragma unroll
            for (int v = 0; v < BV4; v++) {
                int t = tid + v * 256, r = t >> 3, cf = (t & 7) << 2;
                cp16(sbase + (uint32_t)(st * STG + ASZ + r * 36 + cf) * 4,
                     B + (size_t)r * ldb + k0 + cf);
            }
            cp_commit();
            cp_wait<1>();
        } else {
            cp_wait<0>();
        }
        __syncthreads();

        const float* As = sm + (i & 1) * STG;
        const float* Bs = As + ASZ;
        const int r = lane >> 2, c = lane & 3;

#pragma unroll
        for (int kk = 0; kk < 4; kk++) {
            const int k8 = kk * 8;
            uint32_t af[2][4], bf[8][2];
#pragma unroll
            for (int mi = 0; mi < 2; mi++) {
                const int row = wM * 32 + mi * 16;
                af[mi][0] = __float_as_uint(As[(row + r) * 36 + k8 + c]);
                af[mi][1] = __float_as_uint(As[(row + 8 + r) * 36 + k8 + c]);
                af[mi][2] = __float_as_uint(As[(row + r) * 36 + k8 + c + 4]);
                af[mi][3] = __float_as_uint(As[(row + 8 + r) * 36 + k8 + c + 4]);
            }
#pragma unroll
            for (int ni = 0; ni < 8; ni++) {
                const int nr = wN * 64 + ni * 8 + r;
                bf[ni][0] = __float_as_uint(Bs[nr * 36 + k8 + c]);
                bf[ni][1] = __float_as_uint(Bs[nr * 36 + k8 + c + 4]);
            }
#pragma unroll
            for (int mi = 0; mi < 2; mi++)
#pragma unroll
                for (int ni = 0; ni < 8; ni++)
                    mma_tf32(acc[mi][ni], af[mi], bf[ni]);
        }
        __syncthreads();
    }

    // ---- epilogue ----
    const int r = lane >> 2, c = lane & 3;
#pragma unroll
    for (int mi = 0; mi < 2; mi++) {
        const int row0 = m0 + wM * 32 + mi * 16 + r;
#pragma unroll
        for (int ni = 0; ni < 8; ni++) {
            const int col = n0 + wN * 64 + ni * 8 + c * 2;
            if (!TRANS) {
                float2 v0 = make_float2(acc[mi][ni][0], acc[mi][ni][1]);
                float2 v1 = make_float2(acc[mi][ni][2], acc[mi][ni][3]);
                *reinterpret_cast<float2*>(&C[(size_t)row0 * ldc + col]) = v0;
                *reinterpret_cast<float2*>(&C[(size_t)(row0 + 8) * ldc + col]) = v1;
            } else {
                C[(size_t)col * ldc + row0]           = acc[mi][ni][0];
                C[(size_t)(col + 1) * ldc + row0]     = acc[mi][ni][1];
                C[(size_t)col * ldc + row0 + 8]       = acc[mi][ni][2];
                C[(size_t)(col + 1) * ldc + row0 + 8] = acc[mi][ni][3];
            }
        }
    }
}

// ---------------------------------------------------------------------------
// SIMT SGEMM for projections (from R1) + optional tf32 rounding of outputs
// ---------------------------------------------------------------------------
template <bool A_KM, bool B_NK, bool BIAS, bool SQ, bool TF32R>
__global__ __launch_bounds__(256) void gemm128(
    const float* __restrict__ A, const float* __restrict__ B,
    const float* __restrict__ bias,
    float* __restrict__ C, float* __restrict__ C2,
    int M, int N, int K,
    size_t sA, size_t sB, size_t sC)
{
    constexpr int BM = 128, BN = 128, BK = 16;
    __shared__ float As[BK][BM + 4];
    __shared__ float Bs[BK][BN + 4];

    const int tid = threadIdx.x;
    const int tx = tid & 15, ty = tid >> 4, bz = blockIdx.z;
    A += (size_t)bz * sA; B += (size_t)bz * sB; C += (size_t)bz * sC;
    if (SQ) C2 += (size_t)bz * sC;
    const int m0 = blockIdx.y * BM, n0 = blockIdx.x * BN;

    float acc[8][8];
#pragma unroll
    for (int i = 0; i < 8; i++)
#pragma unroll
        for (int j = 0; j < 8; j++) acc[i][j] = 0.f;

    for (int k0 = 0; k0 < K; k0 += BK) {
        if (A_KM) {
#pragma unroll
            for (int r = 0; r < 2; r++) {
                int t = tid + r * 256, k = t >> 5, m4 = (t & 31) << 2;
                float4 v = make_float4(0.f, 0.f, 0.f, 0.f);
                if (m0 + m4 < M)
                    v = *reinterpret_cast<const float4*>(&A[(size_t)(k0 + k) * M + m0 + m4]);
                *reinterpret_cast<float4*>(&As[k][m4]) = v;
            }
        } else {
#pragma unroll
            for (int r = 0; r < 2; r++) {
                int t = tid + r * 256, m = t >> 2, k4 = (t & 3) << 2;
                float4 v = make_float4(0.f, 0.f, 0.f, 0.f);
                if (m0 + m < M)
                    v = *reinterpret_cast<const float4*>(&A[(size_t)(m0 + m) * K + k0 + k4]);
                As[k4 + 0][m] = v.x; As[k4 + 1][m] = v.y;
                As[k4 + 2][m] = v.z; As[k4 + 3][m] = v.w;
            }
        }
        if (!B_NK) {
#pragma unroll
            for (int r = 0; r < 2; r++) {
                int t = tid + r * 256, k = t >> 5, n4 = (t & 31) << 2;
                float4 v = *reinterpret_cast<const float4*>(&B[(size_t)(k0 + k) * N + n0 + n4]);
                *reinterpret_cast<float4*>(&Bs[k][n4]) = v;
            }
        } else {
#pragma unroll
            for (int r = 0; r < 2; r++) {
                int t = tid + r * 256, n = t >> 2, k4 = (t & 3) << 2;
                float4 v = *reinterpret_cast<const float4*>(&B[(size_t)(n0 + n) * K + k0 + k4]);
                Bs[k4 + 0][n] = v.x; Bs[k4 + 1][n] = v.y;
                Bs[k4 + 2][n] = v.z; Bs[k4 + 3][n] = v.w;
            }
        }
        __syncthreads();
#pragma unroll
        for (int kk = 0; kk < BK; kk++) {
            float4 a0 = *reinterpret_cast<const float4*>(&As[kk][ty * 8]);
            float4 a1 = *reinterpret_cast<const float4*>(&As[kk][ty * 8 + 4]);
            float4 b0 = *reinterpret_cast<const float4*>(&Bs[kk][tx * 8]);
            float4 b1 = *reinterpret_cast<const float4*>(&Bs[kk][tx * 8 + 4]);
            float ra[8] = {a0.x, a0.y, a0.z, a0.w, a1.x, a1.y, a1.z, a1.w};
            float rb[8] = {b0.x, b0.y, b0.z, b0.w, b1.x, b1.y, b1.z, b1.w};
#pragma unroll
            for (int i = 0; i < 8; i++)
#pragma unroll
                for (int j = 0; j < 8; j++)
                    acc[i][j] += ra[i] * rb[j];
        }
        __syncthreads();
    }

#pragma unroll
    for (int i = 0; i < 8; i++) {
        int m = m0 + ty * 8 + i;
        if (m >= M) continue;
        float bv = BIAS ? bias[m] : 0.f;
#pragma unroll
        for (int j = 0; j < 8; j += 4) {
            int n = n0 + tx * 8 + j;
            float4 o;
            o.x = acc[i][j + 0] + bv;
            o.y = acc[i][j + 1] + bv;
            o.z = acc[i][j + 2] + bv;
            o.w = acc[i][j + 3] + bv;
            if (TF32R) {
                o.x = tf32r(o.x); o.y = tf32r(o.y); o.z = tf32r(o.z); o.w = tf32r(o.w);
            }
            *reinterpret_cast<float4*>(&C[(size_t)m * N + n]) = o;
            if (SQ) {
                float4 q;
                q.x = tf32r(o.x * o.x); q.y = tf32r(o.y * o.y);
                q.z = tf32r(o.z * o.z); q.w = tf32r(o.w * o.w);
                *reinterpret_cast<float4*>(&C2[(size_t)m * N + n]) = q;
            }
        }
    }
}

// ---------------------------------------------------------------------------
// Transpose [Ck][N] -> [N][Ck] with tf32 rounding. z = b + 4*tensorIdx.
// ---------------------------------------------------------------------------
__global__ __launch_bounds__(256) void transpose_tf32_kernel(
    const float* __restrict__ inF, float* __restrict__ outF,
    const float* __restrict__ inG, float* __restrict__ outG)
{
    __shared__ float t[32][33];
    const int z = blockIdx.z;
    const int b = z & 3;
    const float* in = (z < 4) ? inF : inG;
    float* out = (z < 4) ? outF : outG;
    in  += (size_t)b * CKEY * NTOK;
    out += (size_t)b * NTOK * CKEY;

    const int x0 = blockIdx.x * 32;   // token
    const int y0 = blockIdx.y * 32;   // channel
    const int tx = threadIdx.x & 31, ty = threadIdx.x >> 5;

#pragma unroll
    for (int i = 0; i < 4; i++)
        t[ty + i * 8][tx] = in[(size_t)(y0 + ty + i * 8) * NTOK + x0 + tx];
    __syncthreads();
#pragma unroll
    for (int i = 0; i < 4; i++)
        out[(size_t)(x0 + ty + i * 8) * CKEY + y0 + tx] = tf32r(t[tx][ty + i * 8]);
}

// ---------------------------------------------------------------------------
// Reductions / softmax / stats / combine
// ---------------------------------------------------------------------------
__device__ __forceinline__ float warpMax(float v) {
#pragma unroll
    for (int o = 16; o; o >>= 1) v = fmaxf(v, __shfl_xor_sync(0xffffffffu, v, o));
    return v;
}
__device__ __forceinline__ float warpSum(float v) {
#pragma unroll
    for (int o = 16; o; o >>= 1) v += __shfl_xor_sync(0xffffffffu, v, o);
    return v;
}

__global__ __launch_bounds__(256) void softmax_mask_kernel(
    float* __restrict__ S,
    const int* __restrict__ cmask,
    const int* __restrict__ smask)
{
    const int n = blockIdx.x, b = blockIdx.y;
    float* row = S + ((size_t)b * NTOK + n) * NTOK;
    const int* sm = smask + (size_t)b * NTOK;
    const bool cmn = (cmask[(size_t)b * NTOK + n] != 0);
    const int tid = threadIdx.x;
    __shared__ float red[8];

    float v[16];
    float mx = -INFINITY;
#pragma unroll
    for (int i = 0; i < 16; i++) {
        int m = tid + i * 256;
        float s = row[m];
        if (cmn && sm[m] == 0) s = NEGV;
        v[i] = s;
        mx = fmaxf(mx, s);
    }
    mx = warpMax(mx);
    if ((tid & 31) == 0) red[tid >> 5] = mx;
    __syncthreads();
    if (tid < 32) {
        float x = (tid < 8) ? red[tid] : -INFINITY;
        x = warpMax(x);
        if (tid == 0) red[0] = x;
    }
    __syncthreads();
    mx = red[0];
    __syncthreads();

    float sum = 0.f;
#pragma unroll
    for (int i = 0; i < 16; i++) { v[i] = __expf(v[i] - mx); sum += v[i]; }
    sum = warpSum(sum);
    if ((tid & 31) == 0) red[tid >> 5] = sum;
    __syncthreads();
    if (tid < 32) {
        float x = (tid < 8) ? red[tid] : 0.f;
        x = warpSum(x);
        if (tid == 0) red[0] = x;
    }
    __syncthreads();
    const float inv = 1.f / red[0];
#pragma unroll
    for (int i = 0; i < 16; i++)
        row[tid + i * 256] = tf32r(v[i] * inv);
}

__global__ __launch_bounds__(256) void mvn_stats_kernel(
    const float* __restrict__ content,
    float* __restrict__ cmean, float* __restrict__ crstd)
{
    const int c = blockIdx.x, b = blockIdx.y;
    const float* p = content + ((size_t)b * CIN + c) * NTOK;
    const int tid = threadIdx.x;
    float s = 0.f, ss = 0.f;
#pragma unroll
    for (int i = 0; i < 16; i++) {
        float x = p[tid + i * 256];
        s += x; ss += x * x;
    }
    __shared__ float shs[8], shss[8];
    s = warpSum(s); ss = warpSum(ss);
    if ((tid & 31) == 0) { shs[tid >> 5] = s; shss[tid >> 5] = ss; }
    __syncthreads();
    if (tid == 0) {
        float S = 0.f, SS = 0.f;
#pragma unroll
        for (int i = 0; i < 8; i++) { S += shs[i]; SS += shss[i]; }
        float mean = S / (float)NTOK;
        float var = (SS - S * S / (float)NTOK) / (float)(NTOK - 1);
        cmean[b * CIN + c] = mean;
        crstd[b * CIN + c] = rsqrtf(var + EPSV);
    }
}

__global__ __launch_bounds__(256) void combine_kernel(
    const float4* __restrict__ content,
    const float4* __restrict__ meanT,
    const float4* __restrict__ m2T,
    const float* __restrict__ cmean,
    const float* __restrict__ crstd,
    float4* __restrict__ out)
{
    const int gid = blockIdx.x * 256 + threadIdx.x;
    const int bc = gid >> 10;
    const float mu = cmean[bc];
    const float rs = crstd[bc];
    float4 mn = meanT[gid];
    float4 m2 = m2T[gid];
    float4 ct = content[gid];
    float4 o;
    o.x = sqrtf(fmaxf(m2.x - mn.x * mn.x, 0.f)) * ((ct.x - mu) * rs) + mn.x;
    o.y = sqrtf(fmaxf(m2.y - mn.y * mn.y, 0.f)) * ((ct.y - mu) * rs) + mn.y;
    o.z = sqrtf(fmaxf(m2.z - mn.z * mn.z, 0.f)) * ((ct.z - mu) * rs) + mn.z;
    o.w = sqrtf(fmaxf(m2.w - mn.w * mn.w, 0.f)) * ((ct.w - mu) * rs) + mn.w;
    out[gid] = o;
}

// ---------------------------------------------------------------------------
// Launch
// ---------------------------------------------------------------------------
extern "C" void kernel_launch(void* const* d_in, const int* in_sizes, int n_in,
                              void* d_out, int out_size)
{
    const float* content = (const float*)d_in[0];
    const float* style   = (const float*)d_in[1];
    const float* ckey    = (const float*)d_in[2];
    const float* skey    = (const float*)d_in[3];
    const int*   cmask   = (const int*)  d_in[4];
    const int*   smask   = (const int*)  d_in[5];
    const float* Wf = (const float*)d_in[6];
    const float* bf = (const float*)d_in[7];
    const float* Wg = (const float*)d_in[8];
    const float* bg = (const float*)d_in[9];
    const float* Wh = (const float*)d_in[10];
    const float* bh = (const float*)d_in[11];
    float* out = (float*)d_out;

    float *pFqT, *pG, *pFqN, *pGN, *pHv, *pHv2, *pS, *pMean, *pM2, *pCm, *pCr;
    cudaGetSymbolAddress((void**)&pFqT, g_FqT);
    cudaGetSymbolAddress((void**)&pG,   g_G);
    cudaGetSymbolAddress((void**)&pFqN, g_FqN);
    cudaGetSymbolAddress((void**)&pGN,  g_GN);
    cudaGetSymbolAddress((void**)&pHv,  g_HvT);
    cudaGetSymbolAddress((void**)&pHv2, g_Hv2T);
    cudaGetSymbolAddress((void**)&pS,   g_S);
    cudaGetSymbolAddress((void**)&pMean, g_meanT);
    cudaGetSymbolAddress((void**)&pM2,  g_m2T);
    cudaGetSymbolAddress((void**)&pCm,  g_cmean);
    cudaGetSymbolAddress((void**)&pCr,  g_crstd);

    // dynamic smem sizes: (BM*36 + BN*36) * 4B * 2 stages
    constexpr int SMEM_S  = (128 * 36 + 128 * 36) * 4 * 2;  // 73728
    constexpr int SMEM_AV = (64 * 36 + 256 * 36) * 4 * 2;   // 92160

    static bool attr_done = false;
    if (!attr_done) {
        cudaFuncSetAttribute(mma_gemm<128, 128, 4, 2, false>,
                             cudaFuncAttributeMaxDynamicSharedMemorySize, SMEM_S);
        cudaFuncSetAttribute(mma_gemm<64, 256, 2, 4, true>,
                             cudaFuncAttributeMaxDynamicSharedMemorySize, SMEM_AV);
        attr_done = true;
    }

    const dim3 blk(256);

    // Projections: out[Cout][N] = W @ X + b
    gemm128<false, false, true, false, false><<<dim3(32, 4, NB), blk>>>(
        Wf, ckey, bf, pFqT, nullptr, CKEY, NTOK, CKEY,
        0, (size_t)CKEY * NTOK, (size_t)CKEY * NTOK);
    gemm128<false, false, true, false, false><<<dim3(32, 4, NB), blk>>>(
        Wg, skey, bg, pG, nullptr, CKEY, NTOK, CKEY,
        0, (size_t)CKEY * NTOK, (size_t)CKEY * NTOK);
    gemm128<false, false, true, true, true><<<dim3(32, 2, NB), blk>>>(
        Wh, style, bh, pHv, pHv2, CIN, NTOK, CIN,
        0, (size_t)CIN * NTOK, (size_t)CIN * NTOK);

    // token-major tf32 copies of Fq, G
    transpose_tf32_kernel<<<dim3(NTOK / 32, CKEY / 32, 2 * NB), blk>>>(pFqT, pFqN, pG, pGN);

    // S[n][m] = FqN[n][:] . GN[m][:]   (tf32 mma.sync)
    mma_gemm<128, 128, 4, 2, false><<<dim3(32, 32, NB), blk, SMEM_S>>>(
        pFqN, pGN, pS, CKEY, CKEY, CKEY, NTOK,
        (size_t)NTOK * CKEY, (size_t)NTOK * CKEY, (size_t)NTOK * NTOK);

    // masked softmax (in place, tf32-rounded output)
    softmax_mask_kernel<<<dim3(NTOK, NB), blk>>>(pS, cmask, smask);

    // meanT[c][n] = sum_m A[n][m] * Hv[c][m]  (transposed store); same for m2
    mma_gemm<64, 256, 2, 4, true><<<dim3(1, 64, NB), blk, SMEM_AV>>>(
        pS, pHv, pMean, NTOK, NTOK, NTOK, NTOK,
        (size_t)NTOK * NTOK, (size_t)CIN * NTOK, (size_t)CIN * NTOK);
    mma_gemm<64, 256, 2, 4, true><<<dim3(1, 64, NB), blk, SMEM_AV>>>(
        pS, pHv2, pM2, NTOK, NTOK, NTOK, NTOK,
        (size_t)NTOK * NTOK, (size_t)CIN * NTOK, (size_t)CIN * NTOK);

    // mvn stats + final combine
    mvn_stats_kernel<<<dim3(CIN, NB), blk>>>(content, pCm, pCr);
    combine_kernel<<<dim3((NB * CIN * NTOK / 4) / 256), blk>>>(
        (const float4*)content, (const float4*)pMean, (const float4*)pM2,
        pCm, pCr, (float4*)out);
}

// round 4
// speedup vs baseline: 3.1061x; 1.2657x over previous
#include <cuda_runtime.h>
#include <cstdint>

// ---------------------------------------------------------------------------
// Problem constants
// ---------------------------------------------------------------------------
#define NB   4
#define CIN  256
#define CKEY 448
#define NTOK 4096
#define NEGV (-1e15f)
#define EPSV 1e-5f
#define CKP  512   // padded CKEY for projection N-dim

// ---------------------------------------------------------------------------
// Scratch (static device globals; no runtime allocation)
// ---------------------------------------------------------------------------
__device__ float g_ckT [(size_t)NB * NTOK * CKEY];   // [b][N][Ck] ckey^T (tf32)
__device__ float g_skT [(size_t)NB * NTOK * CKEY];   // [b][N][Ck] skey^T (tf32)
__device__ float g_stT [(size_t)NB * NTOK * CIN];    // [b][N][C]  style^T (tf32)
__device__ float g_FqN [(size_t)NB * NTOK * CKEY];   // [b][N][Ck] f(ckey) token-major
__device__ float g_GN  [(size_t)NB * NTOK * CKEY];   // [b][N][Ck] g(skey) token-major
__device__ float g_HvT [(size_t)NB * CIN  * NTOK];   // [b][C][N]  h(style)   (tf32)
__device__ float g_Hv2T[(size_t)NB * CIN  * NTOK];   // [b][C][N]  h(style)^2 (tf32)
__device__ float g_S   [(size_t)NB * NTOK * NTOK];   // [b][N][N]  scores -> attn
__device__ float g_meanT[(size_t)NB * CIN * NTOK];   // [b][C][N]
__device__ float g_m2T [(size_t)NB * CIN  * NTOK];   // [b][C][N]
__device__ float g_Wf  [CKP * CKEY];                 // rounded, zero-padded rows
__device__ float g_Wg  [CKP * CKEY];
__device__ float g_Wh  [CIN * CIN];
__device__ float g_bf  [CKP];
__device__ float g_bg  [CKP];
__device__ float g_cmean[NB * CIN];
__device__ float g_crstd[NB * CIN];

// ---------------------------------------------------------------------------
// Helpers (sm_103 baseline features only)
// ---------------------------------------------------------------------------
__device__ __forceinline__ uint32_t smem_u32(const void* p) {
    uint32_t a;
    asm("{ .reg .u64 t; cvta.to.shared.u64 t, %1; cvt.u32.u64 %0, t; }"
        : "=r"(a) : "l"(p));
    return a;
}
__device__ __forceinline__ float tf32r(float x) {
    float y;
    asm("cvt.rna.tf32.f32 %0, %1;" : "=f"(y) : "f"(x));
    return y;
}
__device__ __forceinline__ void cp16(uint32_t s, const void* g) {
    asm volatile("cp.async.cg.shared.global [%0], [%1], 16;" :: "r"(s), "l"(g));
}
__device__ __forceinline__ void cp_commit() {
    asm volatile("cp.async.commit_group;" ::: "memory");
}
template <int N> __device__ __forceinline__ void cp_wait() {
    asm volatile("cp.async.wait_group %0;" :: "n"(N) : "memory");
}
__device__ __forceinline__ void mma_tf32(float* d, const uint32_t* a, const uint32_t* b) {
    asm volatile(
        "mma.sync.aligned.m16n8k8.row.col.f32.tf32.tf32.f32 "
        "{%0,%1,%2,%3}, {%4,%5,%6,%7}, {%8,%9}, {%0,%1,%2,%3};"
        : "+f"(d[0]), "+f"(d[1]), "+f"(d[2]), "+f"(d[3])
        : "r"(a[0]), "r"(a[1]), "r"(a[2]), "r"(a[3]), "r"(b[0]), "r"(b[1]));
}

// ---------------------------------------------------------------------------
// Generic TF32 mma.sync GEMM:  C[M][N] = A[M][K] * B[N][K]^T
//   256 threads, WMW x (8/WMW) warps, warp tile (BM/WMW) x (BN*WMW/8)
//   BK=32, cp.async double buffer, smem row stride 36 (conflict-free)
//   BIAS_MODE: 0 none, 1 along M, 2 along N
//   TF32R: round outputs to tf32 (rna)     SQ: also write C2 = round(C*C)
//   Store guard: column < Nrt.
// ---------------------------------------------------------------------------
template <int BM, int BN, int WMW, int BIAS_MODE, bool TF32R, bool SQ>
__global__ __launch_bounds__(256) void mma_gemmX(
    const float* __restrict__ A, const float* __restrict__ B,
    const float* __restrict__ bias,
    float* __restrict__ C, float* __restrict__ C2,
    int Nrt, int K, int lda, int ldb, int ldc,
    size_t sA, size_t sB, size_t sC)
{
    constexpr int WNW = 8 / WMW;
    constexpr int WTM = BM / WMW;          // warp tile M
    constexpr int WTN = BN / WNW;          // warp tile N
    constexpr int MI  = WTM / 16;
    constexpr int NI  = WTN / 8;
    constexpr int ASZ = BM * 36;
    constexpr int BSZ = BN * 36;
    constexpr int STG = ASZ + BSZ;
    constexpr int AV4 = BM * 8 / 256;
    constexpr int BV4 = BN * 8 / 256;

    extern __shared__ float sm[];
    const uint32_t sbase = smem_u32(sm);

    const int tid = threadIdx.x, lane = tid & 31, wid = tid >> 5;
    const int wM = wid % WMW, wN = wid / WMW;
    const int m0 = blockIdx.y * BM, n0 = blockIdx.x * BN, b = blockIdx.z;

    A += (size_t)b * sA + (size_t)m0 * lda;
    B += (size_t)b * sB + (size_t)n0 * ldb;
    C += (size_t)b * sC;
    if (SQ) C2 += (size_t)b * sC;

    float acc[MI][NI][4];
#pragma unroll
    for (int mi = 0; mi < MI; mi++)
#pragma unroll
        for (int ni = 0; ni < NI; ni++)
#pragma unroll
            for (int q = 0; q < 4; q++) acc[mi][ni][q] = 0.f;

    const int NK = K >> 5;

    {
#pragma unroll
        for (int v = 0; v < AV4; v++) {
            int t = tid + v * 256, r = t >> 3, cf = (t & 7) << 2;
            cp16(sbase + (uint32_t)(r * 36 + cf) * 4, A + (size_t)r * lda + cf);
        }
#pragma unroll
        for (int v = 0; v < BV4; v++) {
            int t = tid + v * 256, r = t >> 3, cf = (t & 7) << 2;
            cp16(sbase + (uint32_t)(ASZ + r * 36 + cf) * 4, B + (size_t)r * ldb + cf);
        }
        cp_commit();
    }

    for (int i = 0; i < NK; i++) {
        if (i + 1 < NK) {
            const int st = (i + 1) & 1;
            const int k0 = (i + 1) << 5;
#pragma unroll
            for (int v = 0; v < AV4; v++) {
                int t = tid + v * 256, r = t >> 3, cf = (t & 7) << 2;
                cp16(sbase + (uint32_t)(st * STG + r * 36 + cf) * 4,
                     A + (size_t)r * lda + k0 + cf);
            }
#pragma unroll
            for (int v = 0; v < BV4; v++) {
                int t = tid + v * 256, r = t >> 3, cf = (t & 7) << 2;
                cp16(sbase + (uint32_t)(st * STG + ASZ + r * 36 + cf) * 4,
                     B + (size_t)r * ldb + k0 + cf);
            }
            cp_commit();
            cp_wait<1>();
        } else {
            cp_wait<0>();
        }
        __syncthreads();

        const float* As = sm + (i & 1) * STG;
        const float* Bs = As + ASZ;
        const int r = lane >> 2, c = lane & 3;

#pragma unroll
        for (int kk = 0; kk < 4; kk++) {
            const int k8 = kk * 8;
            uint32_t af[MI][4], bf[NI][2];
#pragma unroll
            for (int mi = 0; mi < MI; mi++) {
                const int row = wM * WTM + mi * 16;
                af[mi][0] = __float_as_uint(As[(row + r) * 36 + k8 + c]);
                af[mi][1] = __float_as_uint(As[(row + 8 + r) * 36 + k8 + c]);
                af[mi][2] = __float_as_uint(As[(row + r) * 36 + k8 + c + 4]);
                af[mi][3] = __float_as_uint(As[(row + 8 + r) * 36 + k8 + c + 4]);
            }
#pragma unroll
            for (int ni = 0; ni < NI; ni++) {
                const int nr = wN * WTN + ni * 8 + r;
                bf[ni][0] = __float_as_uint(Bs[nr * 36 + k8 + c]);
                bf[ni][1] = __float_as_uint(Bs[nr * 36 + k8 + c + 4]);
            }
#pragma unroll
            for (int mi = 0; mi < MI; mi++)
#pragma unroll
                for (int ni = 0; ni < NI; ni++)
                    mma_tf32(acc[mi][ni], af[mi], bf[ni]);
        }
        __syncthreads();
    }

    // ---- epilogue ----
    const int r = lane >> 2, c = lane & 3;
#pragma unroll
    for (int mi = 0; mi < MI; mi++) {
        const int row0 = m0 + wM * WTM + mi * 16 + r;
        float bm0 = 0.f, bm1 = 0.f;
        if (BIAS_MODE == 1) { bm0 = bias[row0]; bm1 = bias[row0 + 8]; }
#pragma unroll
        for (int ni = 0; ni < NI; ni++) {
            const int col = n0 + wN * WTN + ni * 8 + c * 2;
            if (col >= Nrt) continue;
            float o0 = acc[mi][ni][0], o1 = acc[mi][ni][1];
            float o2 = acc[mi][ni][2], o3 = acc[mi][ni][3];
            if (BIAS_MODE == 1) { o0 += bm0; o1 += bm0; o2 += bm1; o3 += bm1; }
            if (BIAS_MODE == 2) {
                float bn0 = bias[col], bn1 = bias[col + 1];
                o0 += bn0; o1 += bn1; o2 += bn0; o3 += bn1;
            }
            if (TF32R) { o0 = tf32r(o0); o1 = tf32r(o1); o2 = tf32r(o2); o3 = tf32r(o3); }
            *reinterpret_cast<float2*>(&C[(size_t)row0 * ldc + col])       = make_float2(o0, o1);
            *reinterpret_cast<float2*>(&C[(size_t)(row0 + 8) * ldc + col]) = make_float2(o2, o3);
            if (SQ) {
                float q0 = tf32r(o0 * o0), q1 = tf32r(o1 * o1);
                float q2 = tf32r(o2 * o2), q3 = tf32r(o3 * o3);
                *reinterpret_cast<float2*>(&C2[(size_t)row0 * ldc + col])       = make_float2(q0, q1);
                *reinterpret_cast<float2*>(&C2[(size_t)(row0 + 8) * ldc + col]) = make_float2(q2, q3);
            }
        }
    }
}

// ---------------------------------------------------------------------------
// Dual-B fused GEMM for mean & m2: shares attn A tiles.
//   C1[n][c] = A[n][:] . B1[c][:],  C2[n][c] = A[n][:] . B2[c][:]
//   BM=64, BN=128, warps 2x4 (warp tile 32x32). Transposed store: out[c][n].
// ---------------------------------------------------------------------------
#define DUAL_SMEM ((64 * 36 + 2 * 128 * 36) * 4 * 2)
__global__ __launch_bounds__(256) void mma_gemm_dual(
    const float* __restrict__ A, const float* __restrict__ B1,
    const float* __restrict__ B2,
    float* __restrict__ C1, float* __restrict__ C2)
{
    constexpr int BM = 64, BN = 128;
    constexpr int ASZ = BM * 36, BSZ = BN * 36;
    constexpr int STG = ASZ + 2 * BSZ;

    extern __shared__ float sm[];
    const uint32_t sbase = smem_u32(sm);

    const int tid = threadIdx.x, lane = tid & 31, wid = tid >> 5;
    const int wM = wid & 1, wN = wid >> 1;
    const int m0 = blockIdx.y * BM, n0 = blockIdx.x * BN, b = blockIdx.z;

    A  += (size_t)b * NTOK * NTOK + (size_t)m0 * NTOK;
    B1 += (size_t)b * CIN * NTOK + (size_t)n0 * NTOK;
    B2 += (size_t)b * CIN * NTOK + (size_t)n0 * NTOK;
    C1 += (size_t)b * CIN * NTOK;
    C2 += (size_t)b * CIN * NTOK;

    float acc1[2][4][4], acc2[2][4][4];
#pragma unroll
    for (int mi = 0; mi < 2; mi++)
#pragma unroll
        for (int ni = 0; ni < 4; ni++)
#pragma unroll
            for (int q = 0; q < 4; q++) { acc1[mi][ni][q] = 0.f; acc2[mi][ni][q] = 0.f; }

    const int NK = NTOK >> 5;

    {
#pragma unroll
        for (int v = 0; v < 2; v++) {
            int t = tid + v * 256, r = t >> 3, cf = (t & 7) << 2;
            cp16(sbase + (uint32_t)(r * 36 + cf) * 4, A + (size_t)r * NTOK + cf);
        }
#pragma unroll
        for (int v = 0; v < 4; v++) {
            int t = tid + v * 256, r = t >> 3, cf = (t & 7) << 2;
            cp16(sbase + (uint32_t)(ASZ + r * 36 + cf) * 4, B1 + (size_t)r * NTOK + cf);
            cp16(sbase + (uint32_t)(ASZ + BSZ + r * 36 + cf) * 4, B2 + (size_t)r * NTOK + cf);
        }
        cp_commit();
    }

    for (int i = 0; i < NK; i++) {
        if (i + 1 < NK) {
            const int st = (i + 1) & 1;
            const int k0 = (i + 1) << 5;
#pragma unroll
            for (int v = 0; v < 2; v++) {
                int t = tid + v * 256, r = t >> 3, cf = (t & 7) << 2;
                cp16(sbase + (uint32_t)(st * STG + r * 36 + cf) * 4,
                     A + (size_t)r * NTOK + k0 + cf);
            }
#pragma unroll
            for (int v = 0; v < 4; v++) {
                int t = tid + v * 256, r = t >> 3, cf = (t & 7) << 2;
                cp16(sbase + (uint32_t)(st * STG + ASZ + r * 36 + cf) * 4,
                     B1 + (size_t)r * NTOK + k0 + cf);
                cp16(sbase + (uint32_t)(st * STG + ASZ + BSZ + r * 36 + cf) * 4,
                     B2 + (size_t)r * NTOK + k0 + cf);
            }
            cp_commit();
            cp_wait<1>();
        } else {
            cp_wait<0>();
        }
        __syncthreads();

        const float* As  = sm + (i & 1) * STG;
        const float* Bs1 = As + ASZ;
        const float* Bs2 = Bs1 + BSZ;
        const int r = lane >> 2, c = lane & 3;

#pragma unroll
        for (int kk = 0; kk < 4; kk++) {
            const int k8 = kk * 8;
            uint32_t af[2][4], bf1[4][2], bf2[4][2];
#pragma unroll
            for (int mi = 0; mi < 2; mi++) {
                const int row = wM * 32 + mi * 16;
                af[mi][0] = __float_as_uint(As[(row + r) * 36 + k8 + c]);
                af[mi][1] = __float_as_uint(As[(row + 8 + r) * 36 + k8 + c]);
                af[mi][2] = __float_as_uint(As[(row + r) * 36 + k8 + c + 4]);
                af[mi][3] = __float_as_uint(As[(row + 8 + r) * 36 + k8 + c + 4]);
            }
#pragma unroll
            for (int ni = 0; ni < 4; ni++) {
                const int nr = wN * 32 + ni * 8 + r;
                bf1[ni][0] = __float_as_uint(Bs1[nr * 36 + k8 + c]);
                bf1[ni][1] = __float_as_uint(Bs1[nr * 36 + k8 + c + 4]);
                bf2[ni][0] = __float_as_uint(Bs2[nr * 36 + k8 + c]);
                bf2[ni][1] = __float_as_uint(Bs2[nr * 36 + k8 + c + 4]);
            }
#pragma unroll
            for (int mi = 0; mi < 2; mi++)
#pragma unroll
                for (int ni = 0; ni < 4; ni++) {
                    mma_tf32(acc1[mi][ni], af[mi], bf1[ni]);
                    mma_tf32(acc2[mi][ni], af[mi], bf2[ni]);
                }
        }
        __syncthreads();
    }

    const int r = lane >> 2, c = lane & 3;
#pragma unroll
    for (int mi = 0; mi < 2; mi++) {
        const int row0 = m0 + wM * 32 + mi * 16 + r;
#pragma unroll
        for (int ni = 0; ni < 4; ni++) {
            const int col = n0 + wN * 32 + ni * 8 + c * 2;
            C1[(size_t)col * NTOK + row0]           = acc1[mi][ni][0];
            C1[(size_t)(col + 1) * NTOK + row0]     = acc1[mi][ni][1];
            C1[(size_t)col * NTOK + row0 + 8]       = acc1[mi][ni][2];
            C1[(size_t)(col + 1) * NTOK + row0 + 8] = acc1[mi][ni][3];
            C2[(size_t)col * NTOK + row0]           = acc2[mi][ni][0];
            C2[(size_t)(col + 1) * NTOK + row0]     = acc2[mi][ni][1];
            C2[(size_t)col * NTOK + row0 + 8]       = acc2[mi][ni][2];
            C2[(size_t)(col + 1) * NTOK + row0 + 8] = acc2[mi][ni][3];
        }
    }
}

// ---------------------------------------------------------------------------
// Weight prep: round W to tf32, pad rows to DSTR with zeros; pad bias.
// ---------------------------------------------------------------------------
__global__ void prep_w_kernel(const float* __restrict__ W, const float* __restrict__ bias,
                              float* __restrict__ Wd, float* __restrict__ bd,
                              int rows, int cols, int dstRows)
{
    int i = blockIdx.x * 256 + threadIdx.x;
    int total = dstRows * cols;
    if (i < total) {
        int r = i / cols;
        Wd[i] = (r < rows) ? tf32r(W[i - (i / cols) * cols + (size_t)r * cols]) : 0.f;
    }
    if (bd && i < dstRows) bd[i] = (i < rows) ? bias[i] : 0.f;
}

// ---------------------------------------------------------------------------
// Transpose [C][N] -> [N][C] with tf32 rounding. Two tensors via z split.
// ---------------------------------------------------------------------------
template <int C>
__global__ __launch_bounds__(256) void transpose_in_kernel(
    const float* __restrict__ in0, float* __restrict__ out0,
    const float* __restrict__ in1, float* __restrict__ out1)
{
    __shared__ float t[32][33];
    const int z = blockIdx.z;
    const int b = z & (NB - 1);
    const float* in = (z < NB) ? in0 : in1;
    float* out = (z < NB) ? out0 : out1;
    in  += (size_t)b * C * NTOK;
    out += (size_t)b * NTOK * C;

    const int x0 = blockIdx.x * 32;   // token
    const int y0 = blockIdx.y * 32;   // channel
    const int tx = threadIdx.x & 31, ty = threadIdx.x >> 5;

#pragma unroll
    for (int i = 0; i < 4; i++)
        t[ty + i * 8][tx] = in[(size_t)(y0 + ty + i * 8) * NTOK + x0 + tx];
    __syncthreads();
#pragma unroll
    for (int i = 0; i < 4; i++)
        out[(size_t)(x0 + ty + i * 8) * C + y0 + tx] = tf32r(t[tx][ty + i * 8]);
}

// ---------------------------------------------------------------------------
// Reductions / softmax / stats / combine
// ---------------------------------------------------------------------------
__device__ __forceinline__ float warpMax(float v) {
#pragma unroll
    for (int o = 16; o; o >>= 1) v = fmaxf(v, __shfl_xor_sync(0xffffffffu, v, o));
    return v;
}
__device__ __forceinline__ float warpSum(float v) {
#pragma unroll
    for (int o = 16; o; o >>= 1) v += __shfl_xor_sync(0xffffffffu, v, o);
    return v;
}

__global__ __launch_bounds__(256) void softmax_mask_kernel(
    float* __restrict__ S,
    const int* __restrict__ cmask,
    const int* __restrict__ smask)
{
    const int n = blockIdx.x, b = blockIdx.y;
    float* row = S + ((size_t)b * NTOK + n) * NTOK;
    const int* sm = smask + (size_t)b * NTOK;
    const bool cmn = (cmask[(size_t)b * NTOK + n] != 0);
    const int tid = threadIdx.x;
    __shared__ float red[8];

    float v[16];
    float mx = -INFINITY;
#pragma unroll
    for (int i = 0; i < 16; i++) {
        int m = tid + i * 256;
        float s = row[m];
        if (cmn && sm[m] == 0) s = NEGV;
        v[i] = s;
        mx = fmaxf(mx, s);
    }
    mx = warpMax(mx);
    if ((tid & 31) == 0) red[tid >> 5] = mx;
    __syncthreads();
    if (tid < 32) {
        float x = (tid < 8) ? red[tid] : -INFINITY;
        x = warpMax(x);
        if (tid == 0) red[0] = x;
    }
    __syncthreads();
    mx = red[0];
    __syncthreads();

    float sum = 0.f;
#pragma unroll
    for (int i = 0; i < 16; i++) { v[i] = __expf(v[i] - mx); sum += v[i]; }
    sum = warpSum(sum);
    if ((tid & 31) == 0) red[tid >> 5] = sum;
    __syncthreads();
    if (tid < 32) {
        float x = (tid < 8) ? red[tid] : 0.f;
        x = warpSum(x);
        if (tid == 0) red[0] = x;
    }
    __syncthreads();
    const float inv = 1.f / red[0];
#pragma unroll
    for (int i = 0; i < 16; i++)
        row[tid + i * 256] = tf32r(v[i] * inv);
}

__global__ __launch_bounds__(256) void mvn_stats_kernel(
    const float* __restrict__ content,
    float* __restrict__ cmean, float* __restrict__ crstd)
{
    const int c = blockIdx.x, b = blockIdx.y;
    const float* p = content + ((size_t)b * CIN + c) * NTOK;
    const int tid = threadIdx.x;
    float s = 0.f, ss = 0.f;
#pragma unroll
    for (int i = 0; i < 16; i++) {
        float x = p[tid + i * 256];
        s += x; ss += x * x;
    }
    __shared__ float shs[8], shss[8];
    s = warpSum(s); ss = warpSum(ss);
    if ((tid & 31) == 0) { shs[tid >> 5] = s; shss[tid >> 5] = ss; }
    __syncthreads();
    if (tid == 0) {
        float S = 0.f, SS = 0.f;
#pragma unroll
        for (int i = 0; i < 8; i++) { S += shs[i]; SS += shss[i]; }
        float mean = S / (float)NTOK;
        float var = (SS - S * S / (float)NTOK) / (float)(NTOK - 1);
        cmean[b * CIN + c] = mean;
        crstd[b * CIN + c] = rsqrtf(var + EPSV);
    }
}

__global__ __launch_bounds__(256) void combine_kernel(
    const float4* __restrict__ content,
    const float4* __restrict__ meanT,
    const float4* __restrict__ m2T,
    const float* __restrict__ cmean,
    const float* __restrict__ crstd,
    float4* __restrict__ out)
{
    const int gid = blockIdx.x * 256 + threadIdx.x;
    const int bc = gid >> 10;
    const float mu = cmean[bc];
    const float rs = crstd[bc];
    float4 mn = meanT[gid];
    float4 m2 = m2T[gid];
    float4 ct = content[gid];
    float4 o;
    o.x = sqrtf(fmaxf(m2.x - mn.x * mn.x, 0.f)) * ((ct.x - mu) * rs) + mn.x;
    o.y = sqrtf(fmaxf(m2.y - mn.y * mn.y, 0.f)) * ((ct.y - mu) * rs) + mn.y;
    o.z = sqrtf(fmaxf(m2.z - mn.z * mn.z, 0.f)) * ((ct.z - mu) * rs) + mn.z;
    o.w = sqrtf(fmaxf(m2.w - mn.w * mn.w, 0.f)) * ((ct.w - mu) * rs) + mn.w;
    out[gid] = o;
}

// ---------------------------------------------------------------------------
// Launch
// ---------------------------------------------------------------------------
extern "C" void kernel_launch(void* const* d_in, const int* in_sizes, int n_in,
                              void* d_out, int out_size)
{
    const float* content = (const float*)d_in[0];
    const float* style   = (const float*)d_in[1];
    const float* ckey    = (const float*)d_in[2];
    const float* skey    = (const float*)d_in[3];
    const int*   cmask   = (const int*)  d_in[4];
    const int*   smask   = (const int*)  d_in[5];
    const float* Wf = (const float*)d_in[6];
    const float* bf = (const float*)d_in[7];
    const float* Wg = (const float*)d_in[8];
    const float* bg = (const float*)d_in[9];
    const float* Wh = (const float*)d_in[10];
    const float* bh = (const float*)d_in[11];
    float* out = (float*)d_out;

    float *pckT, *pskT, *pstT, *pFqN, *pGN, *pHv, *pHv2, *pS, *pMean, *pM2;
    float *pWf, *pWg, *pWh, *pbf, *pbg, *pCm, *pCr;
    cudaGetSymbolAddress((void**)&pckT, g_ckT);
    cudaGetSymbolAddress((void**)&pskT, g_skT);
    cudaGetSymbolAddress((void**)&pstT, g_stT);
    cudaGetSymbolAddress((void**)&pFqN, g_FqN);
    cudaGetSymbolAddress((void**)&pGN,  g_GN);
    cudaGetSymbolAddress((void**)&pHv,  g_HvT);
    cudaGetSymbolAddress((void**)&pHv2, g_Hv2T);
    cudaGetSymbolAddress((void**)&pS,   g_S);
    cudaGetSymbolAddress((void**)&pMean, g_meanT);
    cudaGetSymbolAddress((void**)&pM2,  g_m2T);
    cudaGetSymbolAddress((void**)&pWf,  g_Wf);
    cudaGetSymbolAddress((void**)&pWg,  g_Wg);
    cudaGetSymbolAddress((void**)&pWh,  g_Wh);
    cudaGetSymbolAddress((void**)&pbf,  g_bf);
    cudaGetSymbolAddress((void**)&pbg,  g_bg);
    cudaGetSymbolAddress((void**)&pCm,  g_cmean);
    cudaGetSymbolAddress((void**)&pCr,  g_crstd);

    constexpr int SMEM_STD = (128 * 36 + 128 * 36) * 4 * 2;  // 73728

    static bool attr_done = false;
    if (!attr_done) {
        cudaFuncSetAttribute(mma_gemmX<128, 128, 4, 0, false, false>,
                             cudaFuncAttributeMaxDynamicSharedMemorySize, SMEM_STD);
        cudaFuncSetAttribute(mma_gemmX<128, 128, 4, 2, true, false>,
                             cudaFuncAttributeMaxDynamicSharedMemorySize, SMEM_STD);
        cudaFuncSetAttribute(mma_gemmX<128, 128, 4, 1, true, true>,
                             cudaFuncAttributeMaxDynamicSharedMemorySize, SMEM_STD);
        cudaFuncSetAttribute(mma_gemm_dual,
                             cudaFuncAttributeMaxDynamicSharedMemorySize, DUAL_SMEM);
        attr_done = true;
    }

    const dim3 blk(256);

    // --- weight prep: rounded (+padded) weights & biases ---
    prep_w_kernel<<<(CKP * CKEY + 255) / 256, blk>>>(Wf, bf, pWf, pbf, CKEY, CKEY, CKP);
    prep_w_kernel<<<(CKP * CKEY + 255) / 256, blk>>>(Wg, bg, pWg, pbg, CKEY, CKEY, CKP);
    prep_w_kernel<<<(CIN * CIN + 255) / 256, blk>>>(Wh, nullptr, pWh, nullptr, CIN, CIN, CIN);

    // --- transpose inputs to token-major (tf32-rounded) ---
    transpose_in_kernel<CKEY><<<dim3(NTOK / 32, CKEY / 32, 2 * NB), blk>>>(
        ckey, pckT, skey, pskT);
    transpose_in_kernel<CIN><<<dim3(NTOK / 32, CIN / 32, NB), blk>>>(
        style, pstT, style, pstT);

    // --- projections (tf32 mma) ---
    // FqN[n][ck] = ckT[n][:].Wf[ck][:] + bf    (M=NTOK, N=CKP pad, guard 448)
    mma_gemmX<128, 128, 4, 2, true, false><<<dim3(CKP / 128, NTOK / 128, NB), blk, SMEM_STD>>>(
        pckT, pWf, pbf, pFqN, nullptr, CKEY, CKEY, CKEY, CKEY, CKEY,
        (size_t)NTOK * CKEY, 0, (size_t)NTOK * CKEY);
    mma_gemmX<128, 128, 4, 2, true, false><<<dim3(CKP / 128, NTOK / 128, NB), blk, SMEM_STD>>>(
        pskT, pWg, pbg, pGN, nullptr, CKEY, CKEY, CKEY, CKEY, CKEY,
        (size_t)NTOK * CKEY, 0, (size_t)NTOK * CKEY);
    // Hv[c][n] = Wh[c][:].styleT[n][:] + bh   (M=CIN, N=NTOK) + Hv2
    mma_gemmX<128, 128, 4, 1, true, true><<<dim3(NTOK / 128, CIN / 128, NB), blk, SMEM_STD>>>(
        pWh, pstT, bh, pHv, pHv2, NTOK, CIN, CIN, CIN, NTOK,
        0, (size_t)NTOK * CIN, (size_t)CIN * NTOK);

    // --- S = FqN @ GN^T ---
    mma_gemmX<128, 128, 4, 0, false, false><<<dim3(32, 32, NB), blk, SMEM_STD>>>(
        pFqN, pGN, nullptr, pS, nullptr, NTOK, CKEY, CKEY, CKEY, NTOK,
        (size_t)NTOK * CKEY, (size_t)NTOK * CKEY, (size_t)NTOK * NTOK);

    // --- masked softmax (in place) ---
    softmax_mask_kernel<<<dim3(NTOK, NB), blk>>>(pS, cmask, smask);

    // --- fused mean/m2: shares attn tiles ---
    mma_gemm_dual<<<dim3(CIN / 128, NTOK / 64, NB), blk, DUAL_SMEM>>>(
        pS, pHv, pHv2, pMean, pM2);

    // --- mvn stats + final combine ---
    mvn_stats_kernel<<<dim3(CIN, NB), blk>>>(content, pCm, pCr);
    combine_kernel<<<dim3((NB * CIN * NTOK / 4) / 256), blk>>>(
        (const float4*)content, (const float4*)pMean, (const float4*)pM2,
        pCm, pCr, (float4*)out);
}

// round 5
// speedup vs baseline: 3.1563x; 1.0161x over previous
#include <cuda_runtime.h>
#include <cstdint>

// ---------------------------------------------------------------------------
// Problem constants
// ---------------------------------------------------------------------------
#define NB   4
#define CIN  256
#define CKEY 448
#define NTOK 4096
#define NEGV (-1e15f)
#define EPSV 1e-5f
#define CKP  512   // padded CKEY for projection N-dim

// ---------------------------------------------------------------------------
// Scratch (static device globals; no runtime allocation)
// ---------------------------------------------------------------------------
__device__ float g_ckT [(size_t)NB * NTOK * CKEY];   // [b][N][Ck] ckey^T (tf32)
__device__ float g_skT [(size_t)NB * NTOK * CKEY];   // [b][N][Ck] skey^T (tf32)
__device__ float g_stT [(size_t)NB * NTOK * CIN];    // [b][N][C]  style^T (tf32)
__device__ float g_FqN [(size_t)NB * NTOK * CKEY];   // [b][N][Ck] f(ckey) token-major
__device__ float g_GN  [(size_t)NB * NTOK * CKEY];   // [b][N][Ck] g(skey) token-major
__device__ float g_HvT [(size_t)NB * CIN  * NTOK];   // [b][C][N]  h(style)   (tf32)
__device__ float g_Hv2T[(size_t)NB * CIN  * NTOK];   // [b][C][N]  h(style)^2 (tf32)
__device__ float g_S   [(size_t)NB * NTOK * NTOK];   // [b][N][N]  scores -> attn
__device__ float g_meanT[(size_t)NB * CIN * NTOK];   // [b][C][N]
__device__ float g_m2T [(size_t)NB * CIN  * NTOK];   // [b][C][N]
__device__ float g_Wf  [CKP * CKEY];                 // rounded, zero-padded rows
__device__ float g_Wg  [CKP * CKEY];
__device__ float g_Wh  [CIN * CIN];
__device__ float g_bf  [CKP];
__device__ float g_bg  [CKP];
__device__ float g_cmean[NB * CIN];
__device__ float g_crstd[NB * CIN];

// ---------------------------------------------------------------------------
// Helpers (sm_103 baseline features only)
// ---------------------------------------------------------------------------
__device__ __forceinline__ uint32_t smem_u32(const void* p) {
    uint32_t a;
    asm("{ .reg .u64 t; cvta.to.shared.u64 t, %1; cvt.u32.u64 %0, t; }"
        : "=r"(a) : "l"(p));
    return a;
}
__device__ __forceinline__ float tf32r(float x) {
    float y;
    asm("cvt.rna.tf32.f32 %0, %1;" : "=f"(y) : "f"(x));
    return y;
}
__device__ __forceinline__ void cp16(uint32_t s, const void* g) {
    asm volatile("cp.async.cg.shared.global [%0], [%1], 16;" :: "r"(s), "l"(g));
}
__device__ __forceinline__ void cp_commit() {
    asm volatile("cp.async.commit_group;" ::: "memory");
}
template <int N> __device__ __forceinline__ void cp_wait() {
    asm volatile("cp.async.wait_group %0;" :: "n"(N) : "memory");
}
__device__ __forceinline__ void mma_tf32(float* d, const uint32_t* a, const uint32_t* b) {
    asm volatile(
        "mma.sync.aligned.m16n8k8.row.col.f32.tf32.tf32.f32 "
        "{%0,%1,%2,%3}, {%4,%5,%6,%7}, {%8,%9}, {%0,%1,%2,%3};"
        : "+f"(d[0]), "+f"(d[1]), "+f"(d[2]), "+f"(d[3])
        : "r"(a[0]), "r"(a[1]), "r"(a[2]), "r"(a[3]), "r"(b[0]), "r"(b[1]));
}

// ---------------------------------------------------------------------------
// Generic TF32 mma.sync GEMM:  C[M][N] = A[M][K] * B[N][K]^T
//   256 threads, WMW x (8/WMW) warps, warp tile (BM/WMW) x (BN*WMW/8)
//   BK=32, cp.async double buffer, smem row stride 36 (conflict-free)
//   BIAS_MODE: 0 none, 1 along M, 2 along N
//   TF32R: round outputs to tf32 (rna)     SQ: also write C2 = round(C*C)
//   Store guard: column < Nrt.
// ---------------------------------------------------------------------------
template <int BM, int BN, int WMW, int BIAS_MODE, bool TF32R, bool SQ>
__global__ __launch_bounds__(256) void mma_gemmX(
    const float* __restrict__ A, const float* __restrict__ B,
    const float* __restrict__ bias,
    float* __restrict__ C, float* __restrict__ C2,
    int Nrt, int K, int lda, int ldb, int ldc,
    size_t sA, size_t sB, size_t sC)
{
    constexpr int WNW = 8 / WMW;
    constexpr int WTM = BM / WMW;          // warp tile M
    constexpr int WTN = BN / WNW;          // warp tile N
    constexpr int MI  = WTM / 16;
    constexpr int NI  = WTN / 8;
    constexpr int ASZ = BM * 36;
    constexpr int BSZ = BN * 36;
    constexpr int STG = ASZ + BSZ;
    constexpr int AV4 = BM * 8 / 256;
    constexpr int BV4 = BN * 8 / 256;

    extern __shared__ float sm[];
    const uint32_t sbase = smem_u32(sm);

    const int tid = threadIdx.x, lane = tid & 31, wid = tid >> 5;
    const int wM = wid % WMW, wN = wid / WMW;
    const int m0 = blockIdx.y * BM, n0 = blockIdx.x * BN, b = blockIdx.z;

    A += (size_t)b * sA + (size_t)m0 * lda;
    B += (size_t)b * sB + (size_t)n0 * ldb;
    C += (size_t)b * sC;
    if (SQ) C2 += (size_t)b * sC;

    float acc[MI][NI][4];
#pragma unroll
    for (int mi = 0; mi < MI; mi++)
#pragma unroll
        for (int ni = 0; ni < NI; ni++)
#pragma unroll
            for (int q = 0; q < 4; q++) acc[mi][ni][q] = 0.f;

    const int NK = K >> 5;

    {
#pragma unroll
        for (int v = 0; v < AV4; v++) {
            int t = tid + v * 256, r = t >> 3, cf = (t & 7) << 2;
            cp16(sbase + (uint32_t)(r * 36 + cf) * 4, A + (size_t)r * lda + cf);
        }
#pragma unroll
        for (int v = 0; v < BV4; v++) {
            int t = tid + v * 256, r = t >> 3, cf = (t & 7) << 2;
            cp16(sbase + (uint32_t)(ASZ + r * 36 + cf) * 4, B + (size_t)r * ldb + cf);
        }
        cp_commit();
    }

    for (int i = 0; i < NK; i++) {
        if (i + 1 < NK) {
            const int st = (i + 1) & 1;
            const int k0 = (i + 1) << 5;
#pragma unroll
            for (int v = 0; v < AV4; v++) {
                int t = tid + v * 256, r = t >> 3, cf = (t & 7) << 2;
                cp16(sbase + (uint32_t)(st * STG + r * 36 + cf) * 4,
                     A + (size_t)r * lda + k0 + cf);
            }
#pragma unroll
            for (int v = 0; v < BV4; v++) {
                int t = tid + v * 256, r = t >> 3, cf = (t & 7) << 2;
                cp16(sbase + (uint32_t)(st * STG + ASZ + r * 36 + cf) * 4,
                     B + (size_t)r * ldb + k0 + cf);
            }
            cp_commit();
            cp_wait<1>();
        } else {
            cp_wait<0>();
        }
        __syncthreads();

        const float* As = sm + (i & 1) * STG;
        const float* Bs = As + ASZ;
        const int r = lane >> 2, c = lane & 3;

#pragma unroll
        for (int kk = 0; kk < 4; kk++) {
            const int k8 = kk * 8;
            uint32_t af[MI][4], bf[NI][2];
#pragma unroll
            for (int mi = 0; mi < MI; mi++) {
                const int row = wM * WTM + mi * 16;
                af[mi][0] = __float_as_uint(As[(row + r) * 36 + k8 + c]);
                af[mi][1] = __float_as_uint(As[(row + 8 + r) * 36 + k8 + c]);
                af[mi][2] = __float_as_uint(As[(row + r) * 36 + k8 + c + 4]);
                af[mi][3] = __float_as_uint(As[(row + 8 + r) * 36 + k8 + c + 4]);
            }
#pragma unroll
            for (int ni = 0; ni < NI; ni++) {
                const int nr = wN * WTN + ni * 8 + r;
                bf[ni][0] = __float_as_uint(Bs[nr * 36 + k8 + c]);
                bf[ni][1] = __float_as_uint(Bs[nr * 36 + k8 + c + 4]);
            }
#pragma unroll
            for (int mi = 0; mi < MI; mi++)
#pragma unroll
                for (int ni = 0; ni < NI; ni++)
                    mma_tf32(acc[mi][ni], af[mi], bf[ni]);
        }
        __syncthreads();
    }

    // ---- epilogue ----
    const int r = lane >> 2, c = lane & 3;
#pragma unroll
    for (int mi = 0; mi < MI; mi++) {
        const int row0 = m0 + wM * WTM + mi * 16 + r;
        float bm0 = 0.f, bm1 = 0.f;
        if (BIAS_MODE == 1) { bm0 = bias[row0]; bm1 = bias[row0 + 8]; }
#pragma unroll
        for (int ni = 0; ni < NI; ni++) {
            const int col = n0 + wN * WTN + ni * 8 + c * 2;
            if (col >= Nrt) continue;
            float o0 = acc[mi][ni][0], o1 = acc[mi][ni][1];
            float o2 = acc[mi][ni][2], o3 = acc[mi][ni][3];
            if (BIAS_MODE == 1) { o0 += bm0; o1 += bm0; o2 += bm1; o3 += bm1; }
            if (BIAS_MODE == 2) {
                float bn0 = bias[col], bn1 = bias[col + 1];
                o0 += bn0; o1 += bn1; o2 += bn0; o3 += bn1;
            }
            if (TF32R) { o0 = tf32r(o0); o1 = tf32r(o1); o2 = tf32r(o2); o3 = tf32r(o3); }
            *reinterpret_cast<float2*>(&C[(size_t)row0 * ldc + col])       = make_float2(o0, o1);
            *reinterpret_cast<float2*>(&C[(size_t)(row0 + 8) * ldc + col]) = make_float2(o2, o3);
            if (SQ) {
                float q0 = tf32r(o0 * o0), q1 = tf32r(o1 * o1);
                float q2 = tf32r(o2 * o2), q3 = tf32r(o3 * o3);
                *reinterpret_cast<float2*>(&C2[(size_t)row0 * ldc + col])       = make_float2(q0, q1);
                *reinterpret_cast<float2*>(&C2[(size_t)(row0 + 8) * ldc + col]) = make_float2(q2, q3);
            }
        }
    }
}

// ---------------------------------------------------------------------------
// Dual-B fused GEMM for mean & m2: shares attn A tiles.
//   C1[n][c] = A[n][:] . B1[c][:],  C2[n][c] = A[n][:] . B2[c][:]
//   BM=128, BN=128, warps 2x4 (warp tile 64x32, MI=4, NI=4).
//   Transposed store: out[c][n].
// ---------------------------------------------------------------------------
#define DUAL_SMEM ((128 * 36 + 2 * 128 * 36) * 4 * 2)
__global__ __launch_bounds__(256) void mma_gemm_dual(
    const float* __restrict__ A, const float* __restrict__ B1,
    const float* __restrict__ B2,
    float* __restrict__ C1, float* __restrict__ C2)
{
    constexpr int BM = 128, BN = 128;
    constexpr int ASZ = BM * 36, BSZ = BN * 36;
    constexpr int STG = ASZ + 2 * BSZ;

    extern __shared__ float sm[];
    const uint32_t sbase = smem_u32(sm);

    const int tid = threadIdx.x, lane = tid & 31, wid = tid >> 5;
    const int wM = wid & 1, wN = wid >> 1;
    const int m0 = blockIdx.y * BM, n0 = blockIdx.x * BN, b = blockIdx.z;

    A  += (size_t)b * NTOK * NTOK + (size_t)m0 * NTOK;
    B1 += (size_t)b * CIN * NTOK + (size_t)n0 * NTOK;
    B2 += (size_t)b * CIN * NTOK + (size_t)n0 * NTOK;
    C1 += (size_t)b * CIN * NTOK;
    C2 += (size_t)b * CIN * NTOK;

    float acc1[4][4][4], acc2[4][4][4];
#pragma unroll
    for (int mi = 0; mi < 4; mi++)
#pragma unroll
        for (int ni = 0; ni < 4; ni++)
#pragma unroll
            for (int q = 0; q < 4; q++) { acc1[mi][ni][q] = 0.f; acc2[mi][ni][q] = 0.f; }

    const int NK = NTOK >> 5;

    {
#pragma unroll
        for (int v = 0; v < 4; v++) {
            int t = tid + v * 256, r = t >> 3, cf = (t & 7) << 2;
            cp16(sbase + (uint32_t)(r * 36 + cf) * 4, A + (size_t)r * NTOK + cf);
            cp16(sbase + (uint32_t)(ASZ + r * 36 + cf) * 4, B1 + (size_t)r * NTOK + cf);
            cp16(sbase + (uint32_t)(ASZ + BSZ + r * 36 + cf) * 4, B2 + (size_t)r * NTOK + cf);
        }
        cp_commit();
    }

    for (int i = 0; i < NK; i++) {
        if (i + 1 < NK) {
            const int st = (i + 1) & 1;
            const int k0 = (i + 1) << 5;
#pragma unroll
            for (int v = 0; v < 4; v++) {
                int t = tid + v * 256, r = t >> 3, cf = (t & 7) << 2;
                cp16(sbase + (uint32_t)(st * STG + r * 36 + cf) * 4,
                     A + (size_t)r * NTOK + k0 + cf);
                cp16(sbase + (uint32_t)(st * STG + ASZ + r * 36 + cf) * 4,
                     B1 + (size_t)r * NTOK + k0 + cf);
                cp16(sbase + (uint32_t)(st * STG + ASZ + BSZ + r * 36 + cf) * 4,
                     B2 + (size_t)r * NTOK + k0 + cf);
            }
            cp_commit();
            cp_wait<1>();
        } else {
            cp_wait<0>();
        }
        __syncthreads();

        const float* As  = sm + (i & 1) * STG;
        const float* Bs1 = As + ASZ;
        const float* Bs2 = Bs1 + BSZ;
        const int r = lane >> 2, c = lane & 3;

#pragma unroll
        for (int kk = 0; kk < 4; kk++) {
            const int k8 = kk * 8;
            uint32_t af[4][4], bf1[4][2], bf2[4][2];
#pragma unroll
            for (int mi = 0; mi < 4; mi++) {
                const int row = wM * 64 + mi * 16;
                af[mi][0] = __float_as_uint(As[(row + r) * 36 + k8 + c]);
                af[mi][1] = __float_as_uint(As[(row + 8 + r) * 36 + k8 + c]);
                af[mi][2] = __float_as_uint(As[(row + r) * 36 + k8 + c + 4]);
                af[mi][3] = __float_as_uint(As[(row + 8 + r) * 36 + k8 + c + 4]);
            }
#pragma unroll
            for (int ni = 0; ni < 4; ni++) {
                const int nr = wN * 32 + ni * 8 + r;
                bf1[ni][0] = __float_as_uint(Bs1[nr * 36 + k8 + c]);
                bf1[ni][1] = __float_as_uint(Bs1[nr * 36 + k8 + c + 4]);
                bf2[ni][0] = __float_as_uint(Bs2[nr * 36 + k8 + c]);
                bf2[ni][1] = __float_as_uint(Bs2[nr * 36 + k8 + c + 4]);
            }
#pragma unroll
            for (int mi = 0; mi < 4; mi++)
#pragma unroll
                for (int ni = 0; ni < 4; ni++) {
                    mma_tf32(acc1[mi][ni], af[mi], bf1[ni]);
                    mma_tf32(acc2[mi][ni], af[mi], bf2[ni]);
                }
        }
        __syncthreads();
    }

    const int r = lane >> 2, c = lane & 3;
#pragma unroll
    for (int mi = 0; mi < 4; mi++) {
        const int row0 = m0 + wM * 64 + mi * 16 + r;
#pragma unroll
        for (int ni = 0; ni < 4; ni++) {
            const int col = n0 + wN * 32 + ni * 8 + c * 2;
            C1[(size_t)col * NTOK + row0]           = acc1[mi][ni][0];
            C1[(size_t)(col + 1) * NTOK + row0]     = acc1[mi][ni][1];
            C1[(size_t)col * NTOK + row0 + 8]       = acc1[mi][ni][2];
            C1[(size_t)(col + 1) * NTOK + row0 + 8] = acc1[mi][ni][3];
            C2[(size_t)col * NTOK + row0]           = acc2[mi][ni][0];
            C2[(size_t)(col + 1) * NTOK + row0]     = acc2[mi][ni][1];
            C2[(size_t)col * NTOK + row0 + 8]       = acc2[mi][ni][2];
            C2[(size_t)(col + 1) * NTOK + row0 + 8] = acc2[mi][ni][3];
        }
    }
}

// ---------------------------------------------------------------------------
// Weight prep: round W to tf32, pad rows to dstRows with zeros; pad bias.
// ---------------------------------------------------------------------------
__global__ void prep_w_kernel(const float* __restrict__ W, const float* __restrict__ bias,
                              float* __restrict__ Wd, float* __restrict__ bd,
                              int rows, int cols, int dstRows)
{
    int i = blockIdx.x * 256 + threadIdx.x;
    int total = dstRows * cols;
    if (i < total) {
        int r = i / cols;
        Wd[i] = (r < rows) ? tf32r(W[i - (i / cols) * cols + (size_t)r * cols]) : 0.f;
    }
    if (bd && i < dstRows) bd[i] = (i < rows) ? bias[i] : 0.f;
}

// ---------------------------------------------------------------------------
// Transpose [C][N] -> [N][C] with tf32 rounding. Two tensors via z split.
// ---------------------------------------------------------------------------
template <int C>
__global__ __launch_bounds__(256) void transpose_in_kernel(
    const float* __restrict__ in0, float* __restrict__ out0,
    const float* __restrict__ in1, float* __restrict__ out1)
{
    __shared__ float t[32][33];
    const int z = blockIdx.z;
    const int b = z & (NB - 1);
    const float* in = (z < NB) ? in0 : in1;
    float* out = (z < NB) ? out0 : out1;
    in  += (size_t)b * C * NTOK;
    out += (size_t)b * NTOK * C;

    const int x0 = blockIdx.x * 32;   // token
    const int y0 = blockIdx.y * 32;   // channel
    const int tx = threadIdx.x & 31, ty = threadIdx.x >> 5;

#pragma unroll
    for (int i = 0; i < 4; i++)
        t[ty + i * 8][tx] = in[(size_t)(y0 + ty + i * 8) * NTOK + x0 + tx];
    __syncthreads();
#pragma unroll
    for (int i = 0; i < 4; i++)
        out[(size_t)(x0 + ty + i * 8) * C + y0 + tx] = tf32r(t[tx][ty + i * 8]);
}

// ---------------------------------------------------------------------------
// Reductions / softmax / stats / combine
// ---------------------------------------------------------------------------
__device__ __forceinline__ float warpMax(float v) {
#pragma unroll
    for (int o = 16; o; o >>= 1) v = fmaxf(v, __shfl_xor_sync(0xffffffffu, v, o));
    return v;
}
__device__ __forceinline__ float warpSum(float v) {
#pragma unroll
    for (int o = 16; o; o >>= 1) v += __shfl_xor_sync(0xffffffffu, v, o);
    return v;
}

__global__ __launch_bounds__(256) void softmax_mask_kernel(
    float* __restrict__ S,
    const int* __restrict__ cmask,
    const int* __restrict__ smask)
{
    const int n = blockIdx.x, b = blockIdx.y;
    float* row = S + ((size_t)b * NTOK + n) * NTOK;
    const int* sm = smask + (size_t)b * NTOK;
    const bool cmn = (cmask[(size_t)b * NTOK + n] != 0);
    const int tid = threadIdx.x;
    __shared__ float red[8];

    float v[16];
    float mx = -INFINITY;
#pragma unroll
    for (int i = 0; i < 16; i++) {
        int m = tid + i * 256;
        float s = row[m];
        if (cmn && sm[m] == 0) s = NEGV;
        v[i] = s;
        mx = fmaxf(mx, s);
    }
    mx = warpMax(mx);
    if ((tid & 31) == 0) red[tid >> 5] = mx;
    __syncthreads();
    if (tid < 32) {
        float x = (tid < 8) ? red[tid] : -INFINITY;
        x = warpMax(x);
        if (tid == 0) red[0] = x;
    }
    __syncthreads();
    mx = red[0];
    __syncthreads();

    float sum = 0.f;
#pragma unroll
    for (int i = 0; i < 16; i++) { v[i] = __expf(v[i] - mx); sum += v[i]; }
    sum = warpSum(sum);
    if ((tid & 31) == 0) red[tid >> 5] = sum;
    __syncthreads();
    if (tid < 32) {
        float x = (tid < 8) ? red[tid] : 0.f;
        x = warpSum(x);
        if (tid == 0) red[0] = x;
    }
    __syncthreads();
    const float inv = 1.f / red[0];
#pragma unroll
    for (int i = 0; i < 16; i++)
        row[tid + i * 256] = tf32r(v[i] * inv);
}

__global__ __launch_bounds__(256) void mvn_stats_kernel(
    const float* __restrict__ content,
    float* __restrict__ cmean, float* __restrict__ crstd)
{
    const int c = blockIdx.x, b = blockIdx.y;
    const float* p = content + ((size_t)b * CIN + c) * NTOK;
    const int tid = threadIdx.x;
    float s = 0.f, ss = 0.f;
#pragma unroll
    for (int i = 0; i < 16; i++) {
        float x = p[tid + i * 256];
        s += x; ss += x * x;
    }
    __shared__ float shs[8], shss[8];
    s = warpSum(s); ss = warpSum(ss);
    if ((tid & 31) == 0) { shs[tid >> 5] = s; shss[tid >> 5] = ss; }
    __syncthreads();
    if (tid == 0) {
        float S = 0.f, SS = 0.f;
#pragma unroll
        for (int i = 0; i < 8; i++) { S += shs[i]; SS += shss[i]; }
        float mean = S / (float)NTOK;
        float var = (SS - S * S / (float)NTOK) / (float)(NTOK - 1);
        cmean[b * CIN + c] = mean;
        crstd[b * CIN + c] = rsqrtf(var + EPSV);
    }
}

__global__ __launch_bounds__(256) void combine_kernel(
    const float4* __restrict__ content,
    const float4* __restrict__ meanT,
    const float4* __restrict__ m2T,
    const float* __restrict__ cmean,
    const float* __restrict__ crstd,
    float4* __restrict__ out)
{
    const int gid = blockIdx.x * 256 + threadIdx.x;
    const int bc = gid >> 10;
    const float mu = cmean[bc];
    const float rs = crstd[bc];
    float4 mn = meanT[gid];
    float4 m2 = m2T[gid];
    float4 ct = content[gid];
    float4 o;
    o.x = sqrtf(fmaxf(m2.x - mn.x * mn.x, 0.f)) * ((ct.x - mu) * rs) + mn.x;
    o.y = sqrtf(fmaxf(m2.y - mn.y * mn.y, 0.f)) * ((ct.y - mu) * rs) + mn.y;
    o.z = sqrtf(fmaxf(m2.z - mn.z * mn.z, 0.f)) * ((ct.z - mu) * rs) + mn.z;
    o.w = sqrtf(fmaxf(m2.w - mn.w * mn.w, 0.f)) * ((ct.w - mu) * rs) + mn.w;
    out[gid] = o;
}

// ---------------------------------------------------------------------------
// Launch
// ---------------------------------------------------------------------------
extern "C" void kernel_launch(void* const* d_in, const int* in_sizes, int n_in,
                              void* d_out, int out_size)
{
    const float* content = (const float*)d_in[0];
    const float* style   = (const float*)d_in[1];
    const float* ckey    = (const float*)d_in[2];
    const float* skey    = (const float*)d_in[3];
    const int*   cmask   = (const int*)  d_in[4];
    const int*   smask   = (const int*)  d_in[5];
    const float* Wf = (const float*)d_in[6];
    const float* bf = (const float*)d_in[7];
    const float* Wg = (const float*)d_in[8];
    const float* bg = (const float*)d_in[9];
    const float* Wh = (const float*)d_in[10];
    const float* bh = (const float*)d_in[11];
    float* out = (float*)d_out;

    float *pckT, *pskT, *pstT, *pFqN, *pGN, *pHv, *pHv2, *pS, *pMean, *pM2;
    float *pWf, *pWg, *pWh, *pbf, *pbg, *pCm, *pCr;
    cudaGetSymbolAddress((void**)&pckT, g_ckT);
    cudaGetSymbolAddress((void**)&pskT, g_skT);
    cudaGetSymbolAddress((void**)&pstT, g_stT);
    cudaGetSymbolAddress((void**)&pFqN, g_FqN);
    cudaGetSymbolAddress((void**)&pGN,  g_GN);
    cudaGetSymbolAddress((void**)&pHv,  g_HvT);
    cudaGetSymbolAddress((void**)&pHv2, g_Hv2T);
    cudaGetSymbolAddress((void**)&pS,   g_S);
    cudaGetSymbolAddress((void**)&pMean, g_meanT);
    cudaGetSymbolAddress((void**)&pM2,  g_m2T);
    cudaGetSymbolAddress((void**)&pWf,  g_Wf);
    cudaGetSymbolAddress((void**)&pWg,  g_Wg);
    cudaGetSymbolAddress((void**)&pWh,  g_Wh);
    cudaGetSymbolAddress((void**)&pbf,  g_bf);
    cudaGetSymbolAddress((void**)&pbg,  g_bg);
    cudaGetSymbolAddress((void**)&pCm,  g_cmean);
    cudaGetSymbolAddress((void**)&pCr,  g_crstd);

    constexpr int SMEM_PRJ = (128 * 36 + 128 * 36) * 4 * 2;  // 73728
    constexpr int SMEM_S   = (128 * 36 + 256 * 36) * 4 * 2;  // 110592

    static bool attr_done = false;
    if (!attr_done) {
        cudaFuncSetAttribute(mma_gemmX<128, 256, 2, 0, false, false>,
                             cudaFuncAttributeMaxDynamicSharedMemorySize, SMEM_S);
        cudaFuncSetAttribute(mma_gemmX<128, 128, 4, 2, true, false>,
                             cudaFuncAttributeMaxDynamicSharedMemorySize, SMEM_PRJ);
        cudaFuncSetAttribute(mma_gemmX<128, 128, 4, 1, true, true>,
                             cudaFuncAttributeMaxDynamicSharedMemorySize, SMEM_PRJ);
        cudaFuncSetAttribute(mma_gemm_dual,
                             cudaFuncAttributeMaxDynamicSharedMemorySize, DUAL_SMEM);
        attr_done = true;
    }

    const dim3 blk(256);

    // --- weight prep: rounded (+padded) weights & biases ---
    prep_w_kernel<<<(CKP * CKEY + 255) / 256, blk>>>(Wf, bf, pWf, pbf, CKEY, CKEY, CKP);
    prep_w_kernel<<<(CKP * CKEY + 255) / 256, blk>>>(Wg, bg, pWg, pbg, CKEY, CKEY, CKP);
    prep_w_kernel<<<(CIN * CIN + 255) / 256, blk>>>(Wh, nullptr, pWh, nullptr, CIN, CIN, CIN);

    // --- transpose inputs to token-major (tf32-rounded) ---
    transpose_in_kernel<CKEY><<<dim3(NTOK / 32, CKEY / 32, 2 * NB), blk>>>(
        ckey, pckT, skey, pskT);
    transpose_in_kernel<CIN><<<dim3(NTOK / 32, CIN / 32, NB), blk>>>(
        style, pstT, style, pstT);

    // --- projections (tf32 mma) ---
    mma_gemmX<128, 128, 4, 2, true, false><<<dim3(CKP / 128, NTOK / 128, NB), blk, SMEM_PRJ>>>(
        pckT, pWf, pbf, pFqN, nullptr, CKEY, CKEY, CKEY, CKEY, CKEY,
        (size_t)NTOK * CKEY, 0, (size_t)NTOK * CKEY);
    mma_gemmX<128, 128, 4, 2, true, false><<<dim3(CKP / 128, NTOK / 128, NB), blk, SMEM_PRJ>>>(
        pskT, pWg, pbg, pGN, nullptr, CKEY, CKEY, CKEY, CKEY, CKEY,
        (size_t)NTOK * CKEY, 0, (size_t)NTOK * CKEY);
    mma_gemmX<128, 128, 4, 1, true, true><<<dim3(NTOK / 128, CIN / 128, NB), blk, SMEM_PRJ>>>(
        pWh, pstT, bh, pHv, pHv2, NTOK, CIN, CIN, CIN, NTOK,
        0, (size_t)NTOK * CIN, (size_t)CIN * NTOK);

    // --- S = FqN @ GN^T  (block 128x256, warp 64x64) ---
    mma_gemmX<128, 256, 2, 0, false, false><<<dim3(NTOK / 256, NTOK / 128, NB), blk, SMEM_S>>>(
        pFqN, pGN, nullptr, pS, nullptr, NTOK, CKEY, CKEY, CKEY, NTOK,
        (size_t)NTOK * CKEY, (size_t)NTOK * CKEY, (size_t)NTOK * NTOK);

    // --- masked softmax (in place) ---
    softmax_mask_kernel<<<dim3(NTOK, NB), blk>>>(pS, cmask, smask);

    // --- fused mean/m2: shares attn tiles (block 128x128, warp 64x32) ---
    mma_gemm_dual<<<dim3(CIN / 128, NTOK / 128, NB), blk, DUAL_SMEM>>>(
        pS, pHv, pHv2, pMean, pM2);

    // --- mvn stats + final combine ---
    mvn_stats_kernel<<<dim3(CIN, NB), blk>>>(content, pCm, pCr);
    combine_kernel<<<dim3((NB * CIN * NTOK / 4) / 256), blk>>>(
        (const float4*)content, (const float4*)pMean, (const float4*)pM2,
        pCm, pCr, (float4*)out);
}

// round 6
// speedup vs baseline: 4.6437x; 1.4713x over previous
#include <cuda_runtime.h>
#include <cuda_fp16.h>
#include <cstdint>

// ---------------------------------------------------------------------------
// Problem constants
// ---------------------------------------------------------------------------
#define NB   4
#define CIN  256
#define CKEY 448
#define NTOK 4096
#define NEGV (-1e15f)
#define EPSV 1e-5f
#define CKP  512   // padded CKEY for projection N-dim

// ---------------------------------------------------------------------------
// Scratch (static device globals; no runtime allocation)
// ---------------------------------------------------------------------------
__device__ __half g_ckT [(size_t)NB * NTOK * CKEY];   // [b][N][Ck] ckey^T
__device__ __half g_skT [(size_t)NB * NTOK * CKEY];   // [b][N][Ck] skey^T
__device__ __half g_stT [(size_t)NB * NTOK * CIN];    // [b][N][C]  style^T
__device__ __half g_FqN [(size_t)NB * NTOK * CKEY];   // [b][N][Ck] f(ckey)
__device__ __half g_GN  [(size_t)NB * NTOK * CKEY];   // [b][N][Ck] g(skey)
__device__ __half g_HvT [(size_t)NB * CIN  * NTOK];   // [b][C][N]  h(style)
__device__ __half g_Hv2T[(size_t)NB * CIN  * NTOK];   // [b][C][N]  h(style)^2
__device__ float  g_S   [(size_t)NB * NTOK * NTOK];   // [b][N][N]  scores (fp32)
__device__ __half g_A   [(size_t)NB * NTOK * NTOK];   // [b][N][N]  attn (half)
__device__ float  g_meanT[(size_t)NB * CIN * NTOK];   // [b][C][N]
__device__ float  g_m2T [(size_t)NB * CIN  * NTOK];   // [b][C][N]
__device__ __half g_Wf  [CKP * CKEY];                 // rounded, zero-padded rows
__device__ __half g_Wg  [CKP * CKEY];
__device__ __half g_Wh  [CIN * CIN];
__device__ float  g_bf  [CKP];
__device__ float  g_bg  [CKP];
__device__ float  g_cmean[NB * CIN];
__device__ float  g_crstd[NB * CIN];

// ---------------------------------------------------------------------------
// Helpers
// ---------------------------------------------------------------------------
__device__ __forceinline__ uint32_t smem_u32(const void* p) {
    uint32_t a;
    asm("{ .reg .u64 t; cvta.to.shared.u64 t, %1; cvt.u32.u64 %0, t; }"
        : "=r"(a) : "l"(p));
    return a;
}
__device__ __forceinline__ void cp16(uint32_t s, const void* g) {
    asm volatile("cp.async.cg.shared.global [%0], [%1], 16;" :: "r"(s), "l"(g));
}
__device__ __forceinline__ void cp_commit() {
    asm volatile("cp.async.commit_group;" ::: "memory");
}
template <int N> __device__ __forceinline__ void cp_wait() {
    asm volatile("cp.async.wait_group %0;" :: "n"(N) : "memory");
}
__device__ __forceinline__ void mma_f16(float* d, const uint32_t* a, const uint32_t* b) {
    asm volatile(
        "mma.sync.aligned.m16n8k16.row.col.f32.f16.f16.f32 "
        "{%0,%1,%2,%3}, {%4,%5,%6,%7}, {%8,%9}, {%0,%1,%2,%3};"
        : "+f"(d[0]), "+f"(d[1]), "+f"(d[2]), "+f"(d[3])
        : "r"(a[0]), "r"(a[1]), "r"(a[2]), "r"(a[3]), "r"(b[0]), "r"(b[1]));
}

// smem row stride: 40 halves (80 B = 20 words) -> conflict-free fragment LDS
#define SRS 40
#define SRW 20

// ---------------------------------------------------------------------------
// Generic FP16 mma.sync GEMM:  C[M][N] = A[M][K] * B[N][K]^T   (fp32 accum)
//   256 threads, WMW x (8/WMW) warps, BK=32 halves, double-buffered cp.async.
//   BIAS_MODE: 0 none, 1 along M, 2 along N (bias fp32)
//   SQ: also write C2 = rn(h*h) where h = rn(C) (requires CT == __half)
//   CT: output type (float or __half). Store guard: col < Nrt.
// ---------------------------------------------------------------------------
template <int BM, int BN, int WMW, int BIAS_MODE, bool SQ, typename CT>
__global__ __launch_bounds__(256) void mma_gemmH(
    const __half* __restrict__ A, const __half* __restrict__ B,
    const float* __restrict__ bias,
    CT* __restrict__ C, CT* __restrict__ C2,
    int Nrt, int K, int lda, int ldb, int ldc,
    size_t sA, size_t sB, size_t sC)
{
    constexpr int WNW = 8 / WMW;
    constexpr int WTM = BM / WMW;
    constexpr int WTN = BN / WNW;
    constexpr int MI  = WTM / 16;
    constexpr int NI  = WTN / 8;
    constexpr int ASZ = BM * SRS;          // halves
    constexpr int BSZ = BN * SRS;
    constexpr int STG = ASZ + BSZ;
    constexpr int ACH = BM * 4 / 256;      // cp16 chunks per thread (A)
    constexpr int BCH = BN * 4 / 256;

    extern __shared__ __half smh[];
    const uint32_t sbase = smem_u32(smh);

    const int tid = threadIdx.x, lane = tid & 31, wid = tid >> 5;
    const int wM = wid % WMW, wN = wid / WMW;
    const int m0 = blockIdx.y * BM, n0 = blockIdx.x * BN, b = blockIdx.z;

    A += (size_t)b * sA + (size_t)m0 * lda;
    B += (size_t)b * sB + (size_t)n0 * ldb;
    C += (size_t)b * sC;
    if (SQ) C2 += (size_t)b * sC;

    float acc[MI][NI][4];
#pragma unroll
    for (int mi = 0; mi < MI; mi++)
#pragma unroll
        for (int ni = 0; ni < NI; ni++)
#pragma unroll
            for (int q = 0; q < 4; q++) acc[mi][ni][q] = 0.f;

    const int NK = K >> 5;   // 32 halves per k-block

    {
#pragma unroll
        for (int v = 0; v < ACH; v++) {
            int t = tid + v * 256, r = t >> 2, ch = t & 3;
            cp16(sbase + (uint32_t)(r * SRS + ch * 8) * 2, A + (size_t)r * lda + ch * 8);
        }
#pragma unroll
        for (int v = 0; v < BCH; v++) {
            int t = tid + v * 256, r = t >> 2, ch = t & 3;
            cp16(sbase + (uint32_t)(ASZ + r * SRS + ch * 8) * 2, B + (size_t)r * ldb + ch * 8);
        }
        cp_commit();
    }

    const int g = lane >> 2, tq = lane & 3;

    for (int i = 0; i < NK; i++) {
        if (i + 1 < NK) {
            const int st = (i + 1) & 1;
            const int k0 = (i + 1) << 5;
#pragma unroll
            for (int v = 0; v < ACH; v++) {
                int t = tid + v * 256, r = t >> 2, ch = t & 3;
                cp16(sbase + (uint32_t)(st * STG + r * SRS + ch * 8) * 2,
                     A + (size_t)r * lda + k0 + ch * 8);
            }
#pragma unroll
            for (int v = 0; v < BCH; v++) {
                int t = tid + v * 256, r = t >> 2, ch = t & 3;
                cp16(sbase + (uint32_t)(st * STG + ASZ + r * SRS + ch * 8) * 2,
                     B + (size_t)r * ldb + k0 + ch * 8);
            }
            cp_commit();
            cp_wait<1>();
        } else {
            cp_wait<0>();
        }
        __syncthreads();

        const uint32_t* Asw = reinterpret_cast<const uint32_t*>(smh + (i & 1) * STG);
        const uint32_t* Bsw = Asw + ASZ / 2;

#pragma unroll
        for (int kk = 0; kk < 2; kk++) {
            const int kw = kk * 8;
            uint32_t af[MI][4], bf[NI][2];
#pragma unroll
            for (int mi = 0; mi < MI; mi++) {
                const int row = wM * WTM + mi * 16 + g;
                af[mi][0] = Asw[row * SRW + kw + tq];
                af[mi][1] = Asw[(row + 8) * SRW + kw + tq];
                af[mi][2] = Asw[row * SRW + kw + 4 + tq];
                af[mi][3] = Asw[(row + 8) * SRW + kw + 4 + tq];
            }
#pragma unroll
            for (int ni = 0; ni < NI; ni++) {
                const int nr = wN * WTN + ni * 8 + g;
                bf[ni][0] = Bsw[nr * SRW + kw + tq];
                bf[ni][1] = Bsw[nr * SRW + kw + 4 + tq];
            }
#pragma unroll
            for (int mi = 0; mi < MI; mi++)
#pragma unroll
                for (int ni = 0; ni < NI; ni++)
                    mma_f16(acc[mi][ni], af[mi], bf[ni]);
        }
        __syncthreads();
    }

    // ---- epilogue ----
#pragma unroll
    for (int mi = 0; mi < MI; mi++) {
        const int row0 = m0 + wM * WTM + mi * 16 + g;
        float bm0 = 0.f, bm1 = 0.f;
        if (BIAS_MODE == 1) { bm0 = bias[row0]; bm1 = bias[row0 + 8]; }
#pragma unroll
        for (int ni = 0; ni < NI; ni++) {
            const int col = n0 + wN * WTN + ni * 8 + tq * 2;
            if (col >= Nrt) continue;
            float o0 = acc[mi][ni][0], o1 = acc[mi][ni][1];
            float o2 = acc[mi][ni][2], o3 = acc[mi][ni][3];
            if (BIAS_MODE == 1) { o0 += bm0; o1 += bm0; o2 += bm1; o3 += bm1; }
            if (BIAS_MODE == 2) {
                float bn0 = bias[col], bn1 = bias[col + 1];
                o0 += bn0; o1 += bn1; o2 += bn0; o3 += bn1;
            }
            if (sizeof(CT) == 4) {
                float* Cf = reinterpret_cast<float*>(C);
                *reinterpret_cast<float2*>(&Cf[(size_t)row0 * ldc + col])       = make_float2(o0, o1);
                *reinterpret_cast<float2*>(&Cf[(size_t)(row0 + 8) * ldc + col]) = make_float2(o2, o3);
            } else {
                __half* Ch = reinterpret_cast<__half*>(C);
                __half h0 = __float2half_rn(o0), h1 = __float2half_rn(o1);
                __half h2 = __float2half_rn(o2), h3 = __float2half_rn(o3);
                *reinterpret_cast<__half2*>(&Ch[(size_t)row0 * ldc + col])       = __halves2half2(h0, h1);
                *reinterpret_cast<__half2*>(&Ch[(size_t)(row0 + 8) * ldc + col]) = __halves2half2(h2, h3);
                if (SQ) {
                    __half* C2h = reinterpret_cast<__half*>(C2);
                    float f0 = __half2float(h0), f1 = __half2float(h1);
                    float f2 = __half2float(h2), f3 = __half2float(h3);
                    __half q0 = __float2half_rn(f0 * f0), q1 = __float2half_rn(f1 * f1);
                    __half q2 = __float2half_rn(f2 * f2), q3 = __float2half_rn(f3 * f3);
                    *reinterpret_cast<__half2*>(&C2h[(size_t)row0 * ldc + col])       = __halves2half2(q0, q1);
                    *reinterpret_cast<__half2*>(&C2h[(size_t)(row0 + 8) * ldc + col]) = __halves2half2(q2, q3);
                }
            }
        }
    }
}

// ---------------------------------------------------------------------------
// Dual-B fused FP16 GEMM for mean & m2 (shares attn A tiles):
//   C1[n][c] = A[n][:] . B1[c][:],  C2[n][c] = A[n][:] . B2[c][:]
//   BM=128 (tokens), BN=128 (channels), warps 2x4 -> warp tile 64x32.
//   fp32 accumulate; transposed fp32 store: out[c][n].
// ---------------------------------------------------------------------------
#define DUAL_SMEM ((128 * SRS + 2 * 128 * SRS) * 2 * 2)
__global__ __launch_bounds__(256) void mma_gemm_dualH(
    const __half* __restrict__ A, const __half* __restrict__ B1,
    const __half* __restrict__ B2,
    float* __restrict__ C1, float* __restrict__ C2)
{
    constexpr int BM = 128, BN = 128;
    constexpr int ASZ = BM * SRS, BSZ = BN * SRS;
    constexpr int STG = ASZ + 2 * BSZ;

    extern __shared__ __half smh[];
    const uint32_t sbase = smem_u32(smh);

    const int tid = threadIdx.x, lane = tid & 31, wid = tid >> 5;
    const int wM = wid & 1, wN = wid >> 1;
    const int m0 = blockIdx.y * BM, n0 = blockIdx.x * BN, b = blockIdx.z;

    A  += (size_t)b * NTOK * NTOK + (size_t)m0 * NTOK;
    B1 += (size_t)b * CIN * NTOK + (size_t)n0 * NTOK;
    B2 += (size_t)b * CIN * NTOK + (size_t)n0 * NTOK;
    C1 += (size_t)b * CIN * NTOK;
    C2 += (size_t)b * CIN * NTOK;

    float acc1[4][4][4], acc2[4][4][4];
#pragma unroll
    for (int mi = 0; mi < 4; mi++)
#pragma unroll
        for (int ni = 0; ni < 4; ni++)
#pragma unroll
            for (int q = 0; q < 4; q++) { acc1[mi][ni][q] = 0.f; acc2[mi][ni][q] = 0.f; }

    const int NK = NTOK >> 5;

    {
#pragma unroll
        for (int v = 0; v < 2; v++) {
            int t = tid + v * 256, r = t >> 2, ch = t & 3;
            cp16(sbase + (uint32_t)(r * SRS + ch * 8) * 2, A + (size_t)r * NTOK + ch * 8);
            cp16(sbase + (uint32_t)(ASZ + r * SRS + ch * 8) * 2, B1 + (size_t)r * NTOK + ch * 8);
            cp16(sbase + (uint32_t)(ASZ + BSZ + r * SRS + ch * 8) * 2, B2 + (size_t)r * NTOK + ch * 8);
        }
        cp_commit();
    }

    const int g = lane >> 2, tq = lane & 3;

    for (int i = 0; i < NK; i++) {
        if (i + 1 < NK) {
            const int st = (i + 1) & 1;
            const int k0 = (i + 1) << 5;
#pragma unroll
            for (int v = 0; v < 2; v++) {
                int t = tid + v * 256, r = t >> 2, ch = t & 3;
                cp16(sbase + (uint32_t)(st * STG + r * SRS + ch * 8) * 2,
                     A + (size_t)r * NTOK + k0 + ch * 8);
                cp16(sbase + (uint32_t)(st * STG + ASZ + r * SRS + ch * 8) * 2,
                     B1 + (size_t)r * NTOK + k0 + ch * 8);
                cp16(sbase + (uint32_t)(st * STG + ASZ + BSZ + r * SRS + ch * 8) * 2,
                     B2 + (size_t)r * NTOK + k0 + ch * 8);
            }
            cp_commit();
            cp_wait<1>();
        } else {
            cp_wait<0>();
        }
        __syncthreads();

        const uint32_t* Asw  = reinterpret_cast<const uint32_t*>(smh + (i & 1) * STG);
        const uint32_t* Bsw1 = Asw + ASZ / 2;
        const uint32_t* Bsw2 = Bsw1 + BSZ / 2;

#pragma unroll
        for (int kk = 0; kk < 2; kk++) {
            const int kw = kk * 8;
            uint32_t af[4][4], bf1[4][2], bf2[4][2];
#pragma unroll
            for (int mi = 0; mi < 4; mi++) {
                const int row = wM * 64 + mi * 16 + g;
                af[mi][0] = Asw[row * SRW + kw + tq];
                af[mi][1] = Asw[(row + 8) * SRW + kw + tq];
                af[mi][2] = Asw[row * SRW + kw + 4 + tq];
                af[mi][3] = Asw[(row + 8) * SRW + kw + 4 + tq];
            }
#pragma unroll
            for (int ni = 0; ni < 4; ni++) {
                const int nr = wN * 32 + ni * 8 + g;
                bf1[ni][0] = Bsw1[nr * SRW + kw + tq];
                bf1[ni][1] = Bsw1[nr * SRW + kw + 4 + tq];
                bf2[ni][0] = Bsw2[nr * SRW + kw + tq];
                bf2[ni][1] = Bsw2[nr * SRW + kw + 4 + tq];
            }
#pragma unroll
            for (int mi = 0; mi < 4; mi++)
#pragma unroll
                for (int ni = 0; ni < 4; ni++) {
                    mma_f16(acc1[mi][ni], af[mi], bf1[ni]);
                    mma_f16(acc2[mi][ni], af[mi], bf2[ni]);
                }
        }
        __syncthreads();
    }

#pragma unroll
    for (int mi = 0; mi < 4; mi++) {
        const int row0 = m0 + wM * 64 + mi * 16 + g;
#pragma unroll
        for (int ni = 0; ni < 4; ni++) {
            const int col = n0 + wN * 32 + ni * 8 + tq * 2;
            C1[(size_t)col * NTOK + row0]           = acc1[mi][ni][0];
            C1[(size_t)(col + 1) * NTOK + row0]     = acc1[mi][ni][1];
            C1[(size_t)col * NTOK + row0 + 8]       = acc1[mi][ni][2];
            C1[(size_t)(col + 1) * NTOK + row0 + 8] = acc1[mi][ni][3];
            C2[(size_t)col * NTOK + row0]           = acc2[mi][ni][0];
            C2[(size_t)(col + 1) * NTOK + row0]     = acc2[mi][ni][1];
            C2[(size_t)col * NTOK + row0 + 8]       = acc2[mi][ni][2];
            C2[(size_t)(col + 1) * NTOK + row0 + 8] = acc2[mi][ni][3];
        }
    }
}

// ---------------------------------------------------------------------------
// Weight prep: round W to half, pad rows to dstRows with zeros; pad bias (f32).
// ---------------------------------------------------------------------------
__global__ void prep_w_kernel(const float* __restrict__ W, const float* __restrict__ bias,
                              __half* __restrict__ Wd, float* __restrict__ bd,
                              int rows, int cols, int dstRows)
{
    int i = blockIdx.x * 256 + threadIdx.x;
    int total = dstRows * cols;
    if (i < total) {
        int r = i / cols;
        Wd[i] = (r < rows) ? __float2half_rn(W[i]) : __float2half_rn(0.f);
    }
    if (bd && i < dstRows) bd[i] = (i < rows) ? bias[i] : 0.f;
}

// ---------------------------------------------------------------------------
// Transpose [C][N] fp32 -> [N][C] half. Two tensors via z split.
// ---------------------------------------------------------------------------
template <int C>
__global__ __launch_bounds__(256) void transpose_in_kernel(
    const float* __restrict__ in0, __half* __restrict__ out0,
    const float* __restrict__ in1, __half* __restrict__ out1)
{
    __shared__ float t[32][33];
    const int z = blockIdx.z;
    const int b = z & (NB - 1);
    const float* in = (z < NB) ? in0 : in1;
    __half* out = (z < NB) ? out0 : out1;
    in  += (size_t)b * C * NTOK;
    out += (size_t)b * NTOK * C;

    const int x0 = blockIdx.x * 32;   // token
    const int y0 = blockIdx.y * 32;   // channel
    const int tx = threadIdx.x & 31, ty = threadIdx.x >> 5;

#pragma unroll
    for (int i = 0; i < 4; i++)
        t[ty + i * 8][tx] = in[(size_t)(y0 + ty + i * 8) * NTOK + x0 + tx];
    __syncthreads();
#pragma unroll
    for (int i = 0; i < 4; i++)
        out[(size_t)(x0 + ty + i * 8) * C + y0 + tx] = __float2half_rn(t[tx][ty + i * 8]);
}

// ---------------------------------------------------------------------------
// Reductions / softmax / stats / combine
// ---------------------------------------------------------------------------
__device__ __forceinline__ float warpMax(float v) {
#pragma unroll
    for (int o = 16; o; o >>= 1) v = fmaxf(v, __shfl_xor_sync(0xffffffffu, v, o));
    return v;
}
__device__ __forceinline__ float warpSum(float v) {
#pragma unroll
    for (int o = 16; o; o >>= 1) v += __shfl_xor_sync(0xffffffffu, v, o);
    return v;
}

// reads fp32 S, writes half attn
__global__ __launch_bounds__(256) void softmax_mask_kernel(
    const float* __restrict__ S, __half* __restrict__ Aout,
    const int* __restrict__ cmask, const int* __restrict__ smask)
{
    const int n = blockIdx.x, b = blockIdx.y;
    const float* row = S + ((size_t)b * NTOK + n) * NTOK;
    __half* arow = Aout + ((size_t)b * NTOK + n) * NTOK;
    const int* sm = smask + (size_t)b * NTOK;
    const bool cmn = (cmask[(size_t)b * NTOK + n] != 0);
    const int tid = threadIdx.x;
    __shared__ float red[8];

    float v[16];
    float mx = -INFINITY;
#pragma unroll
    for (int i = 0; i < 16; i++) {
        int m = tid + i * 256;
        float s = row[m];
        if (cmn && sm[m] == 0) s = NEGV;
        v[i] = s;
        mx = fmaxf(mx, s);
    }
    mx = warpMax(mx);
    if ((tid & 31) == 0) red[tid >> 5] = mx;
    __syncthreads();
    if (tid < 32) {
        float x = (tid < 8) ? red[tid] : -INFINITY;
        x = warpMax(x);
        if (tid == 0) red[0] = x;
    }
    __syncthreads();
    mx = red[0];
    __syncthreads();

    float sum = 0.f;
#pragma unroll
    for (int i = 0; i < 16; i++) { v[i] = __expf(v[i] - mx); sum += v[i]; }
    sum = warpSum(sum);
    if ((tid & 31) == 0) red[tid >> 5] = sum;
    __syncthreads();
    if (tid < 32) {
        float x = (tid < 8) ? red[tid] : 0.f;
        x = warpSum(x);
        if (tid == 0) red[0] = x;
    }
    __syncthreads();
    const float inv = 1.f / red[0];
#pragma unroll
    for (int i = 0; i < 16; i++)
        arow[tid + i * 256] = __float2half_rn(v[i] * inv);
}

__global__ __launch_bounds__(256) void mvn_stats_kernel(
    const float* __restrict__ content,
    float* __restrict__ cmean, float* __restrict__ crstd)
{
    const int c = blockIdx.x, b = blockIdx.y;
    const float* p = content + ((size_t)b * CIN + c) * NTOK;
    const int tid = threadIdx.x;
    float s = 0.f, ss = 0.f;
#pragma unroll
    for (int i = 0; i < 16; i++) {
        float x = p[tid + i * 256];
        s += x; ss += x * x;
    }
    __shared__ float shs[8], shss[8];
    s = warpSum(s); ss = warpSum(ss);
    if ((tid & 31) == 0) { shs[tid >> 5] = s; shss[tid >> 5] = ss; }
    __syncthreads();
    if (tid == 0) {
        float S = 0.f, SS = 0.f;
#pragma unroll
        for (int i = 0; i < 8; i++) { S += shs[i]; SS += shss[i]; }
        float mean = S / (float)NTOK;
        float var = (SS - S * S / (float)NTOK) / (float)(NTOK - 1);
        cmean[b * CIN + c] = mean;
        crstd[b * CIN + c] = rsqrtf(var + EPSV);
    }
}

__global__ __launch_bounds__(256) void combine_kernel(
    const float4* __restrict__ content,
    const float4* __restrict__ meanT,
    const float4* __restrict__ m2T,
    const float* __restrict__ cmean,
    const float* __restrict__ crstd,
    float4* __restrict__ out)
{
    const int gid = blockIdx.x * 256 + threadIdx.x;
    const int bc = gid >> 10;
    const float mu = cmean[bc];
    const float rs = crstd[bc];
    float4 mn = meanT[gid];
    float4 m2 = m2T[gid];
    float4 ct = content[gid];
    float4 o;
    o.x = sqrtf(fmaxf(m2.x - mn.x * mn.x, 0.f)) * ((ct.x - mu) * rs) + mn.x;
    o.y = sqrtf(fmaxf(m2.y - mn.y * mn.y, 0.f)) * ((ct.y - mu) * rs) + mn.y;
    o.z = sqrtf(fmaxf(m2.z - mn.z * mn.z, 0.f)) * ((ct.z - mu) * rs) + mn.z;
    o.w = sqrtf(fmaxf(m2.w - mn.w * mn.w, 0.f)) * ((ct.w - mu) * rs) + mn.w;
    out[gid] = o;
}

// ---------------------------------------------------------------------------
// Launch
// ---------------------------------------------------------------------------
extern "C" void kernel_launch(void* const* d_in, const int* in_sizes, int n_in,
                              void* d_out, int out_size)
{
    const float* content = (const float*)d_in[0];
    const float* style   = (const float*)d_in[1];
    const float* ckey    = (const float*)d_in[2];
    const float* skey    = (const float*)d_in[3];
    const int*   cmask   = (const int*)  d_in[4];
    const int*   smask   = (const int*)  d_in[5];
    const float* Wf = (const float*)d_in[6];
    const float* bf = (const float*)d_in[7];
    const float* Wg = (const float*)d_in[8];
    const float* bg = (const float*)d_in[9];
    const float* Wh = (const float*)d_in[10];
    const float* bh = (const float*)d_in[11];
    float* out = (float*)d_out;

    __half *pckT, *pskT, *pstT, *pFqN, *pGN, *pHv, *pHv2, *pA, *pWf, *pWg, *pWh;
    float *pS, *pMean, *pM2, *pbf, *pbg, *pCm, *pCr;
    cudaGetSymbolAddress((void**)&pckT, g_ckT);
    cudaGetSymbolAddress((void**)&pskT, g_skT);
    cudaGetSymbolAddress((void**)&pstT, g_stT);
    cudaGetSymbolAddress((void**)&pFqN, g_FqN);
    cudaGetSymbolAddress((void**)&pGN,  g_GN);
    cudaGetSymbolAddress((void**)&pHv,  g_HvT);
    cudaGetSymbolAddress((void**)&pHv2, g_Hv2T);
    cudaGetSymbolAddress((void**)&pA,   g_A);
    cudaGetSymbolAddress((void**)&pS,   g_S);
    cudaGetSymbolAddress((void**)&pMean, g_meanT);
    cudaGetSymbolAddress((void**)&pM2,  g_m2T);
    cudaGetSymbolAddress((void**)&pWf,  g_Wf);
    cudaGetSymbolAddress((void**)&pWg,  g_Wg);
    cudaGetSymbolAddress((void**)&pWh,  g_Wh);
    cudaGetSymbolAddress((void**)&pbf,  g_bf);
    cudaGetSymbolAddress((void**)&pbg,  g_bg);
    cudaGetSymbolAddress((void**)&pCm,  g_cmean);
    cudaGetSymbolAddress((void**)&pCr,  g_crstd);

    constexpr int SMEM_PRJ = (128 * SRS + 128 * SRS) * 2 * 2;  // 40960
    constexpr int SMEM_S   = (128 * SRS + 256 * SRS) * 2 * 2;  // 61440

    static bool attr_done = false;
    if (!attr_done) {
        cudaFuncSetAttribute(mma_gemmH<128, 256, 2, 0, false, float>,
                             cudaFuncAttributeMaxDynamicSharedMemorySize, SMEM_S);
        cudaFuncSetAttribute(mma_gemmH<128, 128, 4, 2, false, __half>,
                             cudaFuncAttributeMaxDynamicSharedMemorySize, SMEM_PRJ);
        cudaFuncSetAttribute(mma_gemmH<128, 128, 4, 1, true, __half>,
                             cudaFuncAttributeMaxDynamicSharedMemorySize, SMEM_PRJ);
        cudaFuncSetAttribute(mma_gemm_dualH,
                             cudaFuncAttributeMaxDynamicSharedMemorySize, DUAL_SMEM);
        attr_done = true;
    }

    const dim3 blk(256);

    // --- weight prep ---
    prep_w_kernel<<<(CKP * CKEY + 255) / 256, blk>>>(Wf, bf, pWf, pbf, CKEY, CKEY, CKP);
    prep_w_kernel<<<(CKP * CKEY + 255) / 256, blk>>>(Wg, bg, pWg, pbg, CKEY, CKEY, CKP);
    prep_w_kernel<<<(CIN * CIN + 255) / 256, blk>>>(Wh, nullptr, pWh, nullptr, CIN, CIN, CIN);

    // --- transpose inputs to token-major half ---
    transpose_in_kernel<CKEY><<<dim3(NTOK / 32, CKEY / 32, 2 * NB), blk>>>(
        ckey, pckT, skey, pskT);
    transpose_in_kernel<CIN><<<dim3(NTOK / 32, CIN / 32, NB), blk>>>(
        style, pstT, style, pstT);

    // --- projections (fp16 mma, fp32 accum) ---
    mma_gemmH<128, 128, 4, 2, false, __half><<<dim3(CKP / 128, NTOK / 128, NB), blk, SMEM_PRJ>>>(
        pckT, pWf, pbf, pFqN, nullptr, CKEY, CKEY, CKEY, CKEY, CKEY,
        (size_t)NTOK * CKEY, 0, (size_t)NTOK * CKEY);
    mma_gemmH<128, 128, 4, 2, false, __half><<<dim3(CKP / 128, NTOK / 128, NB), blk, SMEM_PRJ>>>(
        pskT, pWg, pbg, pGN, nullptr, CKEY, CKEY, CKEY, CKEY, CKEY,
        (size_t)NTOK * CKEY, 0, (size_t)NTOK * CKEY);
    mma_gemmH<128, 128, 4, 1, true, __half><<<dim3(NTOK / 128, CIN / 128, NB), blk, SMEM_PRJ>>>(
        pWh, pstT, bh, pHv, pHv2, NTOK, CIN, CIN, CIN, NTOK,
        0, (size_t)NTOK * CIN, (size_t)CIN * NTOK);

    // --- S = FqN @ GN^T (fp32 out) ---
    mma_gemmH<128, 256, 2, 0, false, float><<<dim3(NTOK / 256, NTOK / 128, NB), blk, SMEM_S>>>(
        pFqN, pGN, nullptr, pS, nullptr, NTOK, CKEY, CKEY, CKEY, NTOK,
        (size_t)NTOK * CKEY, (size_t)NTOK * CKEY, (size_t)NTOK * NTOK);

    // --- masked softmax: fp32 S -> half attn ---
    softmax_mask_kernel<<<dim3(NTOK, NB), blk>>>(pS, pA, cmask, smask);

    // --- fused mean/m2 ---
    mma_gemm_dualH<<<dim3(CIN / 128, NTOK / 128, NB), blk, DUAL_SMEM>>>(
        pA, pHv, pHv2, pMean, pM2);

    // --- mvn stats + final combine ---
    mvn_stats_kernel<<<dim3(CIN, NB), blk>>>(content, pCm, pCr);
    combine_kernel<<<dim3((NB * CIN * NTOK / 4) / 256), blk>>>(
        (const float4*)content, (const float4*)pMean, (const float4*)pM2,
        pCm, pCr, (float4*)out);
}

// round 7
// speedup vs baseline: 4.8074x; 1.0353x over previous
#include <cuda_runtime.h>
#include <cuda_fp16.h>
#include <cstdint>

// ---------------------------------------------------------------------------
// Problem constants
// ---------------------------------------------------------------------------
#define NB   4
#define CIN  256
#define CKEY 448
#define NTOK 4096
#define NEGV (-1e15f)
#define EPSV 1e-5f
#define CKP  512   // padded CKEY for projection N-dim

// ---------------------------------------------------------------------------
// Scratch (static device globals; no runtime allocation)
// ---------------------------------------------------------------------------
__device__ __half g_ckT [(size_t)NB * NTOK * CKEY];   // [b][N][Ck] ckey^T
__device__ __half g_skT [(size_t)NB * NTOK * CKEY];   // [b][N][Ck] skey^T
__device__ __half g_stT [(size_t)NB * NTOK * CIN];    // [b][N][C]  style^T
__device__ __half g_FqN [(size_t)NB * NTOK * CKEY];   // [b][N][Ck] f(ckey)
__device__ __half g_GN  [(size_t)NB * NTOK * CKEY];   // [b][N][Ck] g(skey)
__device__ __half g_HvT [(size_t)NB * CIN  * NTOK];   // [b][C][N]  h(style)
__device__ __half g_Hv2T[(size_t)NB * CIN  * NTOK];   // [b][C][N]  h(style)^2
__device__ float  g_S   [(size_t)NB * NTOK * NTOK];   // [b][N][N]  scores (fp32)
__device__ __half g_A   [(size_t)NB * NTOK * NTOK];   // [b][N][N]  attn (half)
__device__ float  g_meanT[(size_t)NB * CIN * NTOK];   // [b][C][N]
__device__ float  g_m2T [(size_t)NB * CIN  * NTOK];   // [b][C][N]
__device__ __half g_Wf  [CKP * CKEY];                 // rounded, zero-padded rows
__device__ __half g_Wg  [CKP * CKEY];
__device__ __half g_Wh  [CIN * CIN];
__device__ float  g_bf  [CKP];
__device__ float  g_bg  [CKP];
__device__ float  g_cmean[NB * CIN];
__device__ float  g_crstd[NB * CIN];

// ---------------------------------------------------------------------------
// Helpers
// ---------------------------------------------------------------------------
__device__ __forceinline__ uint32_t smem_u32(const void* p) {
    uint32_t a;
    asm("{ .reg .u64 t; cvta.to.shared.u64 t, %1; cvt.u32.u64 %0, t; }"
        : "=r"(a) : "l"(p));
    return a;
}
__device__ __forceinline__ void cp16(uint32_t s, const void* g) {
    asm volatile("cp.async.cg.shared.global [%0], [%1], 16;" :: "r"(s), "l"(g));
}
__device__ __forceinline__ void cp_commit() {
    asm volatile("cp.async.commit_group;" ::: "memory");
}
template <int N> __device__ __forceinline__ void cp_wait() {
    asm volatile("cp.async.wait_group %0;" :: "n"(N) : "memory");
}
__device__ __forceinline__ void mma_f16(float* d, const uint32_t* a, const uint32_t* b) {
    asm volatile(
        "mma.sync.aligned.m16n8k16.row.col.f32.f16.f16.f32 "
        "{%0,%1,%2,%3}, {%4,%5,%6,%7}, {%8,%9}, {%0,%1,%2,%3};"
        : "+f"(d[0]), "+f"(d[1]), "+f"(d[2]), "+f"(d[3])
        : "r"(a[0]), "r"(a[1]), "r"(a[2]), "r"(a[3]), "r"(b[0]), "r"(b[1]));
}
__device__ __forceinline__ void ldsm_x4(uint32_t* r, uint32_t a) {
    asm volatile("ldmatrix.sync.aligned.m8n8.x4.shared.b16 {%0,%1,%2,%3}, [%4];"
        : "=r"(r[0]), "=r"(r[1]), "=r"(r[2]), "=r"(r[3]) : "r"(a));
}
__device__ __forceinline__ void ldsm_x2(uint32_t* r, uint32_t a) {
    asm volatile("ldmatrix.sync.aligned.m8n8.x2.shared.b16 {%0,%1}, [%2];"
        : "=r"(r[0]), "=r"(r[1]) : "r"(a));
}

// smem row stride: 40 halves (80 B) — conflict-free for LDSM (8 consecutive
// rows hit 8 distinct 16B chunks mod 128B) and for cp.async stores.
#define SRS 40

// ---------------------------------------------------------------------------
// Generic FP16 mma.sync GEMM:  C[M][N] = A[M][K] * B[N][K]^T   (fp32 accum)
//   256 threads, WMW x (8/WMW) warps, BK=32 halves, double-buffered cp.async,
//   ldmatrix fragment loads.
//   BIAS_MODE: 0 none, 1 along M, 2 along N (bias fp32)
//   SQ: also write C2 = rn(h*h), h = rn(C)  (CT == __half)
//   CT: output type (float or __half). Store guard: col < Nrt.
// ---------------------------------------------------------------------------
template <int BM, int BN, int WMW, int BIAS_MODE, bool SQ, typename CT>
__global__ __launch_bounds__(256) void mma_gemmH(
    const __half* __restrict__ A, const __half* __restrict__ B,
    const float* __restrict__ bias,
    CT* __restrict__ C, CT* __restrict__ C2,
    int Nrt, int K, int lda, int ldb, int ldc,
    size_t sA, size_t sB, size_t sC)
{
    constexpr int WNW = 8 / WMW;
    constexpr int WTM = BM / WMW;
    constexpr int WTN = BN / WNW;
    constexpr int MI  = WTM / 16;
    constexpr int NI  = WTN / 8;
    constexpr int ASZ = BM * SRS;          // halves
    constexpr int BSZ = BN * SRS;
    constexpr int STG = ASZ + BSZ;
    constexpr int ACH = BM * 4 / 256;      // cp16 chunks per thread (A)
    constexpr int BCH = BN * 4 / 256;

    extern __shared__ __half smh[];
    const uint32_t sbase = smem_u32(smh);

    const int tid = threadIdx.x, lane = tid & 31, wid = tid >> 5;
    const int wM = wid % WMW, wN = wid / WMW;
    const int m0 = blockIdx.y * BM, n0 = blockIdx.x * BN, b = blockIdx.z;

    A += (size_t)b * sA + (size_t)m0 * lda;
    B += (size_t)b * sB + (size_t)n0 * ldb;
    C += (size_t)b * sC;
    if (SQ) C2 += (size_t)b * sC;

    float acc[MI][NI][4];
#pragma unroll
    for (int mi = 0; mi < MI; mi++)
#pragma unroll
        for (int ni = 0; ni < NI; ni++)
#pragma unroll
            for (int q = 0; q < 4; q++) acc[mi][ni][q] = 0.f;

    const int NK = K >> 5;   // 32 halves per k-block

    {
#pragma unroll
        for (int v = 0; v < ACH; v++) {
            int t = tid + v * 256, r = t >> 2, ch = t & 3;
            cp16(sbase + (uint32_t)(r * SRS + ch * 8) * 2, A + (size_t)r * lda + ch * 8);
        }
#pragma unroll
        for (int v = 0; v < BCH; v++) {
            int t = tid + v * 256, r = t >> 2, ch = t & 3;
            cp16(sbase + (uint32_t)(ASZ + r * SRS + ch * 8) * 2, B + (size_t)r * ldb + ch * 8);
        }
        cp_commit();
    }

    const int g = lane >> 2, tq = lane & 3;
    // ldmatrix per-lane offsets (bytes)
    const uint32_t aoff = (uint32_t)((lane & 15) * SRS + (lane >> 4) * 8) * 2;
    const uint32_t boff = (uint32_t)((lane & 7) * SRS + ((lane >> 3) & 1) * 8) * 2;

    for (int i = 0; i < NK; i++) {
        if (i + 1 < NK) {
            const int st = (i + 1) & 1;
            const int k0 = (i + 1) << 5;
#pragma unroll
            for (int v = 0; v < ACH; v++) {
                int t = tid + v * 256, r = t >> 2, ch = t & 3;
                cp16(sbase + (uint32_t)(st * STG + r * SRS + ch * 8) * 2,
                     A + (size_t)r * lda + k0 + ch * 8);
            }
#pragma unroll
            for (int v = 0; v < BCH; v++) {
                int t = tid + v * 256, r = t >> 2, ch = t & 3;
                cp16(sbase + (uint32_t)(st * STG + ASZ + r * SRS + ch * 8) * 2,
                     B + (size_t)r * ldb + k0 + ch * 8);
            }
            cp_commit();
            cp_wait<1>();
        } else {
            cp_wait<0>();
        }
        __syncthreads();

        const uint32_t stg_b = sbase + (uint32_t)((i & 1) * STG) * 2;
        const uint32_t bstg_b = stg_b + (uint32_t)ASZ * 2;

#pragma unroll
        for (int kk = 0; kk < 2; kk++) {
            const uint32_t kh = kk * 16 * 2;   // byte offset within row
            uint32_t af[MI][4], bf[NI][2];
#pragma unroll
            for (int mi = 0; mi < MI; mi++)
                ldsm_x4(af[mi], stg_b + (uint32_t)((wM * WTM + mi * 16) * SRS) * 2 + kh + aoff);
#pragma unroll
            for (int ni = 0; ni < NI; ni++)
                ldsm_x2(bf[ni], bstg_b + (uint32_t)((wN * WTN + ni * 8) * SRS) * 2 + kh + boff);
#pragma unroll
            for (int mi = 0; mi < MI; mi++)
#pragma unroll
                for (int ni = 0; ni < NI; ni++)
                    mma_f16(acc[mi][ni], af[mi], bf[ni]);
        }
        __syncthreads();
    }

    // ---- epilogue ----
#pragma unroll
    for (int mi = 0; mi < MI; mi++) {
        const int row0 = m0 + wM * WTM + mi * 16 + g;
        float bm0 = 0.f, bm1 = 0.f;
        if (BIAS_MODE == 1) { bm0 = bias[row0]; bm1 = bias[row0 + 8]; }
#pragma unroll
        for (int ni = 0; ni < NI; ni++) {
            const int col = n0 + wN * WTN + ni * 8 + tq * 2;
            if (col >= Nrt) continue;
            float o0 = acc[mi][ni][0], o1 = acc[mi][ni][1];
            float o2 = acc[mi][ni][2], o3 = acc[mi][ni][3];
            if (BIAS_MODE == 1) { o0 += bm0; o1 += bm0; o2 += bm1; o3 += bm1; }
            if (BIAS_MODE == 2) {
                float bn0 = bias[col], bn1 = bias[col + 1];
                o0 += bn0; o1 += bn1; o2 += bn0; o3 += bn1;
            }
            if (sizeof(CT) == 4) {
                float* Cf = reinterpret_cast<float*>(C);
                *reinterpret_cast<float2*>(&Cf[(size_t)row0 * ldc + col])       = make_float2(o0, o1);
                *reinterpret_cast<float2*>(&Cf[(size_t)(row0 + 8) * ldc + col]) = make_float2(o2, o3);
            } else {
                __half* Ch = reinterpret_cast<__half*>(C);
                __half h0 = __float2half_rn(o0), h1 = __float2half_rn(o1);
                __half h2 = __float2half_rn(o2), h3 = __float2half_rn(o3);
                *reinterpret_cast<__half2*>(&Ch[(size_t)row0 * ldc + col])       = __halves2half2(h0, h1);
                *reinterpret_cast<__half2*>(&Ch[(size_t)(row0 + 8) * ldc + col]) = __halves2half2(h2, h3);
                if (SQ) {
                    __half* C2h = reinterpret_cast<__half*>(C2);
                    float f0 = __half2float(h0), f1 = __half2float(h1);
                    float f2 = __half2float(h2), f3 = __half2float(h3);
                    __half q0 = __float2half_rn(f0 * f0), q1 = __float2half_rn(f1 * f1);
                    __half q2 = __float2half_rn(f2 * f2), q3 = __float2half_rn(f3 * f3);
                    *reinterpret_cast<__half2*>(&C2h[(size_t)row0 * ldc + col])       = __halves2half2(q0, q1);
                    *reinterpret_cast<__half2*>(&C2h[(size_t)(row0 + 8) * ldc + col]) = __halves2half2(q2, q3);
                }
            }
        }
    }
}

// ---------------------------------------------------------------------------
// Dual-B fused FP16 GEMM for mean & m2 (shares attn A tiles), ldmatrix loads:
//   C1[n][c] = A[n][:] . B1[c][:],  C2[n][c] = A[n][:] . B2[c][:]
//   BM=128 (tokens), BN=128 (channels), warps 2x4 -> warp tile 64x32.
//   fp32 accumulate; transposed fp32 store: out[c][n].
// ---------------------------------------------------------------------------
#define DUAL_SMEM ((128 * SRS + 2 * 128 * SRS) * 2 * 2)
__global__ __launch_bounds__(256) void mma_gemm_dualH(
    const __half* __restrict__ A, const __half* __restrict__ B1,
    const __half* __restrict__ B2,
    float* __restrict__ C1, float* __restrict__ C2)
{
    constexpr int BM = 128, BN = 128;
    constexpr int ASZ = BM * SRS, BSZ = BN * SRS;
    constexpr int STG = ASZ + 2 * BSZ;

    extern __shared__ __half smh[];
    const uint32_t sbase = smem_u32(smh);

    const int tid = threadIdx.x, lane = tid & 31, wid = tid >> 5;
    const int wM = wid & 1, wN = wid >> 1;
    const int m0 = blockIdx.y * BM, n0 = blockIdx.x * BN, b = blockIdx.z;

    A  += (size_t)b * NTOK * NTOK + (size_t)m0 * NTOK;
    B1 += (size_t)b * CIN * NTOK + (size_t)n0 * NTOK;
    B2 += (size_t)b * CIN * NTOK + (size_t)n0 * NTOK;
    C1 += (size_t)b * CIN * NTOK;
    C2 += (size_t)b * CIN * NTOK;

    float acc1[4][4][4], acc2[4][4][4];
#pragma unroll
    for (int mi = 0; mi < 4; mi++)
#pragma unroll
        for (int ni = 0; ni < 4; ni++)
#pragma unroll
            for (int q = 0; q < 4; q++) { acc1[mi][ni][q] = 0.f; acc2[mi][ni][q] = 0.f; }

    const int NK = NTOK >> 5;

    {
#pragma unroll
        for (int v = 0; v < 2; v++) {
            int t = tid + v * 256, r = t >> 2, ch = t & 3;
            cp16(sbase + (uint32_t)(r * SRS + ch * 8) * 2, A + (size_t)r * NTOK + ch * 8);
            cp16(sbase + (uint32_t)(ASZ + r * SRS + ch * 8) * 2, B1 + (size_t)r * NTOK + ch * 8);
            cp16(sbase + (uint32_t)(ASZ + BSZ + r * SRS + ch * 8) * 2, B2 + (size_t)r * NTOK + ch * 8);
        }
        cp_commit();
    }

    const int g = lane >> 2, tq = lane & 3;
    const uint32_t aoff = (uint32_t)((lane & 15) * SRS + (lane >> 4) * 8) * 2;
    const uint32_t boff = (uint32_t)((lane & 7) * SRS + ((lane >> 3) & 1) * 8) * 2;

    for (int i = 0; i < NK; i++) {
        if (i + 1 < NK) {
            const int st = (i + 1) & 1;
            const int k0 = (i + 1) << 5;
#pragma unroll
            for (int v = 0; v < 2; v++) {
                int t = tid + v * 256, r = t >> 2, ch = t & 3;
                cp16(sbase + (uint32_t)(st * STG + r * SRS + ch * 8) * 2,
                     A + (size_t)r * NTOK + k0 + ch * 8);
                cp16(sbase + (uint32_t)(st * STG + ASZ + r * SRS + ch * 8) * 2,
                     B1 + (size_t)r * NTOK + k0 + ch * 8);
                cp16(sbase + (uint32_t)(st * STG + ASZ + BSZ + r * SRS + ch * 8) * 2,
                     B2 + (size_t)r * NTOK + k0 + ch * 8);
            }
            cp_commit();
            cp_wait<1>();
        } else {
            cp_wait<0>();
        }
        __syncthreads();

        const uint32_t stg_b  = sbase + (uint32_t)((i & 1) * STG) * 2;
        const uint32_t b1stg = stg_b + (uint32_t)ASZ * 2;
        const uint32_t b2stg = b1stg + (uint32_t)BSZ * 2;

#pragma unroll
        for (int kk = 0; kk < 2; kk++) {
            const uint32_t kh = kk * 16 * 2;
            uint32_t af[4][4], bf1[4][2], bf2[4][2];
#pragma unroll
            for (int mi = 0; mi < 4; mi++)
                ldsm_x4(af[mi], stg_b + (uint32_t)((wM * 64 + mi * 16) * SRS) * 2 + kh + aoff);
#pragma unroll
            for (int ni = 0; ni < 4; ni++) {
                ldsm_x2(bf1[ni], b1stg + (uint32_t)((wN * 32 + ni * 8) * SRS) * 2 + kh + boff);
                ldsm_x2(bf2[ni], b2stg + (uint32_t)((wN * 32 + ni * 8) * SRS) * 2 + kh + boff);
            }
#pragma unroll
            for (int mi = 0; mi < 4; mi++)
#pragma unroll
                for (int ni = 0; ni < 4; ni++) {
                    mma_f16(acc1[mi][ni], af[mi], bf1[ni]);
                    mma_f16(acc2[mi][ni], af[mi], bf2[ni]);
                }
        }
        __syncthreads();
    }

#pragma unroll
    for (int mi = 0; mi < 4; mi++) {
        const int row0 = m0 + wM * 64 + mi * 16 + g;
#pragma unroll
        for (int ni = 0; ni < 4; ni++) {
            const int col = n0 + wN * 32 + ni * 8 + tq * 2;
            C1[(size_t)col * NTOK + row0]           = acc1[mi][ni][0];
            C1[(size_t)(col + 1) * NTOK + row0]     = acc1[mi][ni][1];
            C1[(size_t)col * NTOK + row0 + 8]       = acc1[mi][ni][2];
            C1[(size_t)(col + 1) * NTOK + row0 + 8] = acc1[mi][ni][3];
            C2[(size_t)col * NTOK + row0]           = acc2[mi][ni][0];
            C2[(size_t)(col + 1) * NTOK + row0]     = acc2[mi][ni][1];
            C2[(size_t)col * NTOK + row0 + 8]       = acc2[mi][ni][2];
            C2[(size_t)(col + 1) * NTOK + row0 + 8] = acc2[mi][ni][3];
        }
    }
}

// ---------------------------------------------------------------------------
// Weight prep: round W to half, pad rows to dstRows with zeros; pad bias (f32).
// ---------------------------------------------------------------------------
__global__ void prep_w_kernel(const float* __restrict__ W, const float* __restrict__ bias,
                              __half* __restrict__ Wd, float* __restrict__ bd,
                              int rows, int cols, int dstRows)
{
    int i = blockIdx.x * 256 + threadIdx.x;
    int total = dstRows * cols;
    if (i < total) {
        int r = i / cols;
        Wd[i] = (r < rows) ? __float2half_rn(W[i]) : __float2half_rn(0.f);
    }
    if (bd && i < dstRows) bd[i] = (i < rows) ? bias[i] : 0.f;
}

// ---------------------------------------------------------------------------
// Transpose [C][N] fp32 -> [N][C] half. Two tensors via z split.
// ---------------------------------------------------------------------------
template <int C>
__global__ __launch_bounds__(256) void transpose_in_kernel(
    const float* __restrict__ in0, __half* __restrict__ out0,
    const float* __restrict__ in1, __half* __restrict__ out1)
{
    __shared__ float t[32][33];
    const int z = blockIdx.z;
    const int b = z & (NB - 1);
    const float* in = (z < NB) ? in0 : in1;
    __half* out = (z < NB) ? out0 : out1;
    in  += (size_t)b * C * NTOK;
    out += (size_t)b * NTOK * C;

    const int x0 = blockIdx.x * 32;   // token
    const int y0 = blockIdx.y * 32;   // channel
    const int tx = threadIdx.x & 31, ty = threadIdx.x >> 5;

#pragma unroll
    for (int i = 0; i < 4; i++)
        t[ty + i * 8][tx] = in[(size_t)(y0 + ty + i * 8) * NTOK + x0 + tx];
    __syncthreads();
#pragma unroll
    for (int i = 0; i < 4; i++)
        out[(size_t)(x0 + ty + i * 8) * C + y0 + tx] = __float2half_rn(t[tx][ty + i * 8]);
}

// ---------------------------------------------------------------------------
// Reductions / softmax / stats / combine
// ---------------------------------------------------------------------------
__device__ __forceinline__ float warpMax(float v) {
#pragma unroll
    for (int o = 16; o; o >>= 1) v = fmaxf(v, __shfl_xor_sync(0xffffffffu, v, o));
    return v;
}
__device__ __forceinline__ float warpSum(float v) {
#pragma unroll
    for (int o = 16; o; o >>= 1) v += __shfl_xor_sync(0xffffffffu, v, o);
    return v;
}

// reads fp32 S, writes half attn
__global__ __launch_bounds__(256) void softmax_mask_kernel(
    const float* __restrict__ S, __half* __restrict__ Aout,
    const int* __restrict__ cmask, const int* __restrict__ smask)
{
    const int n = blockIdx.x, b = blockIdx.y;
    const float* row = S + ((size_t)b * NTOK + n) * NTOK;
    __half* arow = Aout + ((size_t)b * NTOK + n) * NTOK;
    const int* sm = smask + (size_t)b * NTOK;
    const bool cmn = (cmask[(size_t)b * NTOK + n] != 0);
    const int tid = threadIdx.x;
    __shared__ float red[8];

    float v[16];
    float mx = -INFINITY;
#pragma unroll
    for (int i = 0; i < 16; i++) {
        int m = tid + i * 256;
        float s = row[m];
        if (cmn && sm[m] == 0) s = NEGV;
        v[i] = s;
        mx = fmaxf(mx, s);
    }
    mx = warpMax(mx);
    if ((tid & 31) == 0) red[tid >> 5] = mx;
    __syncthreads();
    if (tid < 32) {
        float x = (tid < 8) ? red[tid] : -INFINITY;
        x = warpMax(x);
        if (tid == 0) red[0] = x;
    }
    __syncthreads();
    mx = red[0];
    __syncthreads();

    float sum = 0.f;
#pragma unroll
    for (int i = 0; i < 16; i++) { v[i] = __expf(v[i] - mx); sum += v[i]; }
    sum = warpSum(sum);
    if ((tid & 31) == 0) red[tid >> 5] = sum;
    __syncthreads();
    if (tid < 32) {
        float x = (tid < 8) ? red[tid] : 0.f;
        x = warpSum(x);
        if (tid == 0) red[0] = x;
    }
    __syncthreads();
    const float inv = 1.f / red[0];
#pragma unroll
    for (int i = 0; i < 16; i++)
        arow[tid + i * 256] = __float2half_rn(v[i] * inv);
}

__global__ __launch_bounds__(256) void mvn_stats_kernel(
    const float* __restrict__ content,
    float* __restrict__ cmean, float* __restrict__ crstd)
{
    const int c = blockIdx.x, b = blockIdx.y;
    const float* p = content + ((size_t)b * CIN + c) * NTOK;
    const int tid = threadIdx.x;
    float s = 0.f, ss = 0.f;
#pragma unroll
    for (int i = 0; i < 16; i++) {
        float x = p[tid + i * 256];
        s += x; ss += x * x;
    }
    __shared__ float shs[8], shss[8];
    s = warpSum(s); ss = warpSum(ss);
    if ((tid & 31) == 0) { shs[tid >> 5] = s; shss[tid >> 5] = ss; }
    __syncthreads();
    if (tid == 0) {
        float S = 0.f, SS = 0.f;
#pragma unroll
        for (int i = 0; i < 8; i++) { S += shs[i]; SS += shss[i]; }
        float mean = S / (float)NTOK;
        float var = (SS - S * S / (float)NTOK) / (float)(NTOK - 1);
        cmean[b * CIN + c] = mean;
        crstd[b * CIN + c] = rsqrtf(var + EPSV);
    }
}

__global__ __launch_bounds__(256) void combine_kernel(
    const float4* __restrict__ content,
    const float4* __restrict__ meanT,
    const float4* __restrict__ m2T,
    const float* __restrict__ cmean,
    const float* __restrict__ crstd,
    float4* __restrict__ out)
{
    const int gid = blockIdx.x * 256 + threadIdx.x;
    const int bc = gid >> 10;
    const float mu = cmean[bc];
    const float rs = crstd[bc];
    float4 mn = meanT[gid];
    float4 m2 = m2T[gid];
    float4 ct = content[gid];
    float4 o;
    o.x = sqrtf(fmaxf(m2.x - mn.x * mn.x, 0.f)) * ((ct.x - mu) * rs) + mn.x;
    o.y = sqrtf(fmaxf(m2.y - mn.y * mn.y, 0.f)) * ((ct.y - mu) * rs) + mn.y;
    o.z = sqrtf(fmaxf(m2.z - mn.z * mn.z, 0.f)) * ((ct.z - mu) * rs) + mn.z;
    o.w = sqrtf(fmaxf(m2.w - mn.w * mn.w, 0.f)) * ((ct.w - mu) * rs) + mn.w;
    out[gid] = o;
}

// ---------------------------------------------------------------------------
// Launch
// ---------------------------------------------------------------------------
extern "C" void kernel_launch(void* const* d_in, const int* in_sizes, int n_in,
                              void* d_out, int out_size)
{
    const float* content = (const float*)d_in[0];
    const float* style   = (const float*)d_in[1];
    const float* ckey    = (const float*)d_in[2];
    const float* skey    = (const float*)d_in[3];
    const int*   cmask   = (const int*)  d_in[4];
    const int*   smask   = (const int*)  d_in[5];
    const float* Wf = (const float*)d_in[6];
    const float* bf = (const float*)d_in[7];
    const float* Wg = (const float*)d_in[8];
    const float* bg = (const float*)d_in[9];
    const float* Wh = (const float*)d_in[10];
    const float* bh = (const float*)d_in[11];
    float* out = (float*)d_out;

    __half *pckT, *pskT, *pstT, *pFqN, *pGN, *pHv, *pHv2, *pA, *pWf, *pWg, *pWh;
    float *pS, *pMean, *pM2, *pbf, *pbg, *pCm, *pCr;
    cudaGetSymbolAddress((void**)&pckT, g_ckT);
    cudaGetSymbolAddress((void**)&pskT, g_skT);
    cudaGetSymbolAddress((void**)&pstT, g_stT);
    cudaGetSymbolAddress((void**)&pFqN, g_FqN);
    cudaGetSymbolAddress((void**)&pGN,  g_GN);
    cudaGetSymbolAddress((void**)&pHv,  g_HvT);
    cudaGetSymbolAddress((void**)&pHv2, g_Hv2T);
    cudaGetSymbolAddress((void**)&pA,   g_A);
    cudaGetSymbolAddress((void**)&pS,   g_S);
    cudaGetSymbolAddress((void**)&pMean, g_meanT);
    cudaGetSymbolAddress((void**)&pM2,  g_m2T);
    cudaGetSymbolAddress((void**)&pWf,  g_Wf);
    cudaGetSymbolAddress((void**)&pWg,  g_Wg);
    cudaGetSymbolAddress((void**)&pWh,  g_Wh);
    cudaGetSymbolAddress((void**)&pbf,  g_bf);
    cudaGetSymbolAddress((void**)&pbg,  g_bg);
    cudaGetSymbolAddress((void**)&pCm,  g_cmean);
    cudaGetSymbolAddress((void**)&pCr,  g_crstd);

    constexpr int SMEM_PRJ = (128 * SRS + 128 * SRS) * 2 * 2;  // 40960
    constexpr int SMEM_S   = (128 * SRS + 256 * SRS) * 2 * 2;  // 61440

    static bool attr_done = false;
    if (!attr_done) {
        cudaFuncSetAttribute(mma_gemmH<128, 256, 2, 0, false, float>,
                             cudaFuncAttributeMaxDynamicSharedMemorySize, SMEM_S);
        cudaFuncSetAttribute(mma_gemmH<128, 128, 4, 2, false, __half>,
                             cudaFuncAttributeMaxDynamicSharedMemorySize, SMEM_PRJ);
        cudaFuncSetAttribute(mma_gemmH<128, 128, 4, 1, true, __half>,
                             cudaFuncAttributeMaxDynamicSharedMemorySize, SMEM_PRJ);
        cudaFuncSetAttribute(mma_gemm_dualH,
                             cudaFuncAttributeMaxDynamicSharedMemorySize, DUAL_SMEM);
        attr_done = true;
    }

    const dim3 blk(256);

    // --- weight prep ---
    prep_w_kernel<<<(CKP * CKEY + 255) / 256, blk>>>(Wf, bf, pWf, pbf, CKEY, CKEY, CKP);
    prep_w_kernel<<<(CKP * CKEY + 255) / 256, blk>>>(Wg, bg, pWg, pbg, CKEY, CKEY, CKP);
    prep_w_kernel<<<(CIN * CIN + 255) / 256, blk>>>(Wh, nullptr, pWh, nullptr, CIN, CIN, CIN);

    // --- transpose inputs to token-major half ---
    transpose_in_kernel<CKEY><<<dim3(NTOK / 32, CKEY / 32, 2 * NB), blk>>>(
        ckey, pckT, skey, pskT);
    transpose_in_kernel<CIN><<<dim3(NTOK / 32, CIN / 32, NB), blk>>>(
        style, pstT, style, pstT);

    // --- projections (fp16 mma, fp32 accum) ---
    mma_gemmH<128, 128, 4, 2, false, __half><<<dim3(CKP / 128, NTOK / 128, NB), blk, SMEM_PRJ>>>(
        pckT, pWf, pbf, pFqN, nullptr, CKEY, CKEY, CKEY, CKEY, CKEY,
        (size_t)NTOK * CKEY, 0, (size_t)NTOK * CKEY);
    mma_gemmH<128, 128, 4, 2, false, __half><<<dim3(CKP / 128, NTOK / 128, NB), blk, SMEM_PRJ>>>(
        pskT, pWg, pbg, pGN, nullptr, CKEY, CKEY, CKEY, CKEY, CKEY,
        (size_t)NTOK * CKEY, 0, (size_t)NTOK * CKEY);
    mma_gemmH<128, 128, 4, 1, true, __half><<<dim3(NTOK / 128, CIN / 128, NB), blk, SMEM_PRJ>>>(
        pWh, pstT, bh, pHv, pHv2, NTOK, CIN, CIN, CIN, NTOK,
        0, (size_t)NTOK * CIN, (size_t)CIN * NTOK);

    // --- S = FqN @ GN^T (fp32 out) ---
    mma_gemmH<128, 256, 2, 0, false, float><<<dim3(NTOK / 256, NTOK / 128, NB), blk, SMEM_S>>>(
        pFqN, pGN, nullptr, pS, nullptr, NTOK, CKEY, CKEY, CKEY, NTOK,
        (size_t)NTOK * CKEY, (size_t)NTOK * CKEY, (size_t)NTOK * NTOK);

    // --- masked softmax: fp32 S -> half attn ---
    softmax_mask_kernel<<<dim3(NTOK, NB), blk>>>(pS, pA, cmask, smask);

    // --- fused mean/m2 ---
    mma_gemm_dualH<<<dim3(CIN / 128, NTOK / 128, NB), blk, DUAL_SMEM>>>(
        pA, pHv, pHv2, pMean, pM2);

    // --- mvn stats + final combine ---
    mvn_stats_kernel<<<dim3(CIN, NB), blk>>>(content, pCm, pCr);
    combine_kernel<<<dim3((NB * CIN * NTOK / 4) / 256), blk>>>(
        (const float4*)content, (const float4*)pMean, (const float4*)pM2,
        pCm, pCr, (float4*)out);
}

// round 9
// speedup vs baseline: 5.1449x; 1.0702x over previous
#include <cuda_runtime.h>
#include <cuda_fp16.h>
#include <cstdint>

// ---------------------------------------------------------------------------
// Problem constants
// ---------------------------------------------------------------------------
#define NB   4
#define CIN  256
#define CKEY 448
#define NTOK 4096
#define NEGV (-1e15f)
#define EPSV 1e-5f
#define CKP  512   // padded CKEY for projection N-dim

// ---------------------------------------------------------------------------
// Scratch (static device globals; no runtime allocation)
// ---------------------------------------------------------------------------
__device__ __half g_ckT [(size_t)NB * NTOK * CKEY];   // [b][N][Ck] ckey^T
__device__ __half g_skT [(size_t)NB * NTOK * CKEY];   // [b][N][Ck] skey^T
__device__ __half g_stT [(size_t)NB * NTOK * CIN];    // [b][N][C]  style^T
__device__ __half g_FqN [(size_t)NB * NTOK * CKEY];   // [b][N][Ck] f(ckey)
__device__ __half g_GN  [(size_t)NB * NTOK * CKEY];   // [b][N][Ck] g(skey)
__device__ __half g_HvT [(size_t)NB * CIN  * NTOK];   // [b][C][N]  h(style)
__device__ __half g_Hv2T[(size_t)NB * CIN  * NTOK];   // [b][C][N]  h(style)^2
__device__ float  g_S   [(size_t)NB * NTOK * NTOK];   // [b][N][N]  scores (fp32)
__device__ __half g_A   [(size_t)NB * NTOK * NTOK];   // [b][N][N]  attn (half)
__device__ float  g_meanT[(size_t)NB * CIN * NTOK];   // [b][C][N]
__device__ float  g_m2T [(size_t)NB * CIN  * NTOK];   // [b][C][N]
__device__ __half g_Wf  [CKP * CKEY];                 // rounded, zero-padded rows
__device__ __half g_Wg  [CKP * CKEY];
__device__ __half g_Wh  [CIN * CIN];
__device__ float  g_bf  [CKP];
__device__ float  g_bg  [CKP];
__device__ float  g_cmean[NB * CIN];
__device__ float  g_crstd[NB * CIN];

// ---------------------------------------------------------------------------
// Helpers
// ---------------------------------------------------------------------------
__device__ __forceinline__ uint32_t smem_u32(const void* p) {
    uint32_t a;
    asm("{ .reg .u64 t; cvta.to.shared.u64 t, %1; cvt.u32.u64 %0, t; }"
        : "=r"(a) : "l"(p));
    return a;
}
__device__ __forceinline__ void cp16(uint32_t s, const void* g) {
    asm volatile("cp.async.cg.shared.global [%0], [%1], 16;" :: "r"(s), "l"(g));
}
__device__ __forceinline__ void cp_commit() {
    asm volatile("cp.async.commit_group;" ::: "memory");
}
template <int N> __device__ __forceinline__ void cp_wait() {
    asm volatile("cp.async.wait_group %0;" :: "n"(N) : "memory");
}
__device__ __forceinline__ void mma_f16(float* d, const uint32_t* a, const uint32_t* b) {
    asm volatile(
        "mma.sync.aligned.m16n8k16.row.col.f32.f16.f16.f32 "
        "{%0,%1,%2,%3}, {%4,%5,%6,%7}, {%8,%9}, {%0,%1,%2,%3};"
        : "+f"(d[0]), "+f"(d[1]), "+f"(d[2]), "+f"(d[3])
        : "r"(a[0]), "r"(a[1]), "r"(a[2]), "r"(a[3]), "r"(b[0]), "r"(b[1]));
}
__device__ __forceinline__ void ldsm_x4(uint32_t* r, uint32_t a) {
    asm volatile("ldmatrix.sync.aligned.m8n8.x4.shared.b16 {%0,%1,%2,%3}, [%4];"
        : "=r"(r[0]), "=r"(r[1]), "=r"(r[2]), "=r"(r[3]) : "r"(a));
}
__device__ __forceinline__ void ldsm_x2(uint32_t* r, uint32_t a) {
    asm volatile("ldmatrix.sync.aligned.m8n8.x2.shared.b16 {%0,%1}, [%2];"
        : "=r"(r[0]), "=r"(r[1]) : "r"(a));
}

// smem row stride: 40 halves (80 B) — conflict-free for LDSM (8 consecutive
// rows hit 8 distinct 16B chunks mod 128B) and for cp.async stores.
#define SRS 40

// ---------------------------------------------------------------------------
// Generic FP16 mma.sync GEMM:  C[M][N] = A[M][K] * B[N][K]^T   (fp32 accum)
//   256 threads / 2 CTAs per SM (reg-capped at 128), BK=32 halves,
//   double-buffered cp.async, ldmatrix fragment loads.
//   Warp grid WMW x (8/WMW); warp tile (BM/WMW) x (BN*WMW/8).
//   BIAS_MODE: 0 none, 1 along M, 2 along N (bias fp32)
//   SQ: also write C2 = rn(h*h), h = rn(C)  (CT == __half)
//   CT: output type (float or __half). Store guard: col < Nrt.
// ---------------------------------------------------------------------------
template <int BM, int BN, int WMW, int BIAS_MODE, bool SQ, typename CT>
__global__ __launch_bounds__(256, 2) void mma_gemmH(
    const __half* __restrict__ A, const __half* __restrict__ B,
    const float* __restrict__ bias,
    CT* __restrict__ C, CT* __restrict__ C2,
    int Nrt, int K, int lda, int ldb, int ldc,
    size_t sA, size_t sB, size_t sC)
{
    constexpr int WNW = 8 / WMW;
    constexpr int WTM = BM / WMW;
    constexpr int WTN = BN / WNW;
    constexpr int MI  = WTM / 16;
    constexpr int NI  = WTN / 8;
    constexpr int ASZ = BM * SRS;          // halves
    constexpr int BSZ = BN * SRS;
    constexpr int STG = ASZ + BSZ;
    constexpr int ACH = BM * 4 / 256;      // cp16 chunks per thread (A)
    constexpr int BCH = BN * 4 / 256;

    extern __shared__ __half smh[];
    const uint32_t sbase = smem_u32(smh);

    const int tid = threadIdx.x, lane = tid & 31, wid = tid >> 5;
    const int wM = wid % WMW, wN = wid / WMW;
    const int m0 = blockIdx.y * BM, n0 = blockIdx.x * BN, b = blockIdx.z;

    A += (size_t)b * sA + (size_t)m0 * lda;
    B += (size_t)b * sB + (size_t)n0 * ldb;
    C += (size_t)b * sC;
    if (SQ) C2 += (size_t)b * sC;

    float acc[MI][NI][4];
#pragma unroll
    for (int mi = 0; mi < MI; mi++)
#pragma unroll
        for (int ni = 0; ni < NI; ni++)
#pragma unroll
            for (int q = 0; q < 4; q++) acc[mi][ni][q] = 0.f;

    const int NK = K >> 5;   // 32 halves per k-block

    {
#pragma unroll
        for (int v = 0; v < ACH; v++) {
            int t = tid + v * 256, r = t >> 2, ch = t & 3;
            cp16(sbase + (uint32_t)(r * SRS + ch * 8) * 2, A + (size_t)r * lda + ch * 8);
        }
#pragma unroll
        for (int v = 0; v < BCH; v++) {
            int t = tid + v * 256, r = t >> 2, ch = t & 3;
            cp16(sbase + (uint32_t)(ASZ + r * SRS + ch * 8) * 2, B + (size_t)r * ldb + ch * 8);
        }
        cp_commit();
    }

    const int g = lane >> 2, tq = lane & 3;
    // ldmatrix per-lane offsets (bytes)
    const uint32_t aoff = (uint32_t)((lane & 15) * SRS + (lane >> 4) * 8) * 2;
    const uint32_t boff = (uint32_t)((lane & 7) * SRS + ((lane >> 3) & 1) * 8) * 2;

    for (int i = 0; i < NK; i++) {
        if (i + 1 < NK) {
            const int st = (i + 1) & 1;
            const int k0 = (i + 1) << 5;
#pragma unroll
            for (int v = 0; v < ACH; v++) {
                int t = tid + v * 256, r = t >> 2, ch = t & 3;
                cp16(sbase + (uint32_t)(st * STG + r * SRS + ch * 8) * 2,
                     A + (size_t)r * lda + k0 + ch * 8);
            }
#pragma unroll
            for (int v = 0; v < BCH; v++) {
                int t = tid + v * 256, r = t >> 2, ch = t & 3;
                cp16(sbase + (uint32_t)(st * STG + ASZ + r * SRS + ch * 8) * 2,
                     B + (size_t)r * ldb + k0 + ch * 8);
            }
            cp_commit();
            cp_wait<1>();
        } else {
            cp_wait<0>();
        }
        __syncthreads();

        const uint32_t stg_b = sbase + (uint32_t)((i & 1) * STG) * 2;
        const uint32_t bstg_b = stg_b + (uint32_t)ASZ * 2;

#pragma unroll
        for (int kk = 0; kk < 2; kk++) {
            const uint32_t kh = kk * 16 * 2;   // byte offset within row
            uint32_t af[MI][4], bf[NI][2];
#pragma unroll
            for (int mi = 0; mi < MI; mi++)
                ldsm_x4(af[mi], stg_b + (uint32_t)((wM * WTM + mi * 16) * SRS) * 2 + kh + aoff);
#pragma unroll
            for (int ni = 0; ni < NI; ni++)
                ldsm_x2(bf[ni], bstg_b + (uint32_t)((wN * WTN + ni * 8) * SRS) * 2 + kh + boff);
#pragma unroll
            for (int mi = 0; mi < MI; mi++)
#pragma unroll
                for (int ni = 0; ni < NI; ni++)
                    mma_f16(acc[mi][ni], af[mi], bf[ni]);
        }
        __syncthreads();
    }

    // ---- epilogue ----
#pragma unroll
    for (int mi = 0; mi < MI; mi++) {
        const int row0 = m0 + wM * WTM + mi * 16 + g;
        float bm0 = 0.f, bm1 = 0.f;
        if (BIAS_MODE == 1) { bm0 = bias[row0]; bm1 = bias[row0 + 8]; }
#pragma unroll
        for (int ni = 0; ni < NI; ni++) {
            const int col = n0 + wN * WTN + ni * 8 + tq * 2;
            if (col >= Nrt) continue;
            float o0 = acc[mi][ni][0], o1 = acc[mi][ni][1];
            float o2 = acc[mi][ni][2], o3 = acc[mi][ni][3];
            if (BIAS_MODE == 1) { o0 += bm0; o1 += bm0; o2 += bm1; o3 += bm1; }
            if (BIAS_MODE == 2) {
                float bn0 = bias[col], bn1 = bias[col + 1];
                o0 += bn0; o1 += bn1; o2 += bn0; o3 += bn1;
            }
            if (sizeof(CT) == 4) {
                float* Cf = reinterpret_cast<float*>(C);
                *reinterpret_cast<float2*>(&Cf[(size_t)row0 * ldc + col])       = make_float2(o0, o1);
                *reinterpret_cast<float2*>(&Cf[(size_t)(row0 + 8) * ldc + col]) = make_float2(o2, o3);
            } else {
                __half* Ch = reinterpret_cast<__half*>(C);
                __half h0 = __float2half_rn(o0), h1 = __float2half_rn(o1);
                __half h2 = __float2half_rn(o2), h3 = __float2half_rn(o3);
                *reinterpret_cast<__half2*>(&Ch[(size_t)row0 * ldc + col])       = __halves2half2(h0, h1);
                *reinterpret_cast<__half2*>(&Ch[(size_t)(row0 + 8) * ldc + col]) = __halves2half2(h2, h3);
                if (SQ) {
                    __half* C2h = reinterpret_cast<__half*>(C2);
                    float f0 = __half2float(h0), f1 = __half2float(h1);
                    float f2 = __half2float(h2), f3 = __half2float(h3);
                    __half q0 = __float2half_rn(f0 * f0), q1 = __float2half_rn(f1 * f1);
                    __half q2 = __float2half_rn(f2 * f2), q3 = __float2half_rn(f3 * f3);
                    *reinterpret_cast<__half2*>(&C2h[(size_t)row0 * ldc + col])       = __halves2half2(q0, q1);
                    *reinterpret_cast<__half2*>(&C2h[(size_t)(row0 + 8) * ldc + col]) = __halves2half2(q2, q3);
                }
            }
        }
    }
}

// ---------------------------------------------------------------------------
// Dual-B fused FP16 GEMM for mean & m2 (shares attn A tiles), ldmatrix loads:
//   C1[n][c] = A[n][:] . B1[c][:],  C2[n][c] = A[n][:] . B2[c][:]
//   BM=128 (tokens), BN=64 (channels), warps 4x2 -> warp tile 32x32.
//   2 CTAs/SM. fp32 accumulate; transposed fp32 store: out[c][n].
// ---------------------------------------------------------------------------
#define DUAL_SMEM ((128 * SRS + 2 * 64 * SRS) * 2 * 2)
__global__ __launch_bounds__(256, 2) void mma_gemm_dualH(
    const __half* __restrict__ A, const __half* __restrict__ B1,
    const __half* __restrict__ B2,
    float* __restrict__ C1, float* __restrict__ C2)
{
    constexpr int BM = 128, BN = 64;
    constexpr int ASZ = BM * SRS, BSZ = BN * SRS;
    constexpr int STG = ASZ + 2 * BSZ;

    extern __shared__ __half smh[];
    const uint32_t sbase = smem_u32(smh);

    const int tid = threadIdx.x, lane = tid & 31, wid = tid >> 5;
    const int wM = wid & 3, wN = wid >> 2;
    const int m0 = blockIdx.y * BM, n0 = blockIdx.x * BN, b = blockIdx.z;

    A  += (size_t)b * NTOK * NTOK + (size_t)m0 * NTOK;
    B1 += (size_t)b * CIN * NTOK + (size_t)n0 * NTOK;
    B2 += (size_t)b * CIN * NTOK + (size_t)n0 * NTOK;
    C1 += (size_t)b * CIN * NTOK;
    C2 += (size_t)b * CIN * NTOK;

    float acc1[2][4][4], acc2[2][4][4];
#pragma unroll
    for (int mi = 0; mi < 2; mi++)
#pragma unroll
        for (int ni = 0; ni < 4; ni++)
#pragma unroll
            for (int q = 0; q < 4; q++) { acc1[mi][ni][q] = 0.f; acc2[mi][ni][q] = 0.f; }

    const int NK = NTOK >> 5;

    {
#pragma unroll
        for (int v = 0; v < 2; v++) {
            int t = tid + v * 256, r = t >> 2, ch = t & 3;
            cp16(sbase + (uint32_t)(r * SRS + ch * 8) * 2, A + (size_t)r * NTOK + ch * 8);
        }
        {
            int r = tid >> 2, ch = tid & 3;
            cp16(sbase + (uint32_t)(ASZ + r * SRS + ch * 8) * 2, B1 + (size_t)r * NTOK + ch * 8);
            cp16(sbase + (uint32_t)(ASZ + BSZ + r * SRS + ch * 8) * 2, B2 + (size_t)r * NTOK + ch * 8);
        }
        cp_commit();
    }

    const int g = lane >> 2, tq = lane & 3;
    const uint32_t aoff = (uint32_t)((lane & 15) * SRS + (lane >> 4) * 8) * 2;
    const uint32_t boff = (uint32_t)((lane & 7) * SRS + ((lane >> 3) & 1) * 8) * 2;

    for (int i = 0; i < NK; i++) {
        if (i + 1 < NK) {
            const int st = (i + 1) & 1;
            const int k0 = (i + 1) << 5;
#pragma unroll
            for (int v = 0; v < 2; v++) {
                int t = tid + v * 256, r = t >> 2, ch = t & 3;
                cp16(sbase + (uint32_t)(st * STG + r * SRS + ch * 8) * 2,
                     A + (size_t)r * NTOK + k0 + ch * 8);
            }
            {
                int r = tid >> 2, ch = tid & 3;
                cp16(sbase + (uint32_t)(st * STG + ASZ + r * SRS + ch * 8) * 2,
                     B1 + (size_t)r * NTOK + k0 + ch * 8);
                cp16(sbase + (uint32_t)(st * STG + ASZ + BSZ + r * SRS + ch * 8) * 2,
                     B2 + (size_t)r * NTOK + k0 + ch * 8);
            }
            cp_commit();
            cp_wait<1>();
        } else {
            cp_wait<0>();
        }
        __syncthreads();

        const uint32_t stg_b = sbase + (uint32_t)((i & 1) * STG) * 2;
        const uint32_t b1stg = stg_b + (uint32_t)ASZ * 2;
        const uint32_t b2stg = b1stg + (uint32_t)BSZ * 2;

#pragma unroll
        for (int kk = 0; kk < 2; kk++) {
            const uint32_t kh = kk * 16 * 2;
            uint32_t af[2][4], bf1[4][2], bf2[4][2];
#pragma unroll
            for (int mi = 0; mi < 2; mi++)
                ldsm_x4(af[mi], stg_b + (uint32_t)((wM * 32 + mi * 16) * SRS) * 2 + kh + aoff);
#pragma unroll
            for (int ni = 0; ni < 4; ni++) {
                ldsm_x2(bf1[ni], b1stg + (uint32_t)((wN * 32 + ni * 8) * SRS) * 2 + kh + boff);
                ldsm_x2(bf2[ni], b2stg + (uint32_t)((wN * 32 + ni * 8) * SRS) * 2 + kh + boff);
            }
#pragma unroll
            for (int mi = 0; mi < 2; mi++)
#pragma unroll
                for (int ni = 0; ni < 4; ni++) {
                    mma_f16(acc1[mi][ni], af[mi], bf1[ni]);
                    mma_f16(acc2[mi][ni], af[mi], bf2[ni]);
                }
        }
        __syncthreads();
    }

#pragma unroll
    for (int mi = 0; mi < 2; mi++) {
        const int row0 = m0 + wM * 32 + mi * 16 + g;
#pragma unroll
        for (int ni = 0; ni < 4; ni++) {
            const int col = n0 + wN * 32 + ni * 8 + tq * 2;
            C1[(size_t)col * NTOK + row0]           = acc1[mi][ni][0];
            C1[(size_t)(col + 1) * NTOK + row0]     = acc1[mi][ni][1];
            C1[(size_t)col * NTOK + row0 + 8]       = acc1[mi][ni][2];
            C1[(size_t)(col + 1) * NTOK + row0 + 8] = acc1[mi][ni][3];
            C2[(size_t)col * NTOK + row0]           = acc2[mi][ni][0];
            C2[(size_t)(col + 1) * NTOK + row0]     = acc2[mi][ni][1];
            C2[(size_t)col * NTOK + row0 + 8]       = acc2[mi][ni][2];
            C2[(size_t)(col + 1) * NTOK + row0 + 8] = acc2[mi][ni][3];
        }
    }
}

// ---------------------------------------------------------------------------
// Weight prep: round W to half, pad rows to dstRows with zeros; pad bias (f32).
// ---------------------------------------------------------------------------
__global__ void prep_w_kernel(const float* __restrict__ W, const float* __restrict__ bias,
                              __half* __restrict__ Wd, float* __restrict__ bd,
                              int rows, int cols, int dstRows)
{
    int i = blockIdx.x * 256 + threadIdx.x;
    int total = dstRows * cols;
    if (i < total) {
        int r = i / cols;
        Wd[i] = (r < rows) ? __float2half_rn(W[i]) : __float2half_rn(0.f);
    }
    if (bd && i < dstRows) bd[i] = (i < rows) ? bias[i] : 0.f;
}

// ---------------------------------------------------------------------------
// Transpose [C][N] fp32 -> [N][C] half. Two tensors via z split.
// ---------------------------------------------------------------------------
template <int C>
__global__ __launch_bounds__(256) void transpose_in_kernel(
    const float* __restrict__ in0, __half* __restrict__ out0,
    const float* __restrict__ in1, __half* __restrict__ out1)
{
    __shared__ float t[32][33];
    const int z = blockIdx.z;
    const int b = z & (NB - 1);
    const float* in = (z < NB) ? in0 : in1;
    __half* out = (z < NB) ? out0 : out1;
    in  += (size_t)b * C * NTOK;
    out += (size_t)b * NTOK * C;

    const int x0 = blockIdx.x * 32;   // token
    const int y0 = blockIdx.y * 32;   // channel
    const int tx = threadIdx.x & 31, ty = threadIdx.x >> 5;

#pragma unroll
    for (int i = 0; i < 4; i++)
        t[ty + i * 8][tx] = in[(size_t)(y0 + ty + i * 8) * NTOK + x0 + tx];
    __syncthreads();
#pragma unroll
    for (int i = 0; i < 4; i++)
        out[(size_t)(x0 + ty + i * 8) * C + y0 + tx] = __float2half_rn(t[tx][ty + i * 8]);
}

// ---------------------------------------------------------------------------
// Reductions / softmax / stats / combine
// ---------------------------------------------------------------------------
__device__ __forceinline__ float warpMax(float v) {
#pragma unroll
    for (int o = 16; o; o >>= 1) v = fmaxf(v, __shfl_xor_sync(0xffffffffu, v, o));
    return v;
}
__device__ __forceinline__ float warpSum(float v) {
#pragma unroll
    for (int o = 16; o; o >>= 1) v += __shfl_xor_sync(0xffffffffu, v, o);
    return v;
}

// reads fp32 S, writes half attn
__global__ __launch_bounds__(256) void softmax_mask_kernel(
    const float* __restrict__ S, __half* __restrict__ Aout,
    const int* __restrict__ cmask, const int* __restrict__ smask)
{
    const int n = blockIdx.x, b = blockIdx.y;
    const float* row = S + ((size_t)b * NTOK + n) * NTOK;
    __half* arow = Aout + ((size_t)b * NTOK + n) * NTOK;
    const int* sm = smask + (size_t)b * NTOK;
    const bool cmn = (cmask[(size_t)b * NTOK + n] != 0);
    const int tid = threadIdx.x;
    __shared__ float red[8];

    float v[16];
    float mx = -INFINITY;
#pragma unroll
    for (int i = 0; i < 16; i++) {
        int m = tid + i * 256;
        float s = row[m];
        if (cmn && sm[m] == 0) s = NEGV;
        v[i] = s;
        mx = fmaxf(mx, s);
    }
    mx = warpMax(mx);
    if ((tid & 31) == 0) red[tid >> 5] = mx;
    __syncthreads();
    if (tid < 32) {
        float x = (tid < 8) ? red[tid] : -INFINITY;
        x = warpMax(x);
        if (tid == 0) red[0] = x;
    }
    __syncthreads();
    mx = red[0];
    __syncthreads();

    float sum = 0.f;
#pragma unroll
    for (int i = 0; i < 16; i++) { v[i] = __expf(v[i] - mx); sum += v[i]; }
    sum = warpSum(sum);
    if ((tid & 31) == 0) red[tid >> 5] = sum;
    __syncthreads();
    if (tid < 32) {
        float x = (tid < 8) ? red[tid] : 0.f;
        x = warpSum(x);
        if (tid == 0) red[0] = x;
    }
    __syncthreads();
    const float inv = 1.f / red[0];
#pragma unroll
    for (int i = 0; i < 16; i++)
        arow[tid + i * 256] = __float2half_rn(v[i] * inv);
}

__global__ __launch_bounds__(256) void mvn_stats_kernel(
    const float* __restrict__ content,
    float* __restrict__ cmean, float* __restrict__ crstd)
{
    const int c = blockIdx.x, b = blockIdx.y;
    const float* p = content + ((size_t)b * CIN + c) * NTOK;
    const int tid = threadIdx.x;
    float s = 0.f, ss = 0.f;
#pragma unroll
    for (int i = 0; i < 16; i++) {
        float x = p[tid + i * 256];
        s += x; ss += x * x;
    }
    __shared__ float shs[8], shss[8];
    s = warpSum(s); ss = warpSum(ss);
    if ((tid & 31) == 0) { shs[tid >> 5] = s; shss[tid >> 5] = ss; }
    __syncthreads();
    if (tid == 0) {
        float S = 0.f, SS = 0.f;
#pragma unroll
        for (int i = 0; i < 8; i++) { S += shs[i]; SS += shss[i]; }
        float mean = S / (float)NTOK;
        float var = (SS - S * S / (float)NTOK) / (float)(NTOK - 1);
        cmean[b * CIN + c] = mean;
        crstd[b * CIN + c] = rsqrtf(var + EPSV);
    }
}

__global__ __launch_bounds__(256) void combine_kernel(
    const float4* __restrict__ content,
    const float4* __restrict__ meanT,
    const float4* __restrict__ m2T,
    const float* __restrict__ cmean,
    const float* __restrict__ crstd,
    float4* __restrict__ out)
{
    const int gid = blockIdx.x * 256 + threadIdx.x;
    const int bc = gid >> 10;
    const float mu = cmean[bc];
    const float rs = crstd[bc];
    float4 mn = meanT[gid];
    float4 m2 = m2T[gid];
    float4 ct = content[gid];
    float4 o;
    o.x = sqrtf(fmaxf(m2.x - mn.x * mn.x, 0.f)) * ((ct.x - mu) * rs) + mn.x;
    o.y = sqrtf(fmaxf(m2.y - mn.y * mn.y, 0.f)) * ((ct.y - mu) * rs) + mn.y;
    o.z = sqrtf(fmaxf(m2.z - mn.z * mn.z, 0.f)) * ((ct.z - mu) * rs) + mn.z;
    o.w = sqrtf(fmaxf(m2.w - mn.w * mn.w, 0.f)) * ((ct.w - mu) * rs) + mn.w;
    out[gid] = o;
}

// ---------------------------------------------------------------------------
// Launch
// ---------------------------------------------------------------------------
extern "C" void kernel_launch(void* const* d_in, const int* in_sizes, int n_in,
                              void* d_out, int out_size)
{
    const float* content = (const float*)d_in[0];
    const float* style   = (const float*)d_in[1];
    const float* ckey    = (const float*)d_in[2];
    const float* skey    = (const float*)d_in[3];
    const int*   cmask   = (const int*)  d_in[4];
    const int*   smask   = (const int*)  d_in[5];
    const float* Wf = (const float*)d_in[6];
    const float* bf = (const float*)d_in[7];
    const float* Wg = (const float*)d_in[8];
    const float* bg = (const float*)d_in[9];
    const float* Wh = (const float*)d_in[10];
    const float* bh = (const float*)d_in[11];
    float* out = (float*)d_out;

    __half *pckT, *pskT, *pstT, *pFqN, *pGN, *pHv, *pHv2, *pA, *pWf, *pWg, *pWh;
    float *pS, *pMean, *pM2, *pbf, *pbg, *pCm, *pCr;
    cudaGetSymbolAddress((void**)&pckT, g_ckT);
    cudaGetSymbolAddress((void**)&pskT, g_skT);
    cudaGetSymbolAddress((void**)&pstT, g_stT);
    cudaGetSymbolAddress((void**)&pFqN, g_FqN);
    cudaGetSymbolAddress((void**)&pGN,  g_GN);
    cudaGetSymbolAddress((void**)&pHv,  g_HvT);
    cudaGetSymbolAddress((void**)&pHv2, g_Hv2T);
    cudaGetSymbolAddress((void**)&pA,   g_A);
    cudaGetSymbolAddress((void**)&pS,   g_S);
    cudaGetSymbolAddress((void**)&pMean, g_meanT);
    cudaGetSymbolAddress((void**)&pM2,  g_m2T);
    cudaGetSymbolAddress((void**)&pWf,  g_Wf);
    cudaGetSymbolAddress((void**)&pWg,  g_Wg);
    cudaGetSymbolAddress((void**)&pWh,  g_Wh);
    cudaGetSymbolAddress((void**)&pbf,  g_bf);
    cudaGetSymbolAddress((void**)&pbg,  g_bg);
    cudaGetSymbolAddress((void**)&pCm,  g_cmean);
    cudaGetSymbolAddress((void**)&pCr,  g_crstd);

    constexpr int SMEM_STD = (128 * SRS + 128 * SRS) * 2 * 2;  // 40960

    static bool attr_done = false;
    if (!attr_done) {
        cudaFuncSetAttribute(mma_gemmH<128, 128, 4, 0, false, float>,
                             cudaFuncAttributeMaxDynamicSharedMemorySize, SMEM_STD);
        cudaFuncSetAttribute(mma_gemmH<128, 128, 4, 2, false, __half>,
                             cudaFuncAttributeMaxDynamicSharedMemorySize, SMEM_STD);
        cudaFuncSetAttribute(mma_gemmH<128, 128, 4, 1, true, __half>,
                             cudaFuncAttributeMaxDynamicSharedMemorySize, SMEM_STD);
        cudaFuncSetAttribute(mma_gemm_dualH,
                             cudaFuncAttributeMaxDynamicSharedMemorySize, DUAL_SMEM);
        attr_done = true;
    }

    const dim3 blk(256);

    // --- weight prep ---
    prep_w_kernel<<<(CKP * CKEY + 255) / 256, blk>>>(Wf, bf, pWf, pbf, CKEY, CKEY, CKP);
    prep_w_kernel<<<(CKP * CKEY + 255) / 256, blk>>>(Wg, bg, pWg, pbg, CKEY, CKEY, CKP);
    prep_w_kernel<<<(CIN * CIN + 255) / 256, blk>>>(Wh, nullptr, pWh, nullptr, CIN, CIN, CIN);

    // --- transpose inputs to token-major half ---
    transpose_in_kernel<CKEY><<<dim3(NTOK / 32, CKEY / 32, 2 * NB), blk>>>(
        ckey, pckT, skey, pskT);
    transpose_in_kernel<CIN><<<dim3(NTOK / 32, CIN / 32, NB), blk>>>(
        style, pstT, style, pstT);

    // --- projections (fp16 mma, fp32 accum) ---
    mma_gemmH<128, 128, 4, 2, false, __half><<<dim3(CKP / 128, NTOK / 128, NB), blk, SMEM_STD>>>(
        pckT, pWf, pbf, pFqN, nullptr, CKEY, CKEY, CKEY, CKEY, CKEY,
        (size_t)NTOK * CKEY, 0, (size_t)NTOK * CKEY);
    mma_gemmH<128, 128, 4, 2, false, __half><<<dim3(CKP / 128, NTOK / 128, NB), blk, SMEM_STD>>>(
        pskT, pWg, pbg, pGN, nullptr, CKEY, CKEY, CKEY, CKEY, CKEY,
        (size_t)NTOK * CKEY, 0, (size_t)NTOK * CKEY);
    mma_gemmH<128, 128, 4, 1, true, __half><<<dim3(NTOK / 128, CIN / 128, NB), blk, SMEM_STD>>>(
        pWh, pstT, bh, pHv, pHv2, NTOK, CIN, CIN, CIN, NTOK,
        0, (size_t)NTOK * CIN, (size_t)CIN * NTOK);

    // --- S = FqN @ GN^T (fp32 out) ---
    mma_gemmH<128, 128, 4, 0, false, float><<<dim3(NTOK / 128, NTOK / 128, NB), blk, SMEM_STD>>>(
        pFqN, pGN, nullptr, pS, nullptr, NTOK, CKEY, CKEY, CKEY, NTOK,
        (size_t)NTOK * CKEY, (size_t)NTOK * CKEY, (size_t)NTOK * NTOK);

    // --- masked softmax: fp32 S -> half attn ---
    softmax_mask_kernel<<<dim3(NTOK, NB), blk>>>(pS, pA, cmask, smask);

    // --- fused mean/m2 ---
    mma_gemm_dualH<<<dim3(CIN / 64, NTOK / 128, NB), blk, DUAL_SMEM>>>(
        pA, pHv, pHv2, pMean, pM2);

    // --- mvn stats + final combine ---
    mvn_stats_kernel<<<dim3(CIN, NB), blk>>>(content, pCm, pCr);
    combine_kernel<<<dim3((NB * CIN * NTOK / 4) / 256), blk>>>(
        (const float4*)content, (const float4*)pMean, (const float4*)pM2,
        pCm, pCr, (float4*)out);
}

// round 10
// speedup vs baseline: 5.6521x; 1.0986x over previous
#include <cuda_runtime.h>
#include <cuda_fp16.h>
#include <cstdint>

// ---------------------------------------------------------------------------
// Problem constants
// ---------------------------------------------------------------------------
#define NB   4
#define CIN  256
#define CKEY 448
#define NTOK 4096
#define NEGV (-1e15f)
#define EPSV 1e-5f
#define CKP  512   // padded CKEY for projection N-dim

// ---------------------------------------------------------------------------
// Scratch (static device globals; no runtime allocation)
// ---------------------------------------------------------------------------
__device__ __half g_ckT [(size_t)NB * NTOK * CKEY];   // [b][N][Ck] ckey^T
__device__ __half g_skT [(size_t)NB * NTOK * CKEY];   // [b][N][Ck] skey^T
__device__ __half g_stT [(size_t)NB * NTOK * CIN];    // [b][N][C]  style^T
__device__ __half g_FqN [(size_t)NB * NTOK * CKEY];   // [b][N][Ck] f(ckey)
__device__ __half g_GN  [(size_t)NB * NTOK * CKEY];   // [b][N][Ck] g(skey)
__device__ __half g_HvT [(size_t)NB * CIN  * NTOK];   // [b][C][N]  h(style)
__device__ __half g_Hv2T[(size_t)NB * CIN  * NTOK];   // [b][C][N]  h(style)^2
__device__ float  g_S   [(size_t)NB * NTOK * NTOK];   // [b][N][N]  scores (fp32)
__device__ __half g_A   [(size_t)NB * NTOK * NTOK];   // [b][N][N]  attn (half)
__device__ float  g_meanT[(size_t)NB * CIN * NTOK];   // [b][C][N]
__device__ float  g_m2T [(size_t)NB * CIN  * NTOK];   // [b][C][N]
__device__ __half g_Wf  [CKP * CKEY];                 // rounded, zero-padded rows
__device__ __half g_Wg  [CKP * CKEY];
__device__ __half g_Wh  [CIN * CIN];
__device__ float  g_bf  [CKP];
__device__ float  g_bg  [CKP];
__device__ float  g_cmean[NB * CIN];
__device__ float  g_crstd[NB * CIN];

// ---------------------------------------------------------------------------
// Helpers
// ---------------------------------------------------------------------------
__device__ __forceinline__ uint32_t smem_u32(const void* p) {
    uint32_t a;
    asm("{ .reg .u64 t; cvta.to.shared.u64 t, %1; cvt.u32.u64 %0, t; }"
        : "=r"(a) : "l"(p));
    return a;
}
__device__ __forceinline__ void cp16(uint32_t s, const void* g) {
    asm volatile("cp.async.cg.shared.global [%0], [%1], 16;" :: "r"(s), "l"(g));
}
__device__ __forceinline__ void cp_commit() {
    asm volatile("cp.async.commit_group;" ::: "memory");
}
template <int N> __device__ __forceinline__ void cp_wait() {
    asm volatile("cp.async.wait_group %0;" :: "n"(N) : "memory");
}
__device__ __forceinline__ void mma_f16(float* d, const uint32_t* a, const uint32_t* b) {
    asm volatile(
        "mma.sync.aligned.m16n8k16.row.col.f32.f16.f16.f32 "
        "{%0,%1,%2,%3}, {%4,%5,%6,%7}, {%8,%9}, {%0,%1,%2,%3};"
        : "+f"(d[0]), "+f"(d[1]), "+f"(d[2]), "+f"(d[3])
        : "r"(a[0]), "r"(a[1]), "r"(a[2]), "r"(a[3]), "r"(b[0]), "r"(b[1]));
}
__device__ __forceinline__ void ldsm_x4(uint32_t* r, uint32_t a) {
    asm volatile("ldmatrix.sync.aligned.m8n8.x4.shared.b16 {%0,%1,%2,%3}, [%4];"
        : "=r"(r[0]), "=r"(r[1]), "=r"(r[2]), "=r"(r[3]) : "r"(a));
}
__device__ __forceinline__ void ldsm_x2(uint32_t* r, uint32_t a) {
    asm volatile("ldmatrix.sync.aligned.m8n8.x2.shared.b16 {%0,%1}, [%2];"
        : "=r"(r[0]), "=r"(r[1]) : "r"(a));
}

// BK = 64 halves per k-block. smem row stride: 72 halves (144 B).
// LDSM conflict check: chunk index (r*144/16) mod 8 = 9r mod 8 -> 8 distinct.
#define SRS 72

// ---------------------------------------------------------------------------
// Generic FP16 mma.sync GEMM:  C[M][N] = A[M][K] * B[N][K]^T   (fp32 accum)
//   256 threads / 2 CTAs per SM (reg-capped), BK=64 halves,
//   double-buffered cp.async, ldmatrix fragment loads.
//   Warp grid WMW x (8/WMW); warp tile (BM/WMW) x (BN*WMW/8).
//   BIAS_MODE: 0 none, 1 along M, 2 along N (bias fp32)
//   SQ: also write C2 = rn(h*h), h = rn(C)  (CT == __half)
//   CT: output type (float or __half). Store guard: col < Nrt.
//   K must be a multiple of 64.
// ---------------------------------------------------------------------------
template <int BM, int BN, int WMW, int BIAS_MODE, bool SQ, typename CT>
__global__ __launch_bounds__(256, 2) void mma_gemmH(
    const __half* __restrict__ A, const __half* __restrict__ B,
    const float* __restrict__ bias,
    CT* __restrict__ C, CT* __restrict__ C2,
    int Nrt, int K, int lda, int ldb, int ldc,
    size_t sA, size_t sB, size_t sC)
{
    constexpr int WNW = 8 / WMW;
    constexpr int WTM = BM / WMW;
    constexpr int WTN = BN / WNW;
    constexpr int MI  = WTM / 16;
    constexpr int NI  = WTN / 8;
    constexpr int ASZ = BM * SRS;          // halves
    constexpr int BSZ = BN * SRS;
    constexpr int STG = ASZ + BSZ;
    constexpr int ACH = BM * 8 / 256;      // cp16 chunks per thread (A), 8 per row
    constexpr int BCH = BN * 8 / 256;

    extern __shared__ __half smh[];
    const uint32_t sbase = smem_u32(smh);

    const int tid = threadIdx.x, lane = tid & 31, wid = tid >> 5;
    const int wM = wid % WMW, wN = wid / WMW;
    const int m0 = blockIdx.y * BM, n0 = blockIdx.x * BN, b = blockIdx.z;

    A += (size_t)b * sA + (size_t)m0 * lda;
    B += (size_t)b * sB + (size_t)n0 * ldb;
    C += (size_t)b * sC;
    if (SQ) C2 += (size_t)b * sC;

    float acc[MI][NI][4];
#pragma unroll
    for (int mi = 0; mi < MI; mi++)
#pragma unroll
        for (int ni = 0; ni < NI; ni++)
#pragma unroll
            for (int q = 0; q < 4; q++) acc[mi][ni][q] = 0.f;

    const int NK = K >> 6;   // 64 halves per k-block

    {
#pragma unroll
        for (int v = 0; v < ACH; v++) {
            int t = tid + v * 256, r = t >> 3, ch = t & 7;
            cp16(sbase + (uint32_t)(r * SRS + ch * 8) * 2, A + (size_t)r * lda + ch * 8);
        }
#pragma unroll
        for (int v = 0; v < BCH; v++) {
            int t = tid + v * 256, r = t >> 3, ch = t & 7;
            cp16(sbase + (uint32_t)(ASZ + r * SRS + ch * 8) * 2, B + (size_t)r * ldb + ch * 8);
        }
        cp_commit();
    }

    const int g = lane >> 2, tq = lane & 3;
    // ldmatrix per-lane offsets (bytes)
    const uint32_t aoff = (uint32_t)((lane & 15) * SRS + (lane >> 4) * 8) * 2;
    const uint32_t boff = (uint32_t)((lane & 7) * SRS + ((lane >> 3) & 1) * 8) * 2;

    for (int i = 0; i < NK; i++) {
        if (i + 1 < NK) {
            const int st = (i + 1) & 1;
            const int k0 = (i + 1) << 6;
#pragma unroll
            for (int v = 0; v < ACH; v++) {
                int t = tid + v * 256, r = t >> 3, ch = t & 7;
                cp16(sbase + (uint32_t)(st * STG + r * SRS + ch * 8) * 2,
                     A + (size_t)r * lda + k0 + ch * 8);
            }
#pragma unroll
            for (int v = 0; v < BCH; v++) {
                int t = tid + v * 256, r = t >> 3, ch = t & 7;
                cp16(sbase + (uint32_t)(st * STG + ASZ + r * SRS + ch * 8) * 2,
                     B + (size_t)r * ldb + k0 + ch * 8);
            }
            cp_commit();
            cp_wait<1>();
        } else {
            cp_wait<0>();
        }
        __syncthreads();

        const uint32_t stg_b = sbase + (uint32_t)((i & 1) * STG) * 2;
        const uint32_t bstg_b = stg_b + (uint32_t)ASZ * 2;

#pragma unroll
        for (int kk = 0; kk < 4; kk++) {
            const uint32_t kh = kk * 16 * 2;   // byte offset within row
            uint32_t af[MI][4], bf[NI][2];
#pragma unroll
            for (int mi = 0; mi < MI; mi++)
                ldsm_x4(af[mi], stg_b + (uint32_t)((wM * WTM + mi * 16) * SRS) * 2 + kh + aoff);
#pragma unroll
            for (int ni = 0; ni < NI; ni++)
                ldsm_x2(bf[ni], bstg_b + (uint32_t)((wN * WTN + ni * 8) * SRS) * 2 + kh + boff);
#pragma unroll
            for (int mi = 0; mi < MI; mi++)
#pragma unroll
                for (int ni = 0; ni < NI; ni++)
                    mma_f16(acc[mi][ni], af[mi], bf[ni]);
        }
        __syncthreads();
    }

    // ---- epilogue ----
#pragma unroll
    for (int mi = 0; mi < MI; mi++) {
        const int row0 = m0 + wM * WTM + mi * 16 + g;
        float bm0 = 0.f, bm1 = 0.f;
        if (BIAS_MODE == 1) { bm0 = bias[row0]; bm1 = bias[row0 + 8]; }
#pragma unroll
        for (int ni = 0; ni < NI; ni++) {
            const int col = n0 + wN * WTN + ni * 8 + tq * 2;
            if (col >= Nrt) continue;
            float o0 = acc[mi][ni][0], o1 = acc[mi][ni][1];
            float o2 = acc[mi][ni][2], o3 = acc[mi][ni][3];
            if (BIAS_MODE == 1) { o0 += bm0; o1 += bm0; o2 += bm1; o3 += bm1; }
            if (BIAS_MODE == 2) {
                float bn0 = bias[col], bn1 = bias[col + 1];
                o0 += bn0; o1 += bn1; o2 += bn0; o3 += bn1;
            }
            if (sizeof(CT) == 4) {
                float* Cf = reinterpret_cast<float*>(C);
                *reinterpret_cast<float2*>(&Cf[(size_t)row0 * ldc + col])       = make_float2(o0, o1);
                *reinterpret_cast<float2*>(&Cf[(size_t)(row0 + 8) * ldc + col]) = make_float2(o2, o3);
            } else {
                __half* Ch = reinterpret_cast<__half*>(C);
                __half h0 = __float2half_rn(o0), h1 = __float2half_rn(o1);
                __half h2 = __float2half_rn(o2), h3 = __float2half_rn(o3);
                *reinterpret_cast<__half2*>(&Ch[(size_t)row0 * ldc + col])       = __halves2half2(h0, h1);
                *reinterpret_cast<__half2*>(&Ch[(size_t)(row0 + 8) * ldc + col]) = __halves2half2(h2, h3);
                if (SQ) {
                    __half* C2h = reinterpret_cast<__half*>(C2);
                    float f0 = __half2float(h0), f1 = __half2float(h1);
                    float f2 = __half2float(h2), f3 = __half2float(h3);
                    __half q0 = __float2half_rn(f0 * f0), q1 = __float2half_rn(f1 * f1);
                    __half q2 = __float2half_rn(f2 * f2), q3 = __float2half_rn(f3 * f3);
                    *reinterpret_cast<__half2*>(&C2h[(size_t)row0 * ldc + col])       = __halves2half2(q0, q1);
                    *reinterpret_cast<__half2*>(&C2h[(size_t)(row0 + 8) * ldc + col]) = __halves2half2(q2, q3);
                }
            }
        }
    }
}

// ---------------------------------------------------------------------------
// Dual-B fused FP16 GEMM for mean & m2 (shares attn A tiles), BK=64:
//   C1[n][c] = A[n][:] . B1[c][:],  C2[n][c] = A[n][:] . B2[c][:]
//   BM=128 (tokens), BN=64 (channels), warps 4x2 -> warp tile 32x32.
//   2 CTAs/SM. fp32 accumulate; transposed fp32 store: out[c][n].
// ---------------------------------------------------------------------------
#define DUAL_SMEM ((128 * SRS + 2 * 64 * SRS) * 2 * 2)
__global__ __launch_bounds__(256, 2) void mma_gemm_dualH(
    const __half* __restrict__ A, const __half* __restrict__ B1,
    const __half* __restrict__ B2,
    float* __restrict__ C1, float* __restrict__ C2)
{
    constexpr int BM = 128, BN = 64;
    constexpr int ASZ = BM * SRS, BSZ = BN * SRS;
    constexpr int STG = ASZ + 2 * BSZ;

    extern __shared__ __half smh[];
    const uint32_t sbase = smem_u32(smh);

    const int tid = threadIdx.x, lane = tid & 31, wid = tid >> 5;
    const int wM = wid & 3, wN = wid >> 2;
    const int m0 = blockIdx.y * BM, n0 = blockIdx.x * BN, b = blockIdx.z;

    A  += (size_t)b * NTOK * NTOK + (size_t)m0 * NTOK;
    B1 += (size_t)b * CIN * NTOK + (size_t)n0 * NTOK;
    B2 += (size_t)b * CIN * NTOK + (size_t)n0 * NTOK;
    C1 += (size_t)b * CIN * NTOK;
    C2 += (size_t)b * CIN * NTOK;

    float acc1[2][4][4], acc2[2][4][4];
#pragma unroll
    for (int mi = 0; mi < 2; mi++)
#pragma unroll
        for (int ni = 0; ni < 4; ni++)
#pragma unroll
            for (int q = 0; q < 4; q++) { acc1[mi][ni][q] = 0.f; acc2[mi][ni][q] = 0.f; }

    const int NK = NTOK >> 6;   // 64

    {
#pragma unroll
        for (int v = 0; v < 4; v++) {
            int t = tid + v * 256, r = t >> 3, ch = t & 7;
            cp16(sbase + (uint32_t)(r * SRS + ch * 8) * 2, A + (size_t)r * NTOK + ch * 8);
        }
#pragma unroll
        for (int v = 0; v < 2; v++) {
            int t = tid + v * 256, r = t >> 3, ch = t & 7;
            cp16(sbase + (uint32_t)(ASZ + r * SRS + ch * 8) * 2, B1 + (size_t)r * NTOK + ch * 8);
            cp16(sbase + (uint32_t)(ASZ + BSZ + r * SRS + ch * 8) * 2, B2 + (size_t)r * NTOK + ch * 8);
        }
        cp_commit();
    }

    const int g = lane >> 2, tq = lane & 3;
    const uint32_t aoff = (uint32_t)((lane & 15) * SRS + (lane >> 4) * 8) * 2;
    const uint32_t boff = (uint32_t)((lane & 7) * SRS + ((lane >> 3) & 1) * 8) * 2;

    for (int i = 0; i < NK; i++) {
        if (i + 1 < NK) {
            const int st = (i + 1) & 1;
            const int k0 = (i + 1) << 6;
#pragma unroll
            for (int v = 0; v < 4; v++) {
                int t = tid + v * 256, r = t >> 3, ch = t & 7;
                cp16(sbase + (uint32_t)(st * STG + r * SRS + ch * 8) * 2,
                     A + (size_t)r * NTOK + k0 + ch * 8);
            }
#pragma unroll
            for (int v = 0; v < 2; v++) {
                int t = tid + v * 256, r = t >> 3, ch = t & 7;
                cp16(sbase + (uint32_t)(st * STG + ASZ + r * SRS + ch * 8) * 2,
                     B1 + (size_t)r * NTOK + k0 + ch * 8);
                cp16(sbase + (uint32_t)(st * STG + ASZ + BSZ + r * SRS + ch * 8) * 2,
                     B2 + (size_t)r * NTOK + k0 + ch * 8);
            }
            cp_commit();
            cp_wait<1>();
        } else {
            cp_wait<0>();
        }
        __syncthreads();

        const uint32_t stg_b = sbase + (uint32_t)((i & 1) * STG) * 2;
        const uint32_t b1stg = stg_b + (uint32_t)ASZ * 2;
        const uint32_t b2stg = b1stg + (uint32_t)BSZ * 2;

#pragma unroll
        for (int kk = 0; kk < 4; kk++) {
            const uint32_t kh = kk * 16 * 2;
            uint32_t af[2][4], bf1[4][2], bf2[4][2];
#pragma unroll
            for (int mi = 0; mi < 2; mi++)
                ldsm_x4(af[mi], stg_b + (uint32_t)((wM * 32 + mi * 16) * SRS) * 2 + kh + aoff);
#pragma unroll
            for (int ni = 0; ni < 4; ni++) {
                ldsm_x2(bf1[ni], b1stg + (uint32_t)((wN * 32 + ni * 8) * SRS) * 2 + kh + boff);
                ldsm_x2(bf2[ni], b2stg + (uint32_t)((wN * 32 + ni * 8) * SRS) * 2 + kh + boff);
            }
#pragma unroll
            for (int mi = 0; mi < 2; mi++)
#pragma unroll
                for (int ni = 0; ni < 4; ni++) {
                    mma_f16(acc1[mi][ni], af[mi], bf1[ni]);
                    mma_f16(acc2[mi][ni], af[mi], bf2[ni]);
                }
        }
        __syncthreads();
    }

#pragma unroll
    for (int mi = 0; mi < 2; mi++) {
        const int row0 = m0 + wM * 32 + mi * 16 + g;
#pragma unroll
        for (int ni = 0; ni < 4; ni++) {
            const int col = n0 + wN * 32 + ni * 8 + tq * 2;
            C1[(size_t)col * NTOK + row0]           = acc1[mi][ni][0];
            C1[(size_t)(col + 1) * NTOK + row0]     = acc1[mi][ni][1];
            C1[(size_t)col * NTOK + row0 + 8]       = acc1[mi][ni][2];
            C1[(size_t)(col + 1) * NTOK + row0 + 8] = acc1[mi][ni][3];
            C2[(size_t)col * NTOK + row0]           = acc2[mi][ni][0];
            C2[(size_t)(col + 1) * NTOK + row0]     = acc2[mi][ni][1];
            C2[(size_t)col * NTOK + row0 + 8]       = acc2[mi][ni][2];
            C2[(size_t)(col + 1) * NTOK + row0 + 8] = acc2[mi][ni][3];
        }
    }
}

// ---------------------------------------------------------------------------
// Weight prep: round W to half, pad rows to dstRows with zeros; pad bias (f32).
// ---------------------------------------------------------------------------
__global__ void prep_w_kernel(const float* __restrict__ W, const float* __restrict__ bias,
                              __half* __restrict__ Wd, float* __restrict__ bd,
                              int rows, int cols, int dstRows)
{
    int i = blockIdx.x * 256 + threadIdx.x;
    int total = dstRows * cols;
    if (i < total) {
        int r = i / cols;
        Wd[i] = (r < rows) ? __float2half_rn(W[i]) : __float2half_rn(0.f);
    }
    if (bd && i < dstRows) bd[i] = (i < rows) ? bias[i] : 0.f;
}

// ---------------------------------------------------------------------------
// Transpose [C][N] fp32 -> [N][C] half. Two tensors via z split.
// ---------------------------------------------------------------------------
template <int C>
__global__ __launch_bounds__(256) void transpose_in_kernel(
    const float* __restrict__ in0, __half* __restrict__ out0,
    const float* __restrict__ in1, __half* __restrict__ out1)
{
    __shared__ float t[32][33];
    const int z = blockIdx.z;
    const int b = z & (NB - 1);
    const float* in = (z < NB) ? in0 : in1;
    __half* out = (z < NB) ? out0 : out1;
    in  += (size_t)b * C * NTOK;
    out += (size_t)b * NTOK * C;

    const int x0 = blockIdx.x * 32;   // token
    const int y0 = blockIdx.y * 32;   // channel
    const int tx = threadIdx.x & 31, ty = threadIdx.x >> 5;

#pragma unroll
    for (int i = 0; i < 4; i++)
        t[ty + i * 8][tx] = in[(size_t)(y0 + ty + i * 8) * NTOK + x0 + tx];
    __syncthreads();
#pragma unroll
    for (int i = 0; i < 4; i++)
        out[(size_t)(x0 + ty + i * 8) * C + y0 + tx] = __float2half_rn(t[tx][ty + i * 8]);
}

// ---------------------------------------------------------------------------
// Reductions / softmax / stats / combine
// ---------------------------------------------------------------------------
__device__ __forceinline__ float warpMax(float v) {
#pragma unroll
    for (int o = 16; o; o >>= 1) v = fmaxf(v, __shfl_xor_sync(0xffffffffu, v, o));
    return v;
}
__device__ __forceinline__ float warpSum(float v) {
#pragma unroll
    for (int o = 16; o; o >>= 1) v += __shfl_xor_sync(0xffffffffu, v, o);
    return v;
}

// reads fp32 S, writes half attn
__global__ __launch_bounds__(256) void softmax_mask_kernel(
    const float* __restrict__ S, __half* __restrict__ Aout,
    const int* __restrict__ cmask, const int* __restrict__ smask)
{
    const int n = blockIdx.x, b = blockIdx.y;
    const float* row = S + ((size_t)b * NTOK + n) * NTOK;
    __half* arow = Aout + ((size_t)b * NTOK + n) * NTOK;
    const int* sm = smask + (size_t)b * NTOK;
    const bool cmn = (cmask[(size_t)b * NTOK + n] != 0);
    const int tid = threadIdx.x;
    __shared__ float red[8];

    float v[16];
    float mx = -INFINITY;
#pragma unroll
    for (int i = 0; i < 16; i++) {
        int m = tid + i * 256;
        float s = row[m];
        if (cmn && sm[m] == 0) s = NEGV;
        v[i] = s;
        mx = fmaxf(mx, s);
    }
    mx = warpMax(mx);
    if ((tid & 31) == 0) red[tid >> 5] = mx;
    __syncthreads();
    if (tid < 32) {
        float x = (tid < 8) ? red[tid] : -INFINITY;
        x = warpMax(x);
        if (tid == 0) red[0] = x;
    }
    __syncthreads();
    mx = red[0];
    __syncthreads();

    float sum = 0.f;
#pragma unroll
    for (int i = 0; i < 16; i++) { v[i] = __expf(v[i] - mx); sum += v[i]; }
    sum = warpSum(sum);
    if ((tid & 31) == 0) red[tid >> 5] = sum;
    __syncthreads();
    if (tid < 32) {
        float x = (tid < 8) ? red[tid] : 0.f;
        x = warpSum(x);
        if (tid == 0) red[0] = x;
    }
    __syncthreads();
    const float inv = 1.f / red[0];
#pragma unroll
    for (int i = 0; i < 16; i++)
        arow[tid + i * 256] = __float2half_rn(v[i] * inv);
}

__global__ __launch_bounds__(256) void mvn_stats_kernel(
    const float* __restrict__ content,
    float* __restrict__ cmean, float* __restrict__ crstd)
{
    const int c = blockIdx.x, b = blockIdx.y;
    const float* p = content + ((size_t)b * CIN + c) * NTOK;
    const int tid = threadIdx.x;
    float s = 0.f, ss = 0.f;
#pragma unroll
    for (int i = 0; i < 16; i++) {
        float x = p[tid + i * 256];
        s += x; ss += x * x;
    }
    __shared__ float shs[8], shss[8];
    s = warpSum(s); ss = warpSum(ss);
    if ((tid & 31) == 0) { shs[tid >> 5] = s; shss[tid >> 5] = ss; }
    __syncthreads();
    if (tid == 0) {
        float S = 0.f, SS = 0.f;
#pragma unroll
        for (int i = 0; i < 8; i++) { S += shs[i]; SS += shss[i]; }
        float mean = S / (float)NTOK;
        float var = (SS - S * S / (float)NTOK) / (float)(NTOK - 1);
        cmean[b * CIN + c] = mean;
        crstd[b * CIN + c] = rsqrtf(var + EPSV);
    }
}

__global__ __launch_bounds__(256) void combine_kernel(
    const float4* __restrict__ content,
    const float4* __restrict__ meanT,
    const float4* __restrict__ m2T,
    const float* __restrict__ cmean,
    const float* __restrict__ crstd,
    float4* __restrict__ out)
{
    const int gid = blockIdx.x * 256 + threadIdx.x;
    const int bc = gid >> 10;
    const float mu = cmean[bc];
    const float rs = crstd[bc];
    float4 mn = meanT[gid];
    float4 m2 = m2T[gid];
    float4 ct = content[gid];
    float4 o;
    o.x = sqrtf(fmaxf(m2.x - mn.x * mn.x, 0.f)) * ((ct.x - mu) * rs) + mn.x;
    o.y = sqrtf(fmaxf(m2.y - mn.y * mn.y, 0.f)) * ((ct.y - mu) * rs) + mn.y;
    o.z = sqrtf(fmaxf(m2.z - mn.z * mn.z, 0.f)) * ((ct.z - mu) * rs) + mn.z;
    o.w = sqrtf(fmaxf(m2.w - mn.w * mn.w, 0.f)) * ((ct.w - mu) * rs) + mn.w;
    out[gid] = o;
}

// ---------------------------------------------------------------------------
// Launch
// ---------------------------------------------------------------------------
extern "C" void kernel_launch(void* const* d_in, const int* in_sizes, int n_in,
                              void* d_out, int out_size)
{
    const float* content = (const float*)d_in[0];
    const float* style   = (const float*)d_in[1];
    const float* ckey    = (const float*)d_in[2];
    const float* skey    = (const float*)d_in[3];
    const int*   cmask   = (const int*)  d_in[4];
    const int*   smask   = (const int*)  d_in[5];
    const float* Wf = (const float*)d_in[6];
    const float* bf = (const float*)d_in[7];
    const float* Wg = (const float*)d_in[8];
    const float* bg = (const float*)d_in[9];
    const float* Wh = (const float*)d_in[10];
    const float* bh = (const float*)d_in[11];
    float* out = (float*)d_out;

    __half *pckT, *pskT, *pstT, *pFqN, *pGN, *pHv, *pHv2, *pA, *pWf, *pWg, *pWh;
    float *pS, *pMean, *pM2, *pbf, *pbg, *pCm, *pCr;
    cudaGetSymbolAddress((void**)&pckT, g_ckT);
    cudaGetSymbolAddress((void**)&pskT, g_skT);
    cudaGetSymbolAddress((void**)&pstT, g_stT);
    cudaGetSymbolAddress((void**)&pFqN, g_FqN);
    cudaGetSymbolAddress((void**)&pGN,  g_GN);
    cudaGetSymbolAddress((void**)&pHv,  g_HvT);
    cudaGetSymbolAddress((void**)&pHv2, g_Hv2T);
    cudaGetSymbolAddress((void**)&pA,   g_A);
    cudaGetSymbolAddress((void**)&pS,   g_S);
    cudaGetSymbolAddress((void**)&pMean, g_meanT);
    cudaGetSymbolAddress((void**)&pM2,  g_m2T);
    cudaGetSymbolAddress((void**)&pWf,  g_Wf);
    cudaGetSymbolAddress((void**)&pWg,  g_Wg);
    cudaGetSymbolAddress((void**)&pWh,  g_Wh);
    cudaGetSymbolAddress((void**)&pbf,  g_bf);
    cudaGetSymbolAddress((void**)&pbg,  g_bg);
    cudaGetSymbolAddress((void**)&pCm,  g_cmean);
    cudaGetSymbolAddress((void**)&pCr,  g_crstd);

    constexpr int SMEM_STD = (128 * SRS + 128 * SRS) * 2 * 2;  // 73728

    static bool attr_done = false;
    if (!attr_done) {
        cudaFuncSetAttribute(mma_gemmH<128, 128, 4, 0, false, float>,
                             cudaFuncAttributeMaxDynamicSharedMemorySize, SMEM_STD);
        cudaFuncSetAttribute(mma_gemmH<128, 128, 4, 2, false, __half>,
                             cudaFuncAttributeMaxDynamicSharedMemorySize, SMEM_STD);
        cudaFuncSetAttribute(mma_gemmH<128, 128, 4, 1, true, __half>,
                             cudaFuncAttributeMaxDynamicSharedMemorySize, SMEM_STD);
        cudaFuncSetAttribute(mma_gemm_dualH,
                             cudaFuncAttributeMaxDynamicSharedMemorySize, DUAL_SMEM);
        attr_done = true;
    }

    const dim3 blk(256);

    // --- weight prep ---
    prep_w_kernel<<<(CKP * CKEY + 255) / 256, blk>>>(Wf, bf, pWf, pbf, CKEY, CKEY, CKP);
    prep_w_kernel<<<(CKP * CKEY + 255) / 256, blk>>>(Wg, bg, pWg, pbg, CKEY, CKEY, CKP);
    prep_w_kernel<<<(CIN * CIN + 255) / 256, blk>>>(Wh, nullptr, pWh, nullptr, CIN, CIN, CIN);

    // --- transpose inputs to token-major half ---
    transpose_in_kernel<CKEY><<<dim3(NTOK / 32, CKEY / 32, 2 * NB), blk>>>(
        ckey, pckT, skey, pskT);
    transpose_in_kernel<CIN><<<dim3(NTOK / 32, CIN / 32, NB), blk>>>(
        style, pstT, style, pstT);

    // --- projections (fp16 mma, fp32 accum), K = CKEY=448 or CIN=256 (mult of 64) ---
    mma_gemmH<128, 128, 4, 2, false, __half><<<dim3(CKP / 128, NTOK / 128, NB), blk, SMEM_STD>>>(
        pckT, pWf, pbf, pFqN, nullptr, CKEY, CKEY, CKEY, CKEY, CKEY,
        (size_t)NTOK * CKEY, 0, (size_t)NTOK * CKEY);
    mma_gemmH<128, 128, 4, 2, false, __half><<<dim3(CKP / 128, NTOK / 128, NB), blk, SMEM_STD>>>(
        pskT, pWg, pbg, pGN, nullptr, CKEY, CKEY, CKEY, CKEY, CKEY,
        (size_t)NTOK * CKEY, 0, (size_t)NTOK * CKEY);
    mma_gemmH<128, 128, 4, 1, true, __half><<<dim3(NTOK / 128, CIN / 128, NB), blk, SMEM_STD>>>(
        pWh, pstT, bh, pHv, pHv2, NTOK, CIN, CIN, CIN, NTOK,
        0, (size_t)NTOK * CIN, (size_t)CIN * NTOK);

    // --- S = FqN @ GN^T (fp32 out) ---
    mma_gemmH<128, 128, 4, 0, false, float><<<dim3(NTOK / 128, NTOK / 128, NB), blk, SMEM_STD>>>(
        pFqN, pGN, nullptr, pS, nullptr, NTOK, CKEY, CKEY, CKEY, NTOK,
        (size_t)NTOK * CKEY, (size_t)NTOK * CKEY, (size_t)NTOK * NTOK);

    // --- masked softmax: fp32 S -> half attn ---
    softmax_mask_kernel<<<dim3(NTOK, NB), blk>>>(pS, pA, cmask, smask);

    // --- fused mean/m2 ---
    mma_gemm_dualH<<<dim3(CIN / 64, NTOK / 128, NB), blk, DUAL_SMEM>>>(
        pA, pHv, pHv2, pMean, pM2);

    // --- mvn stats + final combine ---
    mvn_stats_kernel<<<dim3(CIN, NB), blk>>>(content, pCm, pCr);
    combine_kernel<<<dim3((NB * CIN * NTOK / 4) / 256), blk>>>(
        (const float4*)content, (const float4*)pMean, (const float4*)pM2,
        pCm, pCr, (float4*)out);
}

// round 11
// speedup vs baseline: 5.8578x; 1.0364x over previous
#include <cuda_runtime.h>
#include <cuda_fp16.h>
#include <cstdint>

// ---------------------------------------------------------------------------
// Problem constants
// ---------------------------------------------------------------------------
#define NB   4
#define CIN  256
#define CKEY 448
#define NTOK 4096
#define NEGV (-1e15f)
#define EPSV 1e-5f
#define CKP  512   // padded CKEY for projection N-dim

// ---------------------------------------------------------------------------
// Scratch (static device globals; no runtime allocation)
// ---------------------------------------------------------------------------
__device__ __half g_ckT [(size_t)NB * NTOK * CKEY];   // [b][N][Ck] ckey^T
__device__ __half g_skT [(size_t)NB * NTOK * CKEY];   // [b][N][Ck] skey^T
__device__ __half g_stT [(size_t)NB * NTOK * CIN];    // [b][N][C]  style^T
__device__ __half g_FqN [(size_t)NB * NTOK * CKEY];   // [b][N][Ck] f(ckey)
__device__ __half g_GN  [(size_t)NB * NTOK * CKEY];   // [b][N][Ck] g(skey)
__device__ __half g_HvT [(size_t)NB * CIN  * NTOK];   // [b][C][N]  h(style)
__device__ __half g_Hv2T[(size_t)NB * CIN  * NTOK];   // [b][C][N]  h(style)^2
__device__ float  g_S   [(size_t)NB * NTOK * NTOK];   // [b][N][N]  scores (fp32)
__device__ __half g_A   [(size_t)NB * NTOK * NTOK];   // [b][N][N]  attn (half)
__device__ float  g_meanT[(size_t)NB * CIN * NTOK];   // [b][C][N]
__device__ float  g_m2T [(size_t)NB * CIN  * NTOK];   // [b][C][N]
__device__ __half g_Wf  [CKP * CKEY];                 // rounded, zero-padded rows
__device__ __half g_Wg  [CKP * CKEY];
__device__ __half g_Wh  [CIN * CIN];
__device__ float  g_bf  [CKP];
__device__ float  g_bg  [CKP];
__device__ float  g_cmean[NB * CIN];
__device__ float  g_crstd[NB * CIN];

// ---------------------------------------------------------------------------
// Helpers
// ---------------------------------------------------------------------------
__device__ __forceinline__ uint32_t smem_u32(const void* p) {
    uint32_t a;
    asm("{ .reg .u64 t; cvta.to.shared.u64 t, %1; cvt.u32.u64 %0, t; }"
        : "=r"(a) : "l"(p));
    return a;
}
__device__ __forceinline__ void cp16(uint32_t s, const void* g) {
    asm volatile("cp.async.cg.shared.global [%0], [%1], 16;" :: "r"(s), "l"(g));
}
__device__ __forceinline__ void cp_commit() {
    asm volatile("cp.async.commit_group;" ::: "memory");
}
template <int N> __device__ __forceinline__ void cp_wait() {
    asm volatile("cp.async.wait_group %0;" :: "n"(N) : "memory");
}
__device__ __forceinline__ void mma_f16(float* d, const uint32_t* a, const uint32_t* b) {
    asm volatile(
        "mma.sync.aligned.m16n8k16.row.col.f32.f16.f16.f32 "
        "{%0,%1,%2,%3}, {%4,%5,%6,%7}, {%8,%9}, {%0,%1,%2,%3};"
        : "+f"(d[0]), "+f"(d[1]), "+f"(d[2]), "+f"(d[3])
        : "r"(a[0]), "r"(a[1]), "r"(a[2]), "r"(a[3]), "r"(b[0]), "r"(b[1]));
}
__device__ __forceinline__ void ldsm_x4(uint32_t* r, uint32_t a) {
    asm volatile("ldmatrix.sync.aligned.m8n8.x4.shared.b16 {%0,%1,%2,%3}, [%4];"
        : "=r"(r[0]), "=r"(r[1]), "=r"(r[2]), "=r"(r[3]) : "r"(a));
}
__device__ __forceinline__ void ldsm_x2(uint32_t* r, uint32_t a) {
    asm volatile("ldmatrix.sync.aligned.m8n8.x2.shared.b16 {%0,%1}, [%2];"
        : "=r"(r[0]), "=r"(r[1]) : "r"(a));
}

// BK = 64 halves per k-block. smem row stride: 72 halves (144 B).
// LDSM conflict check: chunk index (r*144/16) mod 8 = 9r mod 8 -> 8 distinct.
#define SRS 72
#define NSTG 3   // pipeline stages

// ---------------------------------------------------------------------------
// Generic FP16 mma.sync GEMM:  C[M][N] = A[M][K] * B[N][K]^T   (fp32 accum)
//   256 threads / 2 CTAs per SM, BK=64 halves, 3-stage cp.async pipeline
//   with ONE __syncthreads per iteration, ldmatrix fragment loads.
//   Warp grid WMW x (8/WMW); warp tile (BM/WMW) x (BN*WMW/8).
//   BIAS_MODE: 0 none, 1 along M, 2 along N (bias fp32)
//   SQ: also write C2 = rn(h*h), h = rn(C)  (CT == __half)
//   CT: output type (float or __half). Store guard: col < Nrt.
//   K must be a multiple of 64.
// ---------------------------------------------------------------------------
template <int BM, int BN, int WMW, int BIAS_MODE, bool SQ, typename CT>
__global__ __launch_bounds__(256, 2) void mma_gemmH(
    const __half* __restrict__ A, const __half* __restrict__ B,
    const float* __restrict__ bias,
    CT* __restrict__ C, CT* __restrict__ C2,
    int Nrt, int K, int lda, int ldb, int ldc,
    size_t sA, size_t sB, size_t sC)
{
    constexpr int WNW = 8 / WMW;
    constexpr int WTM = BM / WMW;
    constexpr int WTN = BN / WNW;
    constexpr int MI  = WTM / 16;
    constexpr int NI  = WTN / 8;
    constexpr int ASZ = BM * SRS;          // halves
    constexpr int BSZ = BN * SRS;
    constexpr int STG = ASZ + BSZ;
    constexpr int ACH = BM * 8 / 256;      // cp16 chunks per thread (A), 8 per row
    constexpr int BCH = BN * 8 / 256;

    extern __shared__ __half smh[];
    const uint32_t sbase = smem_u32(smh);

    const int tid = threadIdx.x, lane = tid & 31, wid = tid >> 5;
    const int wM = wid % WMW, wN = wid / WMW;
    const int m0 = blockIdx.y * BM, n0 = blockIdx.x * BN, b = blockIdx.z;

    A += (size_t)b * sA + (size_t)m0 * lda;
    B += (size_t)b * sB + (size_t)n0 * ldb;
    C += (size_t)b * sC;
    if (SQ) C2 += (size_t)b * sC;

    float acc[MI][NI][4];
#pragma unroll
    for (int mi = 0; mi < MI; mi++)
#pragma unroll
        for (int ni = 0; ni < NI; ni++)
#pragma unroll
            for (int q = 0; q < 4; q++) acc[mi][ni][q] = 0.f;

    const int NK = K >> 6;   // 64 halves per k-block

    // prefetch stages 0 and 1
#pragma unroll
    for (int p = 0; p < 2; p++) {
        if (p < NK) {
            const uint32_t sb = sbase + (uint32_t)(p * STG) * 2;
            const int k0 = p << 6;
#pragma unroll
            for (int v = 0; v < ACH; v++) {
                int t = tid + v * 256, r = t >> 3, ch = t & 7;
                cp16(sb + (uint32_t)(r * SRS + ch * 8) * 2, A + (size_t)r * lda + k0 + ch * 8);
            }
#pragma unroll
            for (int v = 0; v < BCH; v++) {
                int t = tid + v * 256, r = t >> 3, ch = t & 7;
                cp16(sb + (uint32_t)(ASZ + r * SRS + ch * 8) * 2, B + (size_t)r * ldb + k0 + ch * 8);
            }
        }
        cp_commit();
    }

    const int g = lane >> 2, tq = lane & 3;
    // ldmatrix per-lane offsets (bytes)
    const uint32_t aoff = (uint32_t)((lane & 15) * SRS + (lane >> 4) * 8) * 2;
    const uint32_t boff = (uint32_t)((lane & 7) * SRS + ((lane >> 3) & 1) * 8) * 2;

    int stg = 0, pstg = 2;
    for (int i = 0; i < NK; i++) {
        cp_wait<1>();
        __syncthreads();

        if (i + 2 < NK) {
            const uint32_t sb = sbase + (uint32_t)(pstg * STG) * 2;
            const int k0 = (i + 2) << 6;
#pragma unroll
            for (int v = 0; v < ACH; v++) {
                int t = tid + v * 256, r = t >> 3, ch = t & 7;
                cp16(sb + (uint32_t)(r * SRS + ch * 8) * 2, A + (size_t)r * lda + k0 + ch * 8);
            }
#pragma unroll
            for (int v = 0; v < BCH; v++) {
                int t = tid + v * 256, r = t >> 3, ch = t & 7;
                cp16(sb + (uint32_t)(ASZ + r * SRS + ch * 8) * 2, B + (size_t)r * ldb + k0 + ch * 8);
            }
        }
        cp_commit();
        if (++pstg == NSTG) pstg = 0;

        const uint32_t stg_b = sbase + (uint32_t)(stg * STG) * 2;
        const uint32_t bstg_b = stg_b + (uint32_t)ASZ * 2;

#pragma unroll
        for (int kk = 0; kk < 4; kk++) {
            const uint32_t kh = kk * 16 * 2;   // byte offset within row
            uint32_t af[MI][4], bf[NI][2];
#pragma unroll
            for (int mi = 0; mi < MI; mi++)
                ldsm_x4(af[mi], stg_b + (uint32_t)((wM * WTM + mi * 16) * SRS) * 2 + kh + aoff);
#pragma unroll
            for (int ni = 0; ni < NI; ni++)
                ldsm_x2(bf[ni], bstg_b + (uint32_t)((wN * WTN + ni * 8) * SRS) * 2 + kh + boff);
#pragma unroll
            for (int mi = 0; mi < MI; mi++)
#pragma unroll
                for (int ni = 0; ni < NI; ni++)
                    mma_f16(acc[mi][ni], af[mi], bf[ni]);
        }
        if (++stg == NSTG) stg = 0;
    }

    // ---- epilogue ----
#pragma unroll
    for (int mi = 0; mi < MI; mi++) {
        const int row0 = m0 + wM * WTM + mi * 16 + g;
        float bm0 = 0.f, bm1 = 0.f;
        if (BIAS_MODE == 1) { bm0 = bias[row0]; bm1 = bias[row0 + 8]; }
#pragma unroll
        for (int ni = 0; ni < NI; ni++) {
            const int col = n0 + wN * WTN + ni * 8 + tq * 2;
            if (col >= Nrt) continue;
            float o0 = acc[mi][ni][0], o1 = acc[mi][ni][1];
            float o2 = acc[mi][ni][2], o3 = acc[mi][ni][3];
            if (BIAS_MODE == 1) { o0 += bm0; o1 += bm0; o2 += bm1; o3 += bm1; }
            if (BIAS_MODE == 2) {
                float bn0 = bias[col], bn1 = bias[col + 1];
                o0 += bn0; o1 += bn1; o2 += bn0; o3 += bn1;
            }
            if (sizeof(CT) == 4) {
                float* Cf = reinterpret_cast<float*>(C);
                *reinterpret_cast<float2*>(&Cf[(size_t)row0 * ldc + col])       = make_float2(o0, o1);
                *reinterpret_cast<float2*>(&Cf[(size_t)(row0 + 8) * ldc + col]) = make_float2(o2, o3);
            } else {
                __half* Ch = reinterpret_cast<__half*>(C);
                __half h0 = __float2half_rn(o0), h1 = __float2half_rn(o1);
                __half h2 = __float2half_rn(o2), h3 = __float2half_rn(o3);
                *reinterpret_cast<__half2*>(&Ch[(size_t)row0 * ldc + col])       = __halves2half2(h0, h1);
                *reinterpret_cast<__half2*>(&Ch[(size_t)(row0 + 8) * ldc + col]) = __halves2half2(h2, h3);
                if (SQ) {
                    __half* C2h = reinterpret_cast<__half*>(C2);
                    float f0 = __half2float(h0), f1 = __half2float(h1);
                    float f2 = __half2float(h2), f3 = __half2float(h3);
                    __half q0 = __float2half_rn(f0 * f0), q1 = __float2half_rn(f1 * f1);
                    __half q2 = __float2half_rn(f2 * f2), q3 = __float2half_rn(f3 * f3);
                    *reinterpret_cast<__half2*>(&C2h[(size_t)row0 * ldc + col])       = __halves2half2(q0, q1);
                    *reinterpret_cast<__half2*>(&C2h[(size_t)(row0 + 8) * ldc + col]) = __halves2half2(q2, q3);
                }
            }
        }
    }
}

// ---------------------------------------------------------------------------
// Dual-B fused FP16 GEMM for mean & m2 (shares attn A tiles), BK=64, 3-stage:
//   C1[n][c] = A[n][:] . B1[c][:],  C2[n][c] = A[n][:] . B2[c][:]
//   BM=128 (tokens), BN=64 (channels), warps 4x2 -> warp tile 32x32.
//   2 CTAs/SM. fp32 accumulate; transposed fp32 store: out[c][n].
// ---------------------------------------------------------------------------
#define DUAL_SMEM ((128 * SRS + 2 * 64 * SRS) * 2 * NSTG)
__global__ __launch_bounds__(256, 2) void mma_gemm_dualH(
    const __half* __restrict__ A, const __half* __restrict__ B1,
    const __half* __restrict__ B2,
    float* __restrict__ C1, float* __restrict__ C2)
{
    constexpr int BM = 128, BN = 64;
    constexpr int ASZ = BM * SRS, BSZ = BN * SRS;
    constexpr int STG = ASZ + 2 * BSZ;

    extern __shared__ __half smh[];
    const uint32_t sbase = smem_u32(smh);

    const int tid = threadIdx.x, lane = tid & 31, wid = tid >> 5;
    const int wM = wid & 3, wN = wid >> 2;
    const int m0 = blockIdx.y * BM, n0 = blockIdx.x * BN, b = blockIdx.z;

    A  += (size_t)b * NTOK * NTOK + (size_t)m0 * NTOK;
    B1 += (size_t)b * CIN * NTOK + (size_t)n0 * NTOK;
    B2 += (size_t)b * CIN * NTOK + (size_t)n0 * NTOK;
    C1 += (size_t)b * CIN * NTOK;
    C2 += (size_t)b * CIN * NTOK;

    float acc1[2][4][4], acc2[2][4][4];
#pragma unroll
    for (int mi = 0; mi < 2; mi++)
#pragma unroll
        for (int ni = 0; ni < 4; ni++)
#pragma unroll
            for (int q = 0; q < 4; q++) { acc1[mi][ni][q] = 0.f; acc2[mi][ni][q] = 0.f; }

    const int NK = NTOK >> 6;   // 64

    // prefetch stages 0, 1
#pragma unroll
    for (int p = 0; p < 2; p++) {
        const uint32_t sb = sbase + (uint32_t)(p * STG) * 2;
        const int k0 = p << 6;
#pragma unroll
        for (int v = 0; v < 4; v++) {
            int t = tid + v * 256, r = t >> 3, ch = t & 7;
            cp16(sb + (uint32_t)(r * SRS + ch * 8) * 2, A + (size_t)r * NTOK + k0 + ch * 8);
        }
#pragma unroll
        for (int v = 0; v < 2; v++) {
            int t = tid + v * 256, r = t >> 3, ch = t & 7;
            cp16(sb + (uint32_t)(ASZ + r * SRS + ch * 8) * 2, B1 + (size_t)r * NTOK + k0 + ch * 8);
            cp16(sb + (uint32_t)(ASZ + BSZ + r * SRS + ch * 8) * 2, B2 + (size_t)r * NTOK + k0 + ch * 8);
        }
        cp_commit();
    }

    const int g = lane >> 2, tq = lane & 3;
    const uint32_t aoff = (uint32_t)((lane & 15) * SRS + (lane >> 4) * 8) * 2;
    const uint32_t boff = (uint32_t)((lane & 7) * SRS + ((lane >> 3) & 1) * 8) * 2;

    int stg = 0, pstg = 2;
    for (int i = 0; i < NK; i++) {
        cp_wait<1>();
        __syncthreads();

        if (i + 2 < NK) {
            const uint32_t sb = sbase + (uint32_t)(pstg * STG) * 2;
            const int k0 = (i + 2) << 6;
#pragma unroll
            for (int v = 0; v < 4; v++) {
                int t = tid + v * 256, r = t >> 3, ch = t & 7;
                cp16(sb + (uint32_t)(r * SRS + ch * 8) * 2, A + (size_t)r * NTOK + k0 + ch * 8);
            }
#pragma unroll
            for (int v = 0; v < 2; v++) {
                int t = tid + v * 256, r = t >> 3, ch = t & 7;
                cp16(sb + (uint32_t)(ASZ + r * SRS + ch * 8) * 2, B1 + (size_t)r * NTOK + k0 + ch * 8);
                cp16(sb + (uint32_t)(ASZ + BSZ + r * SRS + ch * 8) * 2, B2 + (size_t)r * NTOK + k0 + ch * 8);
            }
        }
        cp_commit();
        if (++pstg == NSTG) pstg = 0;

        const uint32_t stg_b = sbase + (uint32_t)(stg * STG) * 2;
        const uint32_t b1stg = stg_b + (uint32_t)ASZ * 2;
        const uint32_t b2stg = b1stg + (uint32_t)BSZ * 2;

#pragma unroll
        for (int kk = 0; kk < 4; kk++) {
            const uint32_t kh = kk * 16 * 2;
            uint32_t af[2][4], bf1[4][2], bf2[4][2];
#pragma unroll
            for (int mi = 0; mi < 2; mi++)
                ldsm_x4(af[mi], stg_b + (uint32_t)((wM * 32 + mi * 16) * SRS) * 2 + kh + aoff);
#pragma unroll
            for (int ni = 0; ni < 4; ni++) {
                ldsm_x2(bf1[ni], b1stg + (uint32_t)((wN * 32 + ni * 8) * SRS) * 2 + kh + boff);
                ldsm_x2(bf2[ni], b2stg + (uint32_t)((wN * 32 + ni * 8) * SRS) * 2 + kh + boff);
            }
#pragma unroll
            for (int mi = 0; mi < 2; mi++)
#pragma unroll
                for (int ni = 0; ni < 4; ni++) {
                    mma_f16(acc1[mi][ni], af[mi], bf1[ni]);
                    mma_f16(acc2[mi][ni], af[mi], bf2[ni]);
                }
        }
        if (++stg == NSTG) stg = 0;
    }

#pragma unroll
    for (int mi = 0; mi < 2; mi++) {
        const int row0 = m0 + wM * 32 + mi * 16 + g;
#pragma unroll
        for (int ni = 0; ni < 4; ni++) {
            const int col = n0 + wN * 32 + ni * 8 + tq * 2;
            C1[(size_t)col * NTOK + row0]           = acc1[mi][ni][0];
            C1[(size_t)(col + 1) * NTOK + row0]     = acc1[mi][ni][1];
            C1[(size_t)col * NTOK + row0 + 8]       = acc1[mi][ni][2];
            C1[(size_t)(col + 1) * NTOK + row0 + 8] = acc1[mi][ni][3];
            C2[(size_t)col * NTOK + row0]           = acc2[mi][ni][0];
            C2[(size_t)(col + 1) * NTOK + row0]     = acc2[mi][ni][1];
            C2[(size_t)col * NTOK + row0 + 8]       = acc2[mi][ni][2];
            C2[(size_t)(col + 1) * NTOK + row0 + 8] = acc2[mi][ni][3];
        }
    }
}

// ---------------------------------------------------------------------------
// Weight prep: round W to half, pad rows to dstRows with zeros; pad bias (f32).
// ---------------------------------------------------------------------------
__global__ void prep_w_kernel(const float* __restrict__ W, const float* __restrict__ bias,
                              __half* __restrict__ Wd, float* __restrict__ bd,
                              int rows, int cols, int dstRows)
{
    int i = blockIdx.x * 256 + threadIdx.x;
    int total = dstRows * cols;
    if (i < total) {
        int r = i / cols;
        Wd[i] = (r < rows) ? __float2half_rn(W[i]) : __float2half_rn(0.f);
    }
    if (bd && i < dstRows) bd[i] = (i < rows) ? bias[i] : 0.f;
}

// ---------------------------------------------------------------------------
// Transpose [C][N] fp32 -> [N][C] half. Two tensors via z split.
// ---------------------------------------------------------------------------
template <int C>
__global__ __launch_bounds__(256) void transpose_in_kernel(
    const float* __restrict__ in0, __half* __restrict__ out0,
    const float* __restrict__ in1, __half* __restrict__ out1)
{
    __shared__ float t[32][33];
    const int z = blockIdx.z;
    const int b = z & (NB - 1);
    const float* in = (z < NB) ? in0 : in1;
    __half* out = (z < NB) ? out0 : out1;
    in  += (size_t)b * C * NTOK;
    out += (size_t)b * NTOK * C;

    const int x0 = blockIdx.x * 32;   // token
    const int y0 = blockIdx.y * 32;   // channel
    const int tx = threadIdx.x & 31, ty = threadIdx.x >> 5;

#pragma unroll
    for (int i = 0; i < 4; i++)
        t[ty + i * 8][tx] = in[(size_t)(y0 + ty + i * 8) * NTOK + x0 + tx];
    __syncthreads();
#pragma unroll
    for (int i = 0; i < 4; i++)
        out[(size_t)(x0 + ty + i * 8) * C + y0 + tx] = __float2half_rn(t[tx][ty + i * 8]);
}

// ---------------------------------------------------------------------------
// Reductions / softmax / stats / combine
// ---------------------------------------------------------------------------
__device__ __forceinline__ float warpMax(float v) {
#pragma unroll
    for (int o = 16; o; o >>= 1) v = fmaxf(v, __shfl_xor_sync(0xffffffffu, v, o));
    return v;
}
__device__ __forceinline__ float warpSum(float v) {
#pragma unroll
    for (int o = 16; o; o >>= 1) v += __shfl_xor_sync(0xffffffffu, v, o);
    return v;
}

// reads fp32 S, writes half attn
__global__ __launch_bounds__(256) void softmax_mask_kernel(
    const float* __restrict__ S, __half* __restrict__ Aout,
    const int* __restrict__ cmask, const int* __restrict__ smask)
{
    const int n = blockIdx.x, b = blockIdx.y;
    const float* row = S + ((size_t)b * NTOK + n) * NTOK;
    __half* arow = Aout + ((size_t)b * NTOK + n) * NTOK;
    const int* sm = smask + (size_t)b * NTOK;
    const bool cmn = (cmask[(size_t)b * NTOK + n] != 0);
    const int tid = threadIdx.x;
    __shared__ float red[8];

    float v[16];
    float mx = -INFINITY;
#pragma unroll
    for (int i = 0; i < 16; i++) {
        int m = tid + i * 256;
        float s = row[m];
        if (cmn && sm[m] == 0) s = NEGV;
        v[i] = s;
        mx = fmaxf(mx, s);
    }
    mx = warpMax(mx);
    if ((tid & 31) == 0) red[tid >> 5] = mx;
    __syncthreads();
    if (tid < 32) {
        float x = (tid < 8) ? red[tid] : -INFINITY;
        x = warpMax(x);
        if (tid == 0) red[0] = x;
    }
    __syncthreads();
    mx = red[0];
    __syncthreads();

    float sum = 0.f;
#pragma unroll
    for (int i = 0; i < 16; i++) { v[i] = __expf(v[i] - mx); sum += v[i]; }
    sum = warpSum(sum);
    if ((tid & 31) == 0) red[tid >> 5] = sum;
    __syncthreads();
    if (tid < 32) {
        float x = (tid < 8) ? red[tid] : 0.f;
        x = warpSum(x);
        if (tid == 0) red[0] = x;
    }
    __syncthreads();
    const float inv = 1.f / red[0];
#pragma unroll
    for (int i = 0; i < 16; i++)
        arow[tid + i * 256] = __float2half_rn(v[i] * inv);
}

__global__ __launch_bounds__(256) void mvn_stats_kernel(
    const float* __restrict__ content,
    float* __restrict__ cmean, float* __restrict__ crstd)
{
    const int c = blockIdx.x, b = blockIdx.y;
    const float* p = content + ((size_t)b * CIN + c) * NTOK;
    const int tid = threadIdx.x;
    float s = 0.f, ss = 0.f;
#pragma unroll
    for (int i = 0; i < 16; i++) {
        float x = p[tid + i * 256];
        s += x; ss += x * x;
    }
    __shared__ float shs[8], shss[8];
    s = warpSum(s); ss = warpSum(ss);
    if ((tid & 31) == 0) { shs[tid >> 5] = s; shss[tid >> 5] = ss; }
    __syncthreads();
    if (tid == 0) {
        float S = 0.f, SS = 0.f;
#pragma unroll
        for (int i = 0; i < 8; i++) { S += shs[i]; SS += shss[i]; }
        float mean = S / (float)NTOK;
        float var = (SS - S * S / (float)NTOK) / (float)(NTOK - 1);
        cmean[b * CIN + c] = mean;
        crstd[b * CIN + c] = rsqrtf(var + EPSV);
    }
}

__global__ __launch_bounds__(256) void combine_kernel(
    const float4* __restrict__ content,
    const float4* __restrict__ meanT,
    const float4* __restrict__ m2T,
    const float* __restrict__ cmean,
    const float* __restrict__ crstd,
    float4* __restrict__ out)
{
    const int gid = blockIdx.x * 256 + threadIdx.x;
    const int bc = gid >> 10;
    const float mu = cmean[bc];
    const float rs = crstd[bc];
    float4 mn = meanT[gid];
    float4 m2 = m2T[gid];
    float4 ct = content[gid];
    float4 o;
    o.x = sqrtf(fmaxf(m2.x - mn.x * mn.x, 0.f)) * ((ct.x - mu) * rs) + mn.x;
    o.y = sqrtf(fmaxf(m2.y - mn.y * mn.y, 0.f)) * ((ct.y - mu) * rs) + mn.y;
    o.z = sqrtf(fmaxf(m2.z - mn.z * mn.z, 0.f)) * ((ct.z - mu) * rs) + mn.z;
    o.w = sqrtf(fmaxf(m2.w - mn.w * mn.w, 0.f)) * ((ct.w - mu) * rs) + mn.w;
    out[gid] = o;
}

// ---------------------------------------------------------------------------
// Launch
// ---------------------------------------------------------------------------
extern "C" void kernel_launch(void* const* d_in, const int* in_sizes, int n_in,
                              void* d_out, int out_size)
{
    const float* content = (const float*)d_in[0];
    const float* style   = (const float*)d_in[1];
    const float* ckey    = (const float*)d_in[2];
    const float* skey    = (const float*)d_in[3];
    const int*   cmask   = (const int*)  d_in[4];
    const int*   smask   = (const int*)  d_in[5];
    const float* Wf = (const float*)d_in[6];
    const float* bf = (const float*)d_in[7];
    const float* Wg = (const float*)d_in[8];
    const float* bg = (const float*)d_in[9];
    const float* Wh = (const float*)d_in[10];
    const float* bh = (const float*)d_in[11];
    float* out = (float*)d_out;

    __half *pckT, *pskT, *pstT, *pFqN, *pGN, *pHv, *pHv2, *pA, *pWf, *pWg, *pWh;
    float *pS, *pMean, *pM2, *pbf, *pbg, *pCm, *pCr;
    cudaGetSymbolAddress((void**)&pckT, g_ckT);
    cudaGetSymbolAddress((void**)&pskT, g_skT);
    cudaGetSymbolAddress((void**)&pstT, g_stT);
    cudaGetSymbolAddress((void**)&pFqN, g_FqN);
    cudaGetSymbolAddress((void**)&pGN,  g_GN);
    cudaGetSymbolAddress((void**)&pHv,  g_HvT);
    cudaGetSymbolAddress((void**)&pHv2, g_Hv2T);
    cudaGetSymbolAddress((void**)&pA,   g_A);
    cudaGetSymbolAddress((void**)&pS,   g_S);
    cudaGetSymbolAddress((void**)&pMean, g_meanT);
    cudaGetSymbolAddress((void**)&pM2,  g_m2T);
    cudaGetSymbolAddress((void**)&pWf,  g_Wf);
    cudaGetSymbolAddress((void**)&pWg,  g_Wg);
    cudaGetSymbolAddress((void**)&pWh,  g_Wh);
    cudaGetSymbolAddress((void**)&pbf,  g_bf);
    cudaGetSymbolAddress((void**)&pbg,  g_bg);
    cudaGetSymbolAddress((void**)&pCm,  g_cmean);
    cudaGetSymbolAddress((void**)&pCr,  g_crstd);

    constexpr int SMEM_STD = (128 * SRS + 128 * SRS) * 2 * NSTG;  // 110592

    static bool attr_done = false;
    if (!attr_done) {
        cudaFuncSetAttribute(mma_gemmH<128, 128, 4, 0, false, float>,
                             cudaFuncAttributeMaxDynamicSharedMemorySize, SMEM_STD);
        cudaFuncSetAttribute(mma_gemmH<128, 128, 4, 2, false, __half>,
                             cudaFuncAttributeMaxDynamicSharedMemorySize, SMEM_STD);
        cudaFuncSetAttribute(mma_gemmH<128, 128, 4, 1, true, __half>,
                             cudaFuncAttributeMaxDynamicSharedMemorySize, SMEM_STD);
        cudaFuncSetAttribute(mma_gemm_dualH,
                             cudaFuncAttributeMaxDynamicSharedMemorySize, DUAL_SMEM);
        attr_done = true;
    }

    const dim3 blk(256);

    // --- weight prep ---
    prep_w_kernel<<<(CKP * CKEY + 255) / 256, blk>>>(Wf, bf, pWf, pbf, CKEY, CKEY, CKP);
    prep_w_kernel<<<(CKP * CKEY + 255) / 256, blk>>>(Wg, bg, pWg, pbg, CKEY, CKEY, CKP);
    prep_w_kernel<<<(CIN * CIN + 255) / 256, blk>>>(Wh, nullptr, pWh, nullptr, CIN, CIN, CIN);

    // --- transpose inputs to token-major half ---
    transpose_in_kernel<CKEY><<<dim3(NTOK / 32, CKEY / 32, 2 * NB), blk>>>(
        ckey, pckT, skey, pskT);
    transpose_in_kernel<CIN><<<dim3(NTOK / 32, CIN / 32, NB), blk>>>(
        style, pstT, style, pstT);

    // --- projections (fp16 mma, fp32 accum), K multiple of 64 ---
    mma_gemmH<128, 128, 4, 2, false, __half><<<dim3(CKP / 128, NTOK / 128, NB), blk, SMEM_STD>>>(
        pckT, pWf, pbf, pFqN, nullptr, CKEY, CKEY, CKEY, CKEY, CKEY,
        (size_t)NTOK * CKEY, 0, (size_t)NTOK * CKEY);
    mma_gemmH<128, 128, 4, 2, false, __half><<<dim3(CKP / 128, NTOK / 128, NB), blk, SMEM_STD>>>(
        pskT, pWg, pbg, pGN, nullptr, CKEY, CKEY, CKEY, CKEY, CKEY,
        (size_t)NTOK * CKEY, 0, (size_t)NTOK * CKEY);
    mma_gemmH<128, 128, 4, 1, true, __half><<<dim3(NTOK / 128, CIN / 128, NB), blk, SMEM_STD>>>(
        pWh, pstT, bh, pHv, pHv2, NTOK, CIN, CIN, CIN, NTOK,
        0, (size_t)NTOK * CIN, (size_t)CIN * NTOK);

    // --- S = FqN @ GN^T (fp32 out) ---
    mma_gemmH<128, 128, 4, 0, false, float><<<dim3(NTOK / 128, NTOK / 128, NB), blk, SMEM_STD>>>(
        pFqN, pGN, nullptr, pS, nullptr, NTOK, CKEY, CKEY, CKEY, NTOK,
        (size_t)NTOK * CKEY, (size_t)NTOK * CKEY, (size_t)NTOK * NTOK);

    // --- masked softmax: fp32 S -> half attn ---
    softmax_mask_kernel<<<dim3(NTOK, NB), blk>>>(pS, pA, cmask, smask);

    // --- fused mean/m2 ---
    mma_gemm_dualH<<<dim3(CIN / 64, NTOK / 128, NB), blk, DUAL_SMEM>>>(
        pA, pHv, pHv2, pMean, pM2);

    // --- mvn stats + final combine ---
    mvn_stats_kernel<<<dim3(CIN, NB), blk>>>(content, pCm, pCr);
    combine_kernel<<<dim3((NB * CIN * NTOK / 4) / 256), blk>>>(
        (const float4*)content, (const float4*)pMean, (const float4*)pM2,
        pCm, pCr, (float4*)out);
}